// round 1
// baseline (speedup 1.0000x reference)
#include <cuda_runtime.h>
#include <cuda_bf16.h>
#include <math.h>

// ---------------- problem constants ----------------
#define BATCH   4
#define SEQ_Q   3072
#define SEQ_KV  1036
#define D_E     1024
#define D_C     768
#define N_HEADS 8
#define D_HEAD  128

#define MQ (BATCH * SEQ_Q)    // 12288
#define MKV (BATCH * SEQ_KV)  // 4144

// ---------------- scratch (no cudaMalloc allowed) ----------------
__device__ float g_Q[(size_t)MQ * D_E];
__device__ float g_K[(size_t)MKV * D_E];
__device__ float g_V[(size_t)MKV * D_E];
__device__ float g_O[(size_t)MQ * D_E];

// ============================================================
// GEMM: C[M,N] = A[M,K] @ W[N,K]^T + bias[N]
// BM=128, BN=128, BK=8, 256 threads, 8x8 register tile
// ============================================================
__global__ __launch_bounds__(256) void gemm_bias(
    const float* __restrict__ A, const float* __restrict__ W,
    const float* __restrict__ bias, float* __restrict__ C,
    int M, int N, int K)
{
    __shared__ float As[8][128];
    __shared__ float Bs[8][128];

    const int tid = threadIdx.x;
    const int tx = tid & 15;        // n sub-tile
    const int ty = tid >> 4;        // m sub-tile
    const int m0 = blockIdx.y * 128;
    const int n0 = blockIdx.x * 128;

    const int lr = tid >> 1;          // 0..127 row within tile
    const int lk = (tid & 1) * 4;     // 0 or 4

    float acc[8][8];
    #pragma unroll
    for (int i = 0; i < 8; i++)
        #pragma unroll
        for (int j = 0; j < 8; j++) acc[i][j] = 0.0f;

    for (int k0 = 0; k0 < K; k0 += 8) {
        // load A tile (transposed into As[k][m]); guard M
        float4 av = make_float4(0.f, 0.f, 0.f, 0.f);
        int gm = m0 + lr;
        if (gm < M)
            av = *reinterpret_cast<const float4*>(&A[(size_t)gm * K + k0 + lk]);
        As[lk + 0][lr] = av.x;
        As[lk + 1][lr] = av.y;
        As[lk + 2][lr] = av.z;
        As[lk + 3][lr] = av.w;

        // load W tile (N dims here are always multiples of 128)
        float4 bv = *reinterpret_cast<const float4*>(&W[(size_t)(n0 + lr) * K + k0 + lk]);
        Bs[lk + 0][lr] = bv.x;
        Bs[lk + 1][lr] = bv.y;
        Bs[lk + 2][lr] = bv.z;
        Bs[lk + 3][lr] = bv.w;

        __syncthreads();

        #pragma unroll
        for (int k = 0; k < 8; k++) {
            float a[8], b[8];
            *reinterpret_cast<float4*>(&a[0]) = *reinterpret_cast<float4*>(&As[k][ty * 8 + 0]);
            *reinterpret_cast<float4*>(&a[4]) = *reinterpret_cast<float4*>(&As[k][ty * 8 + 4]);
            *reinterpret_cast<float4*>(&b[0]) = *reinterpret_cast<float4*>(&Bs[k][tx * 8 + 0]);
            *reinterpret_cast<float4*>(&b[4]) = *reinterpret_cast<float4*>(&Bs[k][tx * 8 + 4]);
            #pragma unroll
            for (int i = 0; i < 8; i++)
                #pragma unroll
                for (int j = 0; j < 8; j++)
                    acc[i][j] += a[i] * b[j];
        }
        __syncthreads();
    }

    // epilogue
    #pragma unroll
    for (int i = 0; i < 8; i++) {
        int gm = m0 + ty * 8 + i;
        if (gm < M) {
            #pragma unroll
            for (int j = 0; j < 8; j += 4) {
                int gn = n0 + tx * 8 + j;
                float4 o;
                o.x = acc[i][j + 0] + bias[gn + 0];
                o.y = acc[i][j + 1] + bias[gn + 1];
                o.z = acc[i][j + 2] + bias[gn + 2];
                o.w = acc[i][j + 3] + bias[gn + 3];
                *reinterpret_cast<float4*>(&C[(size_t)gm * N + gn]) = o;
            }
        }
    }
}

// ============================================================
// Flash attention (fp32, online softmax)
// grid: (S/64 q-tiles, H, B), 256 threads
// smem: Qs[64][128], KT[128][33], Vs[32][128], Ss[64][33], row stats
// ============================================================
#define FA_SMEM_FLOATS (64 * 128 + 128 * 33 + 32 * 128 + 64 * 33 + 3 * 64)

__global__ __launch_bounds__(256) void fa_kernel(
    const float* __restrict__ Q, const float* __restrict__ K,
    const float* __restrict__ V, float* __restrict__ O)
{
    extern __shared__ float sm[];
    float* Qs     = sm;                      // 64*128
    float* KT     = Qs + 64 * 128;           // 128*33 (transposed, padded)
    float* Vs     = KT + 128 * 33;           // 32*128
    float* Ss     = Vs + 32 * 128;           // 64*33 (padded)
    float* row_m  = Ss + 64 * 33;            // 64
    float* row_l  = row_m + 64;              // 64
    float* row_sc = row_l + 64;              // 64

    const int tid = threadIdx.x;
    const int qt = blockIdx.x;
    const int h  = blockIdx.y;
    const int b  = blockIdx.z;
    const int q0 = qt * 64;
    const float scale = 0.08838834764831845f;  // 1/sqrt(128)

    // load scaled Q tile
    {
        const float* qbase = Q + ((size_t)(b * SEQ_Q + q0)) * D_E + h * D_HEAD;
        for (int f = tid; f < 64 * 32; f += 256) {   // float4 units
            int r = f >> 5;
            int d = (f & 31) << 2;
            float4 v = *reinterpret_cast<const float4*>(qbase + (size_t)r * D_E + d);
            v.x *= scale; v.y *= scale; v.z *= scale; v.w *= scale;
            *reinterpret_cast<float4*>(&Qs[r * 128 + d]) = v;
        }
    }
    if (tid < 64) { row_m[tid] = -1e30f; row_l[tid] = 0.0f; }

    float acc[4][8];
    #pragma unroll
    for (int i = 0; i < 4; i++)
        #pragma unroll
        for (int j = 0; j < 8; j++) acc[i][j] = 0.0f;

    const int tq = tid >> 4;   // q-row group (x4)   for scores & PV
    const int tk = tid & 15;   // kv col group (x2) for scores; d group (x8) for PV

    const float* kb0 = K + ((size_t)(b * SEQ_KV)) * D_E + h * D_HEAD;
    const float* vb0 = V + ((size_t)(b * SEQ_KV)) * D_E + h * D_HEAD;

    const int nt = (SEQ_KV + 31) / 32;   // 33

    for (int t = 0; t < nt; t++) {
        const int kv0 = t * 32;

        // ---- load K tile transposed: KT[d][kv] ----
        for (int f = tid; f < 32 * 32; f += 256) {   // float4 units
            int kv = f >> 5;
            int d  = (f & 31) << 2;
            float4 v = make_float4(0.f, 0.f, 0.f, 0.f);
            if (kv0 + kv < SEQ_KV)
                v = *reinterpret_cast<const float4*>(kb0 + (size_t)(kv0 + kv) * D_E + d);
            KT[(d + 0) * 33 + kv] = v.x;
            KT[(d + 1) * 33 + kv] = v.y;
            KT[(d + 2) * 33 + kv] = v.z;
            KT[(d + 3) * 33 + kv] = v.w;
        }
        __syncthreads();

        // ---- scores: S[64][32] = Qs @ KT ----
        float s[4][2];
        #pragma unroll
        for (int i = 0; i < 4; i++) { s[i][0] = 0.f; s[i][1] = 0.f; }

        #pragma unroll 4
        for (int d = 0; d < 128; d++) {
            float k0v = KT[d * 33 + tk * 2 + 0];
            float k1v = KT[d * 33 + tk * 2 + 1];
            #pragma unroll
            for (int i = 0; i < 4; i++) {
                float qv = Qs[(tq * 4 + i) * 128 + d];
                s[i][0] += qv * k0v;
                s[i][1] += qv * k1v;
            }
        }
        #pragma unroll
        for (int i = 0; i < 4; i++) {
            #pragma unroll
            for (int c = 0; c < 2; c++) {
                int kvg = kv0 + tk * 2 + c;
                Ss[(tq * 4 + i) * 33 + tk * 2 + c] = (kvg < SEQ_KV) ? s[i][c] : -1e30f;
            }
        }
        __syncthreads();

        // ---- load V tile (all threads) ----
        for (int f = tid; f < 32 * 32; f += 256) {
            int kv = f >> 5;
            int d  = (f & 31) << 2;
            float4 v = make_float4(0.f, 0.f, 0.f, 0.f);
            if (kv0 + kv < SEQ_KV)
                v = *reinterpret_cast<const float4*>(vb0 + (size_t)(kv0 + kv) * D_E + d);
            *reinterpret_cast<float4*>(&Vs[kv * 128 + d]) = v;
        }

        // ---- online softmax row update (threads 0..63) ----
        if (tid < 64) {
            int r = tid;
            float mo = row_m[r];
            float mt = -1e30f;
            #pragma unroll 8
            for (int c = 0; c < 32; c++) mt = fmaxf(mt, Ss[r * 33 + c]);
            float mn = fmaxf(mo, mt);
            float sc = __expf(mo - mn);
            float sum = 0.f;
            #pragma unroll 8
            for (int c = 0; c < 32; c++) {
                float p = __expf(Ss[r * 33 + c] - mn);
                Ss[r * 33 + c] = p;
                sum += p;
            }
            row_l[r]  = row_l[r] * sc + sum;
            row_m[r]  = mn;
            row_sc[r] = sc;
        }
        __syncthreads();

        // ---- PV: O[q][d] = O*scale + P @ V ----
        float scr[4];
        #pragma unroll
        for (int i = 0; i < 4; i++) scr[i] = row_sc[tq * 4 + i];
        #pragma unroll
        for (int i = 0; i < 4; i++)
            #pragma unroll
            for (int j = 0; j < 8; j++) acc[i][j] *= scr[i];

        #pragma unroll 2
        for (int kv = 0; kv < 32; kv++) {
            float4 v0 = *reinterpret_cast<float4*>(&Vs[kv * 128 + tk * 8 + 0]);
            float4 v1 = *reinterpret_cast<float4*>(&Vs[kv * 128 + tk * 8 + 4]);
            #pragma unroll
            for (int i = 0; i < 4; i++) {
                float p = Ss[(tq * 4 + i) * 33 + kv];
                acc[i][0] += p * v0.x; acc[i][1] += p * v0.y;
                acc[i][2] += p * v0.z; acc[i][3] += p * v0.w;
                acc[i][4] += p * v1.x; acc[i][5] += p * v1.y;
                acc[i][6] += p * v1.z; acc[i][7] += p * v1.w;
            }
        }
        // no trailing sync needed: next iter writes KT (disjoint) then syncs
        // before touching Ss/Vs/row_*.
    }

    // ---- normalize + write out ----
    float inv[4];
    #pragma unroll
    for (int i = 0; i < 4; i++) inv[i] = 1.0f / row_l[tq * 4 + i];

    float* ob = O + ((size_t)(b * SEQ_Q + q0 + tq * 4)) * D_E + h * D_HEAD + tk * 8;
    #pragma unroll
    for (int i = 0; i < 4; i++) {
        float4 o0, o1;
        o0.x = acc[i][0] * inv[i]; o0.y = acc[i][1] * inv[i];
        o0.z = acc[i][2] * inv[i]; o0.w = acc[i][3] * inv[i];
        o1.x = acc[i][4] * inv[i]; o1.y = acc[i][5] * inv[i];
        o1.z = acc[i][6] * inv[i]; o1.w = acc[i][7] * inv[i];
        *reinterpret_cast<float4*>(ob + (size_t)i * D_E + 0) = o0;
        *reinterpret_cast<float4*>(ob + (size_t)i * D_E + 4) = o1;
    }
}

// ============================================================
// launch
// ============================================================
extern "C" void kernel_launch(void* const* d_in, const int* in_sizes, int n_in,
                              void* d_out, int out_size)
{
    const float* x  = (const float*)d_in[0];
    const float* y  = (const float*)d_in[1];
    const float* Wq = (const float*)d_in[2];
    const float* bq = (const float*)d_in[3];
    const float* Wk = (const float*)d_in[4];
    const float* bk = (const float*)d_in[5];
    const float* Wv = (const float*)d_in[6];
    const float* bv = (const float*)d_in[7];
    const float* Wo = (const float*)d_in[8];
    const float* bo = (const float*)d_in[9];
    float* out = (float*)d_out;

    float *pQ, *pK, *pV, *pO;
    cudaGetSymbolAddress((void**)&pQ, g_Q);
    cudaGetSymbolAddress((void**)&pK, g_K);
    cudaGetSymbolAddress((void**)&pV, g_V);
    cudaGetSymbolAddress((void**)&pO, g_O);

    // projections
    gemm_bias<<<dim3(D_E / 128, (MQ + 127) / 128), 256>>>(x, Wq, bq, pQ, MQ, D_E, D_E);
    gemm_bias<<<dim3(D_E / 128, (MKV + 127) / 128), 256>>>(y, Wk, bk, pK, MKV, D_E, D_C);
    gemm_bias<<<dim3(D_E / 128, (MKV + 127) / 128), 256>>>(y, Wv, bv, pV, MKV, D_E, D_C);

    // attention
    const int fa_smem = FA_SMEM_FLOATS * (int)sizeof(float);
    cudaFuncSetAttribute(fa_kernel, cudaFuncAttributeMaxDynamicSharedMemorySize, fa_smem);
    fa_kernel<<<dim3(SEQ_Q / 64, N_HEADS, BATCH), 256, fa_smem>>>(pQ, pK, pV, pO);

    // output projection -> d_out
    gemm_bias<<<dim3(D_E / 128, (MQ + 127) / 128), 256>>>(pO, Wo, bo, out, MQ, D_E, D_E);
}

// round 2
// speedup vs baseline: 1.3974x; 1.3974x over previous
#include <cuda_runtime.h>
#include <cuda_bf16.h>
#include <math.h>

// ---------------- problem constants ----------------
#define BATCH   4
#define SEQ_Q   3072
#define SEQ_KV  1036
#define D_E     1024
#define D_C     768
#define N_HEADS 8
#define D_HEAD  128

#define MQ (BATCH * SEQ_Q)    // 12288
#define MKV (BATCH * SEQ_KV)  // 4144

// ---------------- scratch ----------------
__device__ float g_Q[(size_t)MQ * D_E];
__device__ float g_K[(size_t)MKV * D_E];
__device__ float g_V[(size_t)MKV * D_E];
__device__ float g_O[(size_t)MQ * D_E];

// ---------------- helpers ----------------
__device__ __forceinline__ unsigned f2tf32(float x) {
    unsigned r;
    asm("cvt.rna.tf32.f32 %0, %1;" : "=r"(r) : "f"(x));
    return r;
}

// D = A(16x8, row) * B(8x8, col) + D, fp32 accum, tf32 inputs
__device__ __forceinline__ void mma_tf32(float d[4], const unsigned a[4], const unsigned b[2]) {
    asm volatile(
        "mma.sync.aligned.m16n8k8.row.col.f32.tf32.tf32.f32 "
        "{%0,%1,%2,%3}, {%4,%5,%6,%7}, {%8,%9}, {%0,%1,%2,%3};\n"
        : "+f"(d[0]), "+f"(d[1]), "+f"(d[2]), "+f"(d[3])
        : "r"(a[0]), "r"(a[1]), "r"(a[2]), "r"(a[3]),
          "r"(b[0]), "r"(b[1]));
}

// ============================================================
// tf32 tensor-core GEMM: C[M,N] = A[M,K] @ W[N,K]^T + bias
// block 128x128x32, 8 warps (warp tile 64x32)
// SMEM holds operands pre-swizzled in mma fragment order.
// ============================================================
__global__ __launch_bounds__(256, 2) void gemm_tf32(
    const float* __restrict__ A, const float* __restrict__ W,
    const float* __restrict__ bias, float* __restrict__ C,
    int M, int N, int K)
{
    // sA: [mt(8)][kt(4)][lane(32)*4+reg] ; sB: [nt(16)][kt(4)][lane*2+reg]
    __shared__ unsigned sA[8 * 4 * 128];
    __shared__ unsigned sB[16 * 4 * 64];

    const int tid  = threadIdx.x;
    const int lane = tid & 31;
    const int wid  = tid >> 5;
    const int wm   = wid >> 2;   // 0..1
    const int wn   = wid & 3;    // 0..3
    const int m0   = blockIdx.y * 128;
    const int n0   = blockIdx.x * 128;

    float acc[4][4][4];
    #pragma unroll
    for (int i = 0; i < 4; i++)
        #pragma unroll
        for (int j = 0; j < 4; j++)
            #pragma unroll
            for (int c = 0; c < 4; c++) acc[i][j][c] = 0.0f;

    for (int k0 = 0; k0 < K; k0 += 32) {
        // ---- load A tile [128 x 32] into fragment layout ----
        #pragma unroll
        for (int i = 0; i < 4; i++) {
            int linear = tid + i * 256;          // 1024 float4 slots
            int row = linear >> 3;
            int col = (linear & 7) << 2;
            float4 v = make_float4(0.f, 0.f, 0.f, 0.f);
            if (m0 + row < M)
                v = *reinterpret_cast<const float4*>(A + (size_t)(m0 + row) * K + k0 + col);
            int mt = row >> 4, r = row & 15;
            int lbase = (r & 7) << 2;
            int rbit  = (r >> 3) & 1;
            float vv[4] = {v.x, v.y, v.z, v.w};
            #pragma unroll
            for (int j = 0; j < 4; j++) {
                int c  = col + j;
                int kt = c >> 3, kk = c & 7;
                sA[(mt * 4 + kt) * 128 + (lbase | (kk & 3)) * 4 + (rbit | ((kk >> 2) << 1))] =
                    f2tf32(vv[j]);
            }
        }
        // ---- load W tile [128 x 32] into B fragment layout ----
        #pragma unroll
        for (int i = 0; i < 4; i++) {
            int linear = tid + i * 256;
            int row = linear >> 3;               // n within tile
            int col = (linear & 7) << 2;
            float4 v = *reinterpret_cast<const float4*>(W + (size_t)(n0 + row) * K + k0 + col);
            int nt = row >> 3, nn = row & 7;
            float vv[4] = {v.x, v.y, v.z, v.w};
            #pragma unroll
            for (int j = 0; j < 4; j++) {
                int c  = col + j;
                int kt = c >> 3, kk = c & 7;
                sB[(nt * 4 + kt) * 64 + ((nn << 2) | (kk & 3)) * 2 + (kk >> 2)] = f2tf32(vv[j]);
            }
        }
        __syncthreads();

        // ---- mma over 4 k8-steps ----
        #pragma unroll
        for (int kt = 0; kt < 4; kt++) {
            unsigned af[4][4];
            unsigned bf[4][2];
            #pragma unroll
            for (int mi = 0; mi < 4; mi++) {
                uint4 t = *reinterpret_cast<const uint4*>(&sA[((wm * 4 + mi) * 4 + kt) * 128 + lane * 4]);
                af[mi][0] = t.x; af[mi][1] = t.y; af[mi][2] = t.z; af[mi][3] = t.w;
            }
            #pragma unroll
            for (int ni = 0; ni < 4; ni++) {
                uint2 t = *reinterpret_cast<const uint2*>(&sB[((wn * 4 + ni) * 4 + kt) * 64 + lane * 2]);
                bf[ni][0] = t.x; bf[ni][1] = t.y;
            }
            #pragma unroll
            for (int mi = 0; mi < 4; mi++)
                #pragma unroll
                for (int ni = 0; ni < 4; ni++)
                    mma_tf32(acc[mi][ni], af[mi], bf[ni]);
        }
        __syncthreads();
    }

    // ---- epilogue: bias + store ----
    const int rb = lane >> 2;
    const int cb = (lane & 3) * 2;
    #pragma unroll
    for (int mi = 0; mi < 4; mi++) {
        int row1 = m0 + (wm * 4 + mi) * 16 + rb;
        int row2 = row1 + 8;
        #pragma unroll
        for (int ni = 0; ni < 4; ni++) {
            int colg = n0 + (wn * 4 + ni) * 8 + cb;
            float b0 = bias[colg], b1 = bias[colg + 1];
            if (row1 < M) {
                float2 o = make_float2(acc[mi][ni][0] + b0, acc[mi][ni][1] + b1);
                *reinterpret_cast<float2*>(C + (size_t)row1 * N + colg) = o;
            }
            if (row2 < M) {
                float2 o = make_float2(acc[mi][ni][2] + b0, acc[mi][ni][3] + b1);
                *reinterpret_cast<float2*>(C + (size_t)row2 * N + colg) = o;
            }
        }
    }
}

// ============================================================
// tf32 tensor-core flash attention
// block: 64 q-rows, chunks of 64 kv, 256 threads / 8 warps
// ============================================================
#define SSS 66
#define NCHUNK 17   // 17*64 = 1088 >= 1036

__global__ __launch_bounds__(256, 1) void fa_tf32(
    const float* __restrict__ Q, const float* __restrict__ K,
    const float* __restrict__ V, float* __restrict__ O)
{
    extern __shared__ float fsm[];
    unsigned* Qf = reinterpret_cast<unsigned*>(fsm);  // 4*16*128 = 8192
    unsigned* Kf = Qf + 8192;                         // 8*16*64  = 8192
    unsigned* Vf = Kf + 8192;                         // 16*8*64  = 8192
    unsigned* Pf = Vf + 8192;                         // 4*8*128  = 4096
    float* Ss     = reinterpret_cast<float*>(Pf + 4096);  // 64*66
    float* row_m  = Ss + 64 * SSS;
    float* row_l  = row_m + 64;
    float* row_sc = row_l + 64;

    const int tid  = threadIdx.x;
    const int lane = tid & 31;
    const int wid  = tid >> 5;
    const int q0 = blockIdx.x * 64;
    const int h  = blockIdx.y;
    const int b  = blockIdx.z;
    const float scale = 0.08838834764831845f;  // 1/sqrt(128)

    // ---- load Q tile (scaled) into A fragment layout ----
    {
        const float* qb = Q + ((size_t)(b * SEQ_Q + q0)) * D_E + h * D_HEAD;
        #pragma unroll
        for (int i = 0; i < 8; i++) {
            int linear = tid + i * 256;     // 2048 float4 slots
            int row = linear >> 5;
            int col = (linear & 31) << 2;
            float4 v = *reinterpret_cast<const float4*>(qb + (size_t)row * D_E + col);
            int mt = row >> 4, r = row & 15;
            int lbase = (r & 7) << 2;
            int rbit  = (r >> 3) & 1;
            float vv[4] = {v.x, v.y, v.z, v.w};
            #pragma unroll
            for (int j = 0; j < 4; j++) {
                int d  = col + j;
                int kt = d >> 3, kk = d & 7;
                Qf[(mt * 16 + kt) * 128 + (lbase | (kk & 3)) * 4 + (rbit | ((kk >> 2) << 1))] =
                    f2tf32(vv[j] * scale);
            }
        }
    }
    if (tid < 64) { row_m[tid] = -1e30f; row_l[tid] = 0.0f; }

    float oacc[4][2][4];
    #pragma unroll
    for (int mt = 0; mt < 4; mt++)
        #pragma unroll
        for (int n2 = 0; n2 < 2; n2++)
            #pragma unroll
            for (int c = 0; c < 4; c++) oacc[mt][n2][c] = 0.0f;

    const float* kb = K + ((size_t)(b * SEQ_KV)) * D_E + h * D_HEAD;
    const float* vb = V + ((size_t)(b * SEQ_KV)) * D_E + h * D_HEAD;

    for (int t = 0; t < NCHUNK; t++) {
        const int kv0 = t * 64;

        // ---- K chunk [64 kv x 128 d] -> B-frag (n=kv, k=d) ----
        #pragma unroll
        for (int i = 0; i < 8; i++) {
            int linear = tid + i * 256;
            int row = linear >> 5;
            int col = (linear & 31) << 2;
            int kv = kv0 + row;
            float4 v = make_float4(0.f, 0.f, 0.f, 0.f);
            if (kv < SEQ_KV)
                v = *reinterpret_cast<const float4*>(kb + (size_t)kv * D_E + col);
            int nt = row >> 3, nn = row & 7;
            float vv[4] = {v.x, v.y, v.z, v.w};
            #pragma unroll
            for (int j = 0; j < 4; j++) {
                int d  = col + j;
                int kt = d >> 3, kk = d & 7;
                Kf[(nt * 16 + kt) * 64 + ((nn << 2) | (kk & 3)) * 2 + (kk >> 2)] = f2tf32(vv[j]);
            }
        }
        // ---- V chunk [64 kv x 128 d] -> B-frag (n=d, k=kv) ----
        #pragma unroll
        for (int i = 0; i < 8; i++) {
            int linear = tid + i * 256;
            int row = linear >> 5;
            int col = (linear & 31) << 2;
            int kv = kv0 + row;
            float4 v = make_float4(0.f, 0.f, 0.f, 0.f);
            if (kv < SEQ_KV)
                v = *reinterpret_cast<const float4*>(vb + (size_t)kv * D_E + col);
            int kt = row >> 3;
            float vv[4] = {v.x, v.y, v.z, v.w};
            #pragma unroll
            for (int j = 0; j < 4; j++) {
                int d  = col + j;
                int nt = d >> 3, dd = d & 7;
                Vf[(nt * 8 + kt) * 64 + ((dd << 2) | (row & 3)) * 2 + ((row >> 2) & 1)] = f2tf32(vv[j]);
            }
        }
        __syncthreads();

        // ---- S = Q @ K^T : warp handles n8-tile = wid ----
        float sacc[4][4];
        #pragma unroll
        for (int mt = 0; mt < 4; mt++)
            #pragma unroll
            for (int c = 0; c < 4; c++) sacc[mt][c] = 0.0f;

        #pragma unroll
        for (int kt = 0; kt < 16; kt++) {
            uint2 bt = *reinterpret_cast<const uint2*>(&Kf[(wid * 16 + kt) * 64 + lane * 2]);
            unsigned bf[2] = {bt.x, bt.y};
            #pragma unroll
            for (int mt = 0; mt < 4; mt++) {
                uint4 at = *reinterpret_cast<const uint4*>(&Qf[(mt * 16 + kt) * 128 + lane * 4]);
                unsigned af[4] = {at.x, at.y, at.z, at.w};
                mma_tf32(sacc[mt], af, bf);
            }
        }
        // write S to smem
        {
            int cbw = wid * 8 + (lane & 3) * 2;
            #pragma unroll
            for (int mt = 0; mt < 4; mt++) {
                int r1 = mt * 16 + (lane >> 2);
                *reinterpret_cast<float2*>(&Ss[r1 * SSS + cbw]) = make_float2(sacc[mt][0], sacc[mt][1]);
                *reinterpret_cast<float2*>(&Ss[(r1 + 8) * SSS + cbw]) = make_float2(sacc[mt][2], sacc[mt][3]);
            }
        }
        __syncthreads();

        // ---- online softmax: 4 threads per row, 16 cols each ----
        {
            int row = tid >> 2, qd = tid & 3;
            float mold = row_m[row];
            float s[16];
            float mx = -1e30f;
            #pragma unroll
            for (int j = 0; j < 16; j++) {
                int c = qd * 16 + j;
                float sv = (kv0 + c < SEQ_KV) ? Ss[row * SSS + c] : -1e30f;
                s[j] = sv;
                mx = fmaxf(mx, sv);
            }
            mx = fmaxf(mx, __shfl_xor_sync(0xffffffffu, mx, 1));
            mx = fmaxf(mx, __shfl_xor_sync(0xffffffffu, mx, 2));
            float mnew = fmaxf(mold, mx);
            int mt = row >> 4, rr = row & 15;
            int lbase = (rr & 7) << 2;
            int rbit  = (rr >> 3) & 1;
            float sum = 0.f;
            #pragma unroll
            for (int j = 0; j < 16; j++) {
                int c = qd * 16 + j;
                float p = __expf(s[j] - mnew);
                sum += p;
                int kt = c >> 3, cc = c & 7;
                Pf[(mt * 8 + kt) * 128 + (lbase | (cc & 3)) * 4 + (rbit | ((cc >> 2) << 1))] = f2tf32(p);
            }
            sum += __shfl_xor_sync(0xffffffffu, sum, 1);
            sum += __shfl_xor_sync(0xffffffffu, sum, 2);
            float sc = __expf(mold - mnew);
            if (qd == 0) {
                row_l[row]  = row_l[row] * sc + sum;
                row_m[row]  = mnew;
                row_sc[row] = sc;
            }
        }
        __syncthreads();

        // ---- rescale O, then O += P @ V ----
        #pragma unroll
        for (int mt = 0; mt < 4; mt++) {
            float s1 = row_sc[mt * 16 + (lane >> 2)];
            float s2 = row_sc[mt * 16 + (lane >> 2) + 8];
            #pragma unroll
            for (int n2 = 0; n2 < 2; n2++) {
                oacc[mt][n2][0] *= s1; oacc[mt][n2][1] *= s1;
                oacc[mt][n2][2] *= s2; oacc[mt][n2][3] *= s2;
            }
        }
        #pragma unroll
        for (int kt = 0; kt < 8; kt++) {
            unsigned af[4][4];
            #pragma unroll
            for (int mt = 0; mt < 4; mt++) {
                uint4 at = *reinterpret_cast<const uint4*>(&Pf[(mt * 8 + kt) * 128 + lane * 4]);
                af[mt][0] = at.x; af[mt][1] = at.y; af[mt][2] = at.z; af[mt][3] = at.w;
            }
            #pragma unroll
            for (int n2 = 0; n2 < 2; n2++) {
                int nt = wid * 2 + n2;
                uint2 bt = *reinterpret_cast<const uint2*>(&Vf[(nt * 8 + kt) * 64 + lane * 2]);
                unsigned bf[2] = {bt.x, bt.y};
                #pragma unroll
                for (int mt = 0; mt < 4; mt++)
                    mma_tf32(oacc[mt][n2], af[mt], bf);
            }
        }
        __syncthreads();
    }

    // ---- normalize + write ----
    float* ob = O + ((size_t)(b * SEQ_Q + q0)) * D_E + h * D_HEAD;
    #pragma unroll
    for (int mt = 0; mt < 4; mt++) {
        int r1 = mt * 16 + (lane >> 2);
        int r2 = r1 + 8;
        float il1 = 1.0f / row_l[r1];
        float il2 = 1.0f / row_l[r2];
        #pragma unroll
        for (int n2 = 0; n2 < 2; n2++) {
            int colg = (wid * 2 + n2) * 8 + (lane & 3) * 2;
            *reinterpret_cast<float2*>(ob + (size_t)r1 * D_E + colg) =
                make_float2(oacc[mt][n2][0] * il1, oacc[mt][n2][1] * il1);
            *reinterpret_cast<float2*>(ob + (size_t)r2 * D_E + colg) =
                make_float2(oacc[mt][n2][2] * il2, oacc[mt][n2][3] * il2);
        }
    }
}

#define FA_SMEM_BYTES ((8192 * 3 + 4096 + 64 * SSS + 192) * 4)

// ============================================================
// launch
// ============================================================
extern "C" void kernel_launch(void* const* d_in, const int* in_sizes, int n_in,
                              void* d_out, int out_size)
{
    const float* x  = (const float*)d_in[0];
    const float* y  = (const float*)d_in[1];
    const float* Wq = (const float*)d_in[2];
    const float* bq = (const float*)d_in[3];
    const float* Wk = (const float*)d_in[4];
    const float* bk = (const float*)d_in[5];
    const float* Wv = (const float*)d_in[6];
    const float* bv = (const float*)d_in[7];
    const float* Wo = (const float*)d_in[8];
    const float* bo = (const float*)d_in[9];
    float* out = (float*)d_out;

    float *pQ, *pK, *pV, *pO;
    cudaGetSymbolAddress((void**)&pQ, g_Q);
    cudaGetSymbolAddress((void**)&pK, g_K);
    cudaGetSymbolAddress((void**)&pV, g_V);
    cudaGetSymbolAddress((void**)&pO, g_O);

    // projections
    gemm_tf32<<<dim3(D_E / 128, (MQ + 127) / 128), 256>>>(x, Wq, bq, pQ, MQ, D_E, D_E);
    gemm_tf32<<<dim3(D_E / 128, (MKV + 127) / 128), 256>>>(y, Wk, bk, pK, MKV, D_E, D_C);
    gemm_tf32<<<dim3(D_E / 128, (MKV + 127) / 128), 256>>>(y, Wv, bv, pV, MKV, D_E, D_C);

    // attention
    cudaFuncSetAttribute(fa_tf32, cudaFuncAttributeMaxDynamicSharedMemorySize, FA_SMEM_BYTES);
    fa_tf32<<<dim3(SEQ_Q / 64, N_HEADS, BATCH), 256, FA_SMEM_BYTES>>>(pQ, pK, pV, pO);

    // output projection -> d_out
    gemm_tf32<<<dim3(D_E / 128, (MQ + 127) / 128), 256>>>(pO, Wo, bo, out, MQ, D_E, D_E);
}

// round 3
// speedup vs baseline: 1.3981x; 1.0005x over previous
#include <cuda_runtime.h>
#include <cuda_bf16.h>
#include <math.h>

// ---------------- problem constants ----------------
#define BATCH   4
#define SEQ_Q   3072
#define SEQ_KV  1036
#define D_E     1024
#define D_C     768
#define N_HEADS 8
#define D_HEAD  128

#define MQ (BATCH * SEQ_Q)    // 12288
#define MKV (BATCH * SEQ_KV)  // 4144

// ---------------- scratch ----------------
__device__ float g_Q[(size_t)MQ * D_E];
__device__ float g_K[(size_t)MKV * D_E];
__device__ float g_V[(size_t)MKV * D_E];
__device__ float g_O[(size_t)MQ * D_E];

// ---------------- helpers ----------------
__device__ __forceinline__ unsigned f2tf32(float x) {
    unsigned r;
    asm("cvt.rna.tf32.f32 %0, %1;" : "=r"(r) : "f"(x));
    return r;
}

// D = A(16x8, row) * B(8x8, col) + D, fp32 accum, tf32 inputs
__device__ __forceinline__ void mma_tf32(float d[4], const unsigned a[4], const unsigned b[2]) {
    asm volatile(
        "mma.sync.aligned.m16n8k8.row.col.f32.tf32.tf32.f32 "
        "{%0,%1,%2,%3}, {%4,%5,%6,%7}, {%8,%9}, {%0,%1,%2,%3};\n"
        : "+f"(d[0]), "+f"(d[1]), "+f"(d[2]), "+f"(d[3])
        : "r"(a[0]), "r"(a[1]), "r"(a[2]), "r"(a[3]),
          "r"(b[0]), "r"(b[1]));
}

// ============================================================
// tf32 tensor-core GEMM: C[M,N] = A[M,K] @ W[N,K]^T + bias
// block 128x128x32, 8 warps (warp tile 64x32)
// SMEM holds operands pre-swizzled in mma fragment order.
// ============================================================
__global__ __launch_bounds__(256, 2) void gemm_tf32(
    const float* __restrict__ A, const float* __restrict__ W,
    const float* __restrict__ bias, float* __restrict__ C,
    int M, int N, int K)
{
    // sA: [mt(8)][kt(4)][lane(32)*4+reg] ; sB: [nt(16)][kt(4)][lane*2+reg]
    __shared__ unsigned sA[8 * 4 * 128];
    __shared__ unsigned sB[16 * 4 * 64];

    const int tid  = threadIdx.x;
    const int lane = tid & 31;
    const int wid  = tid >> 5;
    const int wm   = wid >> 2;   // 0..1
    const int wn   = wid & 3;    // 0..3
    const int m0   = blockIdx.y * 128;
    const int n0   = blockIdx.x * 128;

    float acc[4][4][4];
    #pragma unroll
    for (int i = 0; i < 4; i++)
        #pragma unroll
        for (int j = 0; j < 4; j++)
            #pragma unroll
            for (int c = 0; c < 4; c++) acc[i][j][c] = 0.0f;

    for (int k0 = 0; k0 < K; k0 += 32) {
        // ---- load A tile [128 x 32] into fragment layout ----
        #pragma unroll
        for (int i = 0; i < 4; i++) {
            int linear = tid + i * 256;          // 1024 float4 slots
            int row = linear >> 3;
            int col = (linear & 7) << 2;
            float4 v = make_float4(0.f, 0.f, 0.f, 0.f);
            if (m0 + row < M)
                v = *reinterpret_cast<const float4*>(A + (size_t)(m0 + row) * K + k0 + col);
            int mt = row >> 4, r = row & 15;
            int lbase = (r & 7) << 2;
            int rbit  = (r >> 3) & 1;
            float vv[4] = {v.x, v.y, v.z, v.w};
            #pragma unroll
            for (int j = 0; j < 4; j++) {
                int c  = col + j;
                int kt = c >> 3, kk = c & 7;
                sA[(mt * 4 + kt) * 128 + (lbase | (kk & 3)) * 4 + (rbit | ((kk >> 2) << 1))] =
                    f2tf32(vv[j]);
            }
        }
        // ---- load W tile [128 x 32] into B fragment layout ----
        #pragma unroll
        for (int i = 0; i < 4; i++) {
            int linear = tid + i * 256;
            int row = linear >> 3;               // n within tile
            int col = (linear & 7) << 2;
            float4 v = *reinterpret_cast<const float4*>(W + (size_t)(n0 + row) * K + k0 + col);
            int nt = row >> 3, nn = row & 7;
            float vv[4] = {v.x, v.y, v.z, v.w};
            #pragma unroll
            for (int j = 0; j < 4; j++) {
                int c  = col + j;
                int kt = c >> 3, kk = c & 7;
                sB[(nt * 4 + kt) * 64 + ((nn << 2) | (kk & 3)) * 2 + (kk >> 2)] = f2tf32(vv[j]);
            }
        }
        __syncthreads();

        // ---- mma over 4 k8-steps ----
        #pragma unroll
        for (int kt = 0; kt < 4; kt++) {
            unsigned af[4][4];
            unsigned bf[4][2];
            #pragma unroll
            for (int mi = 0; mi < 4; mi++) {
                uint4 t = *reinterpret_cast<const uint4*>(&sA[((wm * 4 + mi) * 4 + kt) * 128 + lane * 4]);
                af[mi][0] = t.x; af[mi][1] = t.y; af[mi][2] = t.z; af[mi][3] = t.w;
            }
            #pragma unroll
            for (int ni = 0; ni < 4; ni++) {
                uint2 t = *reinterpret_cast<const uint2*>(&sB[((wn * 4 + ni) * 4 + kt) * 64 + lane * 2]);
                bf[ni][0] = t.x; bf[ni][1] = t.y;
            }
            #pragma unroll
            for (int mi = 0; mi < 4; mi++)
                #pragma unroll
                for (int ni = 0; ni < 4; ni++)
                    mma_tf32(acc[mi][ni], af[mi], bf[ni]);
        }
        __syncthreads();
    }

    // ---- epilogue: bias + store ----
    const int rb = lane >> 2;
    const int cb = (lane & 3) * 2;
    #pragma unroll
    for (int mi = 0; mi < 4; mi++) {
        int row1 = m0 + (wm * 4 + mi) * 16 + rb;
        int row2 = row1 + 8;
        #pragma unroll
        for (int ni = 0; ni < 4; ni++) {
            int colg = n0 + (wn * 4 + ni) * 8 + cb;
            float b0 = bias[colg], b1 = bias[colg + 1];
            if (row1 < M) {
                float2 o = make_float2(acc[mi][ni][0] + b0, acc[mi][ni][1] + b1);
                *reinterpret_cast<float2*>(C + (size_t)row1 * N + colg) = o;
            }
            if (row2 < M) {
                float2 o = make_float2(acc[mi][ni][2] + b0, acc[mi][ni][3] + b1);
                *reinterpret_cast<float2*>(C + (size_t)row2 * N + colg) = o;
            }
        }
    }
}

// ============================================================
// tf32 tensor-core flash attention
// block: 64 q-rows, chunks of 64 kv, 256 threads / 8 warps
// ============================================================
#define SSS 66
#define NCHUNK 17   // 17*64 = 1088 >= 1036

__global__ __launch_bounds__(256, 1) void fa_tf32(
    const float* __restrict__ Q, const float* __restrict__ K,
    const float* __restrict__ V, float* __restrict__ O)
{
    extern __shared__ float fsm[];
    unsigned* Qf = reinterpret_cast<unsigned*>(fsm);  // 4*16*128 = 8192
    unsigned* Kf = Qf + 8192;                         // 8*16*64  = 8192
    unsigned* Vf = Kf + 8192;                         // 16*8*64  = 8192
    unsigned* Pf = Vf + 8192;                         // 4*8*128  = 4096
    float* Ss     = reinterpret_cast<float*>(Pf + 4096);  // 64*66
    float* row_m  = Ss + 64 * SSS;
    float* row_l  = row_m + 64;
    float* row_sc = row_l + 64;

    const int tid  = threadIdx.x;
    const int lane = tid & 31;
    const int wid  = tid >> 5;
    const int q0 = blockIdx.x * 64;
    const int h  = blockIdx.y;
    const int b  = blockIdx.z;
    const float scale = 0.08838834764831845f;  // 1/sqrt(128)

    // ---- load Q tile (scaled) into A fragment layout ----
    {
        const float* qb = Q + ((size_t)(b * SEQ_Q + q0)) * D_E + h * D_HEAD;
        #pragma unroll
        for (int i = 0; i < 8; i++) {
            int linear = tid + i * 256;     // 2048 float4 slots
            int row = linear >> 5;
            int col = (linear & 31) << 2;
            float4 v = *reinterpret_cast<const float4*>(qb + (size_t)row * D_E + col);
            int mt = row >> 4, r = row & 15;
            int lbase = (r & 7) << 2;
            int rbit  = (r >> 3) & 1;
            float vv[4] = {v.x, v.y, v.z, v.w};
            #pragma unroll
            for (int j = 0; j < 4; j++) {
                int d  = col + j;
                int kt = d >> 3, kk = d & 7;
                Qf[(mt * 16 + kt) * 128 + (lbase | (kk & 3)) * 4 + (rbit | ((kk >> 2) << 1))] =
                    f2tf32(vv[j] * scale);
            }
        }
    }
    if (tid < 64) { row_m[tid] = -1e30f; row_l[tid] = 0.0f; }

    float oacc[4][2][4];
    #pragma unroll
    for (int mt = 0; mt < 4; mt++)
        #pragma unroll
        for (int n2 = 0; n2 < 2; n2++)
            #pragma unroll
            for (int c = 0; c < 4; c++) oacc[mt][n2][c] = 0.0f;

    const float* kb = K + ((size_t)(b * SEQ_KV)) * D_E + h * D_HEAD;
    const float* vb = V + ((size_t)(b * SEQ_KV)) * D_E + h * D_HEAD;

    for (int t = 0; t < NCHUNK; t++) {
        const int kv0 = t * 64;

        // ---- K chunk [64 kv x 128 d] -> B-frag (n=kv, k=d) ----
        #pragma unroll
        for (int i = 0; i < 8; i++) {
            int linear = tid + i * 256;
            int row = linear >> 5;
            int col = (linear & 31) << 2;
            int kv = kv0 + row;
            float4 v = make_float4(0.f, 0.f, 0.f, 0.f);
            if (kv < SEQ_KV)
                v = *reinterpret_cast<const float4*>(kb + (size_t)kv * D_E + col);
            int nt = row >> 3, nn = row & 7;
            float vv[4] = {v.x, v.y, v.z, v.w};
            #pragma unroll
            for (int j = 0; j < 4; j++) {
                int d  = col + j;
                int kt = d >> 3, kk = d & 7;
                Kf[(nt * 16 + kt) * 64 + ((nn << 2) | (kk & 3)) * 2 + (kk >> 2)] = f2tf32(vv[j]);
            }
        }
        // ---- V chunk [64 kv x 128 d] -> B-frag (n=d, k=kv) ----
        #pragma unroll
        for (int i = 0; i < 8; i++) {
            int linear = tid + i * 256;
            int row = linear >> 5;
            int col = (linear & 31) << 2;
            int kv = kv0 + row;
            float4 v = make_float4(0.f, 0.f, 0.f, 0.f);
            if (kv < SEQ_KV)
                v = *reinterpret_cast<const float4*>(vb + (size_t)kv * D_E + col);
            int kt = row >> 3;
            float vv[4] = {v.x, v.y, v.z, v.w};
            #pragma unroll
            for (int j = 0; j < 4; j++) {
                int d  = col + j;
                int nt = d >> 3, dd = d & 7;
                Vf[(nt * 8 + kt) * 64 + ((dd << 2) | (row & 3)) * 2 + ((row >> 2) & 1)] = f2tf32(vv[j]);
            }
        }
        __syncthreads();

        // ---- S = Q @ K^T : warp handles n8-tile = wid ----
        float sacc[4][4];
        #pragma unroll
        for (int mt = 0; mt < 4; mt++)
            #pragma unroll
            for (int c = 0; c < 4; c++) sacc[mt][c] = 0.0f;

        #pragma unroll
        for (int kt = 0; kt < 16; kt++) {
            uint2 bt = *reinterpret_cast<const uint2*>(&Kf[(wid * 16 + kt) * 64 + lane * 2]);
            unsigned bf[2] = {bt.x, bt.y};
            #pragma unroll
            for (int mt = 0; mt < 4; mt++) {
                uint4 at = *reinterpret_cast<const uint4*>(&Qf[(mt * 16 + kt) * 128 + lane * 4]);
                unsigned af[4] = {at.x, at.y, at.z, at.w};
                mma_tf32(sacc[mt], af, bf);
            }
        }
        // write S to smem
        {
            int cbw = wid * 8 + (lane & 3) * 2;
            #pragma unroll
            for (int mt = 0; mt < 4; mt++) {
                int r1 = mt * 16 + (lane >> 2);
                *reinterpret_cast<float2*>(&Ss[r1 * SSS + cbw]) = make_float2(sacc[mt][0], sacc[mt][1]);
                *reinterpret_cast<float2*>(&Ss[(r1 + 8) * SSS + cbw]) = make_float2(sacc[mt][2], sacc[mt][3]);
            }
        }
        __syncthreads();

        // ---- online softmax: 4 threads per row, 16 cols each ----
        {
            int row = tid >> 2, qd = tid & 3;
            float mold = row_m[row];
            float s[16];
            float mx = -1e30f;
            #pragma unroll
            for (int j = 0; j < 16; j++) {
                int c = qd * 16 + j;
                float sv = (kv0 + c < SEQ_KV) ? Ss[row * SSS + c] : -1e30f;
                s[j] = sv;
                mx = fmaxf(mx, sv);
            }
            mx = fmaxf(mx, __shfl_xor_sync(0xffffffffu, mx, 1));
            mx = fmaxf(mx, __shfl_xor_sync(0xffffffffu, mx, 2));
            float mnew = fmaxf(mold, mx);
            int mt = row >> 4, rr = row & 15;
            int lbase = (rr & 7) << 2;
            int rbit  = (rr >> 3) & 1;
            float sum = 0.f;
            #pragma unroll
            for (int j = 0; j < 16; j++) {
                int c = qd * 16 + j;
                float p = __expf(s[j] - mnew);
                sum += p;
                int kt = c >> 3, cc = c & 7;
                Pf[(mt * 8 + kt) * 128 + (lbase | (cc & 3)) * 4 + (rbit | ((cc >> 2) << 1))] = f2tf32(p);
            }
            sum += __shfl_xor_sync(0xffffffffu, sum, 1);
            sum += __shfl_xor_sync(0xffffffffu, sum, 2);
            float sc = __expf(mold - mnew);
            if (qd == 0) {
                row_l[row]  = row_l[row] * sc + sum;
                row_m[row]  = mnew;
                row_sc[row] = sc;
            }
        }
        __syncthreads();

        // ---- rescale O, then O += P @ V ----
        #pragma unroll
        for (int mt = 0; mt < 4; mt++) {
            float s1 = row_sc[mt * 16 + (lane >> 2)];
            float s2 = row_sc[mt * 16 + (lane >> 2) + 8];
            #pragma unroll
            for (int n2 = 0; n2 < 2; n2++) {
                oacc[mt][n2][0] *= s1; oacc[mt][n2][1] *= s1;
                oacc[mt][n2][2] *= s2; oacc[mt][n2][3] *= s2;
            }
        }
        #pragma unroll
        for (int kt = 0; kt < 8; kt++) {
            unsigned af[4][4];
            #pragma unroll
            for (int mt = 0; mt < 4; mt++) {
                uint4 at = *reinterpret_cast<const uint4*>(&Pf[(mt * 8 + kt) * 128 + lane * 4]);
                af[mt][0] = at.x; af[mt][1] = at.y; af[mt][2] = at.z; af[mt][3] = at.w;
            }
            #pragma unroll
            for (int n2 = 0; n2 < 2; n2++) {
                int nt = wid * 2 + n2;
                uint2 bt = *reinterpret_cast<const uint2*>(&Vf[(nt * 8 + kt) * 64 + lane * 2]);
                unsigned bf[2] = {bt.x, bt.y};
                #pragma unroll
                for (int mt = 0; mt < 4; mt++)
                    mma_tf32(oacc[mt][n2], af[mt], bf);
            }
        }
        __syncthreads();
    }

    // ---- normalize + write ----
    float* ob = O + ((size_t)(b * SEQ_Q + q0)) * D_E + h * D_HEAD;
    #pragma unroll
    for (int mt = 0; mt < 4; mt++) {
        int r1 = mt * 16 + (lane >> 2);
        int r2 = r1 + 8;
        float il1 = 1.0f / row_l[r1];
        float il2 = 1.0f / row_l[r2];
        #pragma unroll
        for (int n2 = 0; n2 < 2; n2++) {
            int colg = (wid * 2 + n2) * 8 + (lane & 3) * 2;
            *reinterpret_cast<float2*>(ob + (size_t)r1 * D_E + colg) =
                make_float2(oacc[mt][n2][0] * il1, oacc[mt][n2][1] * il1);
            *reinterpret_cast<float2*>(ob + (size_t)r2 * D_E + colg) =
                make_float2(oacc[mt][n2][2] * il2, oacc[mt][n2][3] * il2);
        }
    }
}

#define FA_SMEM_BYTES ((8192 * 3 + 4096 + 64 * SSS + 192) * 4)

// ============================================================
// launch
// ============================================================
extern "C" void kernel_launch(void* const* d_in, const int* in_sizes, int n_in,
                              void* d_out, int out_size)
{
    const float* x  = (const float*)d_in[0];
    const float* y  = (const float*)d_in[1];
    const float* Wq = (const float*)d_in[2];
    const float* bq = (const float*)d_in[3];
    const float* Wk = (const float*)d_in[4];
    const float* bk = (const float*)d_in[5];
    const float* Wv = (const float*)d_in[6];
    const float* bv = (const float*)d_in[7];
    const float* Wo = (const float*)d_in[8];
    const float* bo = (const float*)d_in[9];
    float* out = (float*)d_out;

    float *pQ, *pK, *pV, *pO;
    cudaGetSymbolAddress((void**)&pQ, g_Q);
    cudaGetSymbolAddress((void**)&pK, g_K);
    cudaGetSymbolAddress((void**)&pV, g_V);
    cudaGetSymbolAddress((void**)&pO, g_O);

    // projections
    gemm_tf32<<<dim3(D_E / 128, (MQ + 127) / 128), 256>>>(x, Wq, bq, pQ, MQ, D_E, D_E);
    gemm_tf32<<<dim3(D_E / 128, (MKV + 127) / 128), 256>>>(y, Wk, bk, pK, MKV, D_E, D_C);
    gemm_tf32<<<dim3(D_E / 128, (MKV + 127) / 128), 256>>>(y, Wv, bv, pV, MKV, D_E, D_C);

    // attention
    cudaFuncSetAttribute(fa_tf32, cudaFuncAttributeMaxDynamicSharedMemorySize, FA_SMEM_BYTES);
    fa_tf32<<<dim3(SEQ_Q / 64, N_HEADS, BATCH), 256, FA_SMEM_BYTES>>>(pQ, pK, pV, pO);

    // output projection -> d_out
    gemm_tf32<<<dim3(D_E / 128, (MQ + 127) / 128), 256>>>(pO, Wo, bo, out, MQ, D_E, D_E);
}

// round 4
// speedup vs baseline: 2.1822x; 1.5609x over previous
#include <cuda_runtime.h>
#include <cuda_bf16.h>
#include <math.h>

// ---------------- problem constants ----------------
#define BATCH   4
#define SEQ_Q   3072
#define SEQ_KV  1036
#define D_E     1024
#define D_C     768
#define N_HEADS 8
#define D_HEAD  128

#define MQ (BATCH * SEQ_Q)    // 12288
#define MKV (BATCH * SEQ_KV)  // 4144

// ---------------- scratch ----------------
__device__ float g_Q[(size_t)MQ * D_E];
__device__ float g_K[(size_t)MKV * D_E];
__device__ float g_V[(size_t)MKV * D_E];
__device__ float g_O[(size_t)MQ * D_E];

// ---------------- helpers ----------------
__device__ __forceinline__ unsigned f2tf32(float x) {
    unsigned r;
    asm("cvt.rna.tf32.f32 %0, %1;" : "=r"(r) : "f"(x));
    return r;
}

// D = A(16x8, row) * B(8x8, col) + D, fp32 accum, tf32 inputs
__device__ __forceinline__ void mma_tf32(float d[4], const unsigned a[4], const unsigned b[2]) {
    asm volatile(
        "mma.sync.aligned.m16n8k8.row.col.f32.tf32.tf32.f32 "
        "{%0,%1,%2,%3}, {%4,%5,%6,%7}, {%8,%9}, {%0,%1,%2,%3};\n"
        : "+f"(d[0]), "+f"(d[1]), "+f"(d[2]), "+f"(d[3])
        : "r"(a[0]), "r"(a[1]), "r"(a[2]), "r"(a[3]),
          "r"(b[0]), "r"(b[1]));
}

// ============================================================
// tf32 tensor-core GEMM: C[M,N] = A[M,K] @ W[N,K]^T + bias
// block 128x128x32, 8 warps (warp tile 64x32)
// ============================================================
__global__ __launch_bounds__(256, 2) void gemm_tf32(
    const float* __restrict__ A, const float* __restrict__ W,
    const float* __restrict__ bias, float* __restrict__ C,
    int M, int N, int K)
{
    __shared__ unsigned sA[8 * 4 * 128];
    __shared__ unsigned sB[16 * 4 * 64];

    const int tid  = threadIdx.x;
    const int lane = tid & 31;
    const int wid  = tid >> 5;
    const int wm   = wid >> 2;
    const int wn   = wid & 3;
    const int m0   = blockIdx.y * 128;
    const int n0   = blockIdx.x * 128;

    float acc[4][4][4];
    #pragma unroll
    for (int i = 0; i < 4; i++)
        #pragma unroll
        for (int j = 0; j < 4; j++)
            #pragma unroll
            for (int c = 0; c < 4; c++) acc[i][j][c] = 0.0f;

    for (int k0 = 0; k0 < K; k0 += 32) {
        #pragma unroll
        for (int i = 0; i < 4; i++) {
            int linear = tid + i * 256;
            int row = linear >> 3;
            int col = (linear & 7) << 2;
            float4 v = make_float4(0.f, 0.f, 0.f, 0.f);
            if (m0 + row < M)
                v = *reinterpret_cast<const float4*>(A + (size_t)(m0 + row) * K + k0 + col);
            int mt = row >> 4, r = row & 15;
            int lbase = (r & 7) << 2;
            int rbit  = (r >> 3) & 1;
            float vv[4] = {v.x, v.y, v.z, v.w};
            #pragma unroll
            for (int j = 0; j < 4; j++) {
                int c  = col + j;
                int kt = c >> 3, kk = c & 7;
                sA[(mt * 4 + kt) * 128 + (lbase | (kk & 3)) * 4 + (rbit | ((kk >> 2) << 1))] =
                    f2tf32(vv[j]);
            }
        }
        #pragma unroll
        for (int i = 0; i < 4; i++) {
            int linear = tid + i * 256;
            int row = linear >> 3;
            int col = (linear & 7) << 2;
            float4 v = *reinterpret_cast<const float4*>(W + (size_t)(n0 + row) * K + k0 + col);
            int nt = row >> 3, nn = row & 7;
            float vv[4] = {v.x, v.y, v.z, v.w};
            #pragma unroll
            for (int j = 0; j < 4; j++) {
                int c  = col + j;
                int kt = c >> 3, kk = c & 7;
                sB[(nt * 4 + kt) * 64 + ((nn << 2) | (kk & 3)) * 2 + (kk >> 2)] = f2tf32(vv[j]);
            }
        }
        __syncthreads();

        #pragma unroll
        for (int kt = 0; kt < 4; kt++) {
            unsigned af[4][4];
            unsigned bf[4][2];
            #pragma unroll
            for (int mi = 0; mi < 4; mi++) {
                uint4 t = *reinterpret_cast<const uint4*>(&sA[((wm * 4 + mi) * 4 + kt) * 128 + lane * 4]);
                af[mi][0] = t.x; af[mi][1] = t.y; af[mi][2] = t.z; af[mi][3] = t.w;
            }
            #pragma unroll
            for (int ni = 0; ni < 4; ni++) {
                uint2 t = *reinterpret_cast<const uint2*>(&sB[((wn * 4 + ni) * 4 + kt) * 64 + lane * 2]);
                bf[ni][0] = t.x; bf[ni][1] = t.y;
            }
            #pragma unroll
            for (int mi = 0; mi < 4; mi++)
                #pragma unroll
                for (int ni = 0; ni < 4; ni++)
                    mma_tf32(acc[mi][ni], af[mi], bf[ni]);
        }
        __syncthreads();
    }

    const int rb = lane >> 2;
    const int cb = (lane & 3) * 2;
    #pragma unroll
    for (int mi = 0; mi < 4; mi++) {
        int row1 = m0 + (wm * 4 + mi) * 16 + rb;
        int row2 = row1 + 8;
        #pragma unroll
        for (int ni = 0; ni < 4; ni++) {
            int colg = n0 + (wn * 4 + ni) * 8 + cb;
            float b0 = bias[colg], b1 = bias[colg + 1];
            if (row1 < M) {
                float2 o = make_float2(acc[mi][ni][0] + b0, acc[mi][ni][1] + b1);
                *reinterpret_cast<float2*>(C + (size_t)row1 * N + colg) = o;
            }
            if (row2 < M) {
                float2 o = make_float2(acc[mi][ni][2] + b0, acc[mi][ni][3] + b1);
                *reinterpret_cast<float2*>(C + (size_t)row2 * N + colg) = o;
            }
        }
    }
}

// ============================================================
// tf32 flash attention, register-resident softmax
// CTA: 128 q rows, 8 warps (warp = 16 q rows), kv chunks of 64
// smem: only K-frag + V-frag tiles (64KB)
// ============================================================
#define NCHUNK 17   // 17*64 = 1088 >= 1036

__global__ __launch_bounds__(256, 1) void fa2_tf32(
    const float* __restrict__ Q, const float* __restrict__ K,
    const float* __restrict__ V, float* __restrict__ O)
{
    extern __shared__ unsigned fsm[];
    unsigned* Kf = fsm;            // 8 nt * 16 kt * 64 = 8192
    unsigned* Vf = fsm + 8192;     // 16 nt * 8 kt * 64 = 8192

    const int tid  = threadIdx.x;
    const int lane = tid & 31;
    const int wid  = tid >> 5;
    const int r    = lane >> 2;      // row-in-16 (and +8)
    const int c    = lane & 3;
    const int q0   = blockIdx.x * 128;
    const int h    = blockIdx.y;
    const int b    = blockIdx.z;
    const float scale = 0.08838834764831845f;  // 1/sqrt(128)

    // ---- Q -> register A-fragments (once) ----
    unsigned qf[16][4];
    {
        const float* qb = Q + ((size_t)(b * SEQ_Q + q0 + wid * 16)) * D_E + h * D_HEAD;
        #pragma unroll
        for (int kt = 0; kt < 16; kt++) {
            int d0 = kt * 8 + c;
            qf[kt][0] = f2tf32(scale * __ldg(qb + (size_t)r * D_E + d0));
            qf[kt][1] = f2tf32(scale * __ldg(qb + (size_t)(r + 8) * D_E + d0));
            qf[kt][2] = f2tf32(scale * __ldg(qb + (size_t)r * D_E + d0 + 4));
            qf[kt][3] = f2tf32(scale * __ldg(qb + (size_t)(r + 8) * D_E + d0 + 4));
        }
    }

    float oacc[16][4];
    #pragma unroll
    for (int nt = 0; nt < 16; nt++)
        #pragma unroll
        for (int e = 0; e < 4; e++) oacc[nt][e] = 0.0f;

    float row_m0 = -1e30f, row_m1 = -1e30f;
    float row_l0 = 0.0f,   row_l1 = 0.0f;

    const float* kb = K + ((size_t)(b * SEQ_KV)) * D_E + h * D_HEAD;
    const float* vb = V + ((size_t)(b * SEQ_KV)) * D_E + h * D_HEAD;

    for (int t = 0; t < NCHUNK; t++) {
        const int kv0 = t * 64;
        __syncthreads();   // previous chunk's consumers done

        // ---- K chunk [64 kv x 128 d] -> B-frag (n=kv, k=d) ----
        #pragma unroll
        for (int i = 0; i < 8; i++) {
            int linear = tid + i * 256;      // 2048 float4 slots
            int row = linear >> 5;           // kv local 0..63
            int col = (linear & 31) << 2;    // d
            int kv = kv0 + row;
            float4 v = make_float4(0.f, 0.f, 0.f, 0.f);
            if (kv < SEQ_KV)
                v = *reinterpret_cast<const float4*>(kb + (size_t)kv * D_E + col);
            int nt = row >> 3, nn = row & 7;
            float vv[4] = {v.x, v.y, v.z, v.w};
            #pragma unroll
            for (int j = 0; j < 4; j++) {
                int d  = col + j;
                int kt = d >> 3, kk = d & 7;
                Kf[(nt * 16 + kt) * 64 + ((nn << 2) | (kk & 3)) * 2 + (kk >> 2)] = f2tf32(vv[j]);
            }
        }
        // ---- V chunk [64 kv x 128 d] -> B-frag (n=d, k=kv) ----
        #pragma unroll
        for (int i = 0; i < 8; i++) {
            int linear = tid + i * 256;
            int row = linear >> 5;
            int col = (linear & 31) << 2;
            int kv = kv0 + row;
            float4 v = make_float4(0.f, 0.f, 0.f, 0.f);
            if (kv < SEQ_KV)
                v = *reinterpret_cast<const float4*>(vb + (size_t)kv * D_E + col);
            int kt = row >> 3;
            float vv[4] = {v.x, v.y, v.z, v.w};
            #pragma unroll
            for (int j = 0; j < 4; j++) {
                int d  = col + j;
                int nt = d >> 3, dd = d & 7;
                Vf[(nt * 8 + kt) * 64 + ((dd << 2) | (row & 3)) * 2 + ((row >> 2) & 1)] = f2tf32(vv[j]);
            }
        }
        __syncthreads();

        // ---- S = Q @ K^T : warp's 16 rows x 64 kv in registers ----
        float sacc[8][4];
        #pragma unroll
        for (int ni = 0; ni < 8; ni++)
            #pragma unroll
            for (int e = 0; e < 4; e++) sacc[ni][e] = 0.0f;

        #pragma unroll
        for (int kt = 0; kt < 16; kt++) {
            #pragma unroll
            for (int ni = 0; ni < 8; ni++) {
                uint2 bt = *reinterpret_cast<const uint2*>(&Kf[(ni * 16 + kt) * 64 + lane * 2]);
                unsigned bf[2] = {bt.x, bt.y};
                mma_tf32(sacc[ni], qf[kt], bf);
            }
        }

        // ---- mask + register softmax ----
        float mx0 = -1e30f, mx1 = -1e30f;
        #pragma unroll
        for (int ni = 0; ni < 8; ni++) {
            int colg = kv0 + ni * 8 + c * 2;       // even; colg+1 OOB iff colg OOB
            if (colg >= SEQ_KV) {
                sacc[ni][0] = -1e30f; sacc[ni][1] = -1e30f;
                sacc[ni][2] = -1e30f; sacc[ni][3] = -1e30f;
            }
            mx0 = fmaxf(mx0, fmaxf(sacc[ni][0], sacc[ni][1]));
            mx1 = fmaxf(mx1, fmaxf(sacc[ni][2], sacc[ni][3]));
        }
        mx0 = fmaxf(mx0, __shfl_xor_sync(0xffffffffu, mx0, 1));
        mx0 = fmaxf(mx0, __shfl_xor_sync(0xffffffffu, mx0, 2));
        mx1 = fmaxf(mx1, __shfl_xor_sync(0xffffffffu, mx1, 1));
        mx1 = fmaxf(mx1, __shfl_xor_sync(0xffffffffu, mx1, 2));

        float mnew0 = fmaxf(row_m0, mx0);
        float mnew1 = fmaxf(row_m1, mx1);
        float sc0 = __expf(row_m0 - mnew0);
        float sc1 = __expf(row_m1 - mnew1);
        row_m0 = mnew0; row_m1 = mnew1;

        float sum0 = 0.f, sum1 = 0.f;
        #pragma unroll
        for (int ni = 0; ni < 8; ni++) {
            sacc[ni][0] = __expf(sacc[ni][0] - mnew0);
            sacc[ni][1] = __expf(sacc[ni][1] - mnew0);
            sacc[ni][2] = __expf(sacc[ni][2] - mnew1);
            sacc[ni][3] = __expf(sacc[ni][3] - mnew1);
            sum0 += sacc[ni][0] + sacc[ni][1];
            sum1 += sacc[ni][2] + sacc[ni][3];
        }
        sum0 += __shfl_xor_sync(0xffffffffu, sum0, 1);
        sum0 += __shfl_xor_sync(0xffffffffu, sum0, 2);
        sum1 += __shfl_xor_sync(0xffffffffu, sum1, 1);
        sum1 += __shfl_xor_sync(0xffffffffu, sum1, 2);
        row_l0 = row_l0 * sc0 + sum0;
        row_l1 = row_l1 * sc1 + sum1;

        // rescale O accumulators
        #pragma unroll
        for (int nt = 0; nt < 16; nt++) {
            oacc[nt][0] *= sc0; oacc[nt][1] *= sc0;
            oacc[nt][2] *= sc1; oacc[nt][3] *= sc1;
        }

        // ---- P (C-frag) -> A-frag via quad shuffles, then O += P @ V ----
        const int qbase = lane & ~3;
        #pragma unroll
        for (int kt = 0; kt < 8; kt++) {
            float s0 = sacc[kt][0], s1 = sacc[kt][1];
            float s2 = sacc[kt][2], s3 = sacc[kt][3];
            int srcA = qbase + (c >> 1);
            int srcB = srcA + 2;
            float u0 = __shfl_sync(0xffffffffu, s0, srcA);
            float u1 = __shfl_sync(0xffffffffu, s1, srcA);
            float v0 = __shfl_sync(0xffffffffu, s0, srcB);
            float v1 = __shfl_sync(0xffffffffu, s1, srcB);
            float w0 = __shfl_sync(0xffffffffu, s2, srcA);
            float w1 = __shfl_sync(0xffffffffu, s3, srcA);
            float x0 = __shfl_sync(0xffffffffu, s2, srcB);
            float x1 = __shfl_sync(0xffffffffu, s3, srcB);
            bool odd = (c & 1);
            unsigned pa[4];
            pa[0] = f2tf32(odd ? u1 : u0);   // (r,   c)
            pa[1] = f2tf32(odd ? w1 : w0);   // (r+8, c)
            pa[2] = f2tf32(odd ? v1 : v0);   // (r,   c+4)
            pa[3] = f2tf32(odd ? x1 : x0);   // (r+8, c+4)

            #pragma unroll
            for (int nt = 0; nt < 16; nt++) {
                uint2 bt = *reinterpret_cast<const uint2*>(&Vf[(nt * 8 + kt) * 64 + lane * 2]);
                unsigned bf[2] = {bt.x, bt.y};
                mma_tf32(oacc[nt], pa, bf);
            }
        }
    }

    // ---- normalize + write ----
    float inv0 = 1.0f / row_l0;
    float inv1 = 1.0f / row_l1;
    float* ob = O + ((size_t)(b * SEQ_Q + q0 + wid * 16 + r)) * D_E + h * D_HEAD;
    #pragma unroll
    for (int nt = 0; nt < 16; nt++) {
        int colg = nt * 8 + c * 2;
        *reinterpret_cast<float2*>(ob + colg) =
            make_float2(oacc[nt][0] * inv0, oacc[nt][1] * inv0);
        *reinterpret_cast<float2*>(ob + (size_t)8 * D_E + colg) =
            make_float2(oacc[nt][2] * inv1, oacc[nt][3] * inv1);
    }
}

#define FA2_SMEM_BYTES (16384 * 4)

// ============================================================
// launch
// ============================================================
extern "C" void kernel_launch(void* const* d_in, const int* in_sizes, int n_in,
                              void* d_out, int out_size)
{
    const float* x  = (const float*)d_in[0];
    const float* y  = (const float*)d_in[1];
    const float* Wq = (const float*)d_in[2];
    const float* bq = (const float*)d_in[3];
    const float* Wk = (const float*)d_in[4];
    const float* bk = (const float*)d_in[5];
    const float* Wv = (const float*)d_in[6];
    const float* bv = (const float*)d_in[7];
    const float* Wo = (const float*)d_in[8];
    const float* bo = (const float*)d_in[9];
    float* out = (float*)d_out;

    float *pQ, *pK, *pV, *pO;
    cudaGetSymbolAddress((void**)&pQ, g_Q);
    cudaGetSymbolAddress((void**)&pK, g_K);
    cudaGetSymbolAddress((void**)&pV, g_V);
    cudaGetSymbolAddress((void**)&pO, g_O);

    // projections
    gemm_tf32<<<dim3(D_E / 128, (MQ + 127) / 128), 256>>>(x, Wq, bq, pQ, MQ, D_E, D_E);
    gemm_tf32<<<dim3(D_E / 128, (MKV + 127) / 128), 256>>>(y, Wk, bk, pK, MKV, D_E, D_C);
    gemm_tf32<<<dim3(D_E / 128, (MKV + 127) / 128), 256>>>(y, Wv, bv, pV, MKV, D_E, D_C);

    // attention
    cudaFuncSetAttribute(fa2_tf32, cudaFuncAttributeMaxDynamicSharedMemorySize, FA2_SMEM_BYTES);
    fa2_tf32<<<dim3(SEQ_Q / 128, N_HEADS, BATCH), 256, FA2_SMEM_BYTES>>>(pQ, pK, pV, pO);

    // output projection -> d_out
    gemm_tf32<<<dim3(D_E / 128, (MQ + 127) / 128), 256>>>(pO, Wo, bo, out, MQ, D_E, D_E);
}

// round 5
// speedup vs baseline: 2.2811x; 1.0453x over previous
#include <cuda_runtime.h>
#include <cuda_bf16.h>
#include <math.h>

// ---------------- problem constants ----------------
#define BATCH   4
#define SEQ_Q   3072
#define SEQ_KV  1036
#define D_E     1024
#define D_C     768
#define N_HEADS 8
#define D_HEAD  128

#define MQ (BATCH * SEQ_Q)    // 12288
#define MKV (BATCH * SEQ_KV)  // 4144

// ---------------- scratch ----------------
__device__ float g_Q[(size_t)MQ * D_E];
__device__ float g_K[(size_t)MKV * D_E];
__device__ float g_V[(size_t)MKV * D_E];
__device__ float g_O[(size_t)MQ * D_E];

// ---------------- helpers ----------------
__device__ __forceinline__ unsigned f2tf32(float x) {
    unsigned r;
    asm("cvt.rna.tf32.f32 %0, %1;" : "=r"(r) : "f"(x));
    return r;
}

// D = A(16x8, row) * B(8x8, col) + D, fp32 accum, tf32 inputs
__device__ __forceinline__ void mma_tf32(float d[4], const unsigned a[4], const unsigned b[2]) {
    asm volatile(
        "mma.sync.aligned.m16n8k8.row.col.f32.tf32.tf32.f32 "
        "{%0,%1,%2,%3}, {%4,%5,%6,%7}, {%8,%9}, {%0,%1,%2,%3};\n"
        : "+f"(d[0]), "+f"(d[1]), "+f"(d[2]), "+f"(d[3])
        : "r"(a[0]), "r"(a[1]), "r"(a[2]), "r"(a[3]),
          "r"(b[0]), "r"(b[1]));
}

// ============================================================
// tf32 tensor-core GEMM: C[M,N] = A[M,K] @ W[N,K]^T + bias
// block 128x128x32, 8 warps (warp tile 64x32)
// smem in fragment order; WRITERS are linear (conflict-free STS),
// gathering gmem via the inverse permutation.
// ============================================================
__global__ __launch_bounds__(256, 2) void gemm_tf32(
    const float* __restrict__ A, const float* __restrict__ W,
    const float* __restrict__ bias, float* __restrict__ C,
    int M, int N, int K)
{
    __shared__ unsigned sA[8 * 4 * 128];   // [mt*4+kt][lane*4+reg]
    __shared__ unsigned sB[16 * 4 * 64];   // [nt*4+kt][lane*2+reg]

    const int tid  = threadIdx.x;
    const int lane = tid & 31;
    const int wid  = tid >> 5;
    const int wm   = wid >> 2;
    const int wn   = wid & 3;
    const int m0   = blockIdx.y * 128;
    const int n0   = blockIdx.x * 128;

    float acc[4][4][4];
    #pragma unroll
    for (int i = 0; i < 4; i++)
        #pragma unroll
        for (int j = 0; j < 4; j++)
            #pragma unroll
            for (int c = 0; c < 4; c++) acc[i][j][c] = 0.0f;

    for (int k0 = 0; k0 < K; k0 += 32) {
        // ---- sA: linear STS.128, inverse-permutation gather ----
        // word w in tile: l=w>>2, reg=w&3 ; r=(l>>2)|((reg&1)<<3), kk=(l&3)|((reg>>1)<<2)
        #pragma unroll
        for (int i = 0; i < 4; i++) {
            int u = tid + i * 256;          // uint4 slot, 0..1023
            int tile = u >> 5;              // mt*4 + kt
            int l = u & 31;
            int mt = tile >> 2, kt = tile & 3;
            int rbase = m0 + mt * 16 + (l >> 2);
            const float* ap = A + (size_t)rbase * K + k0 + kt * 8 + (l & 3);
            float a0 = 0.f, a1 = 0.f, a2 = 0.f, a3 = 0.f;
            if (rbase < M)     { a0 = ap[0];              a2 = ap[4]; }
            if (rbase + 8 < M) { a1 = ap[(size_t)8 * K];  a3 = ap[(size_t)8 * K + 4]; }
            uint4 o;
            o.x = f2tf32(a0); o.y = f2tf32(a1);
            o.z = f2tf32(a2); o.w = f2tf32(a3);
            *reinterpret_cast<uint4*>(&sA[tile * 128 + l * 4]) = o;
        }
        // ---- sB: linear STS.64, inverse-permutation gather ----
        // word w: l=w>>1, reg=w&1 ; n=nt*8+(l>>2), k=kt*8+(l&3)+4*reg
        #pragma unroll
        for (int i = 0; i < 8; i++) {
            int u = tid + i * 256;          // uint2 slot, 0..2047
            int tile = u >> 5;              // nt*4 + kt
            int l = u & 31;
            int nt = tile >> 2, kt = tile & 3;
            const float* wp = W + (size_t)(n0 + nt * 8 + (l >> 2)) * K + k0 + kt * 8 + (l & 3);
            uint2 o;
            o.x = f2tf32(wp[0]);
            o.y = f2tf32(wp[4]);
            *reinterpret_cast<uint2*>(&sB[tile * 64 + l * 2]) = o;
        }
        __syncthreads();

        #pragma unroll
        for (int kt = 0; kt < 4; kt++) {
            unsigned af[4][4];
            unsigned bf[4][2];
            #pragma unroll
            for (int mi = 0; mi < 4; mi++) {
                uint4 t = *reinterpret_cast<const uint4*>(&sA[((wm * 4 + mi) * 4 + kt) * 128 + lane * 4]);
                af[mi][0] = t.x; af[mi][1] = t.y; af[mi][2] = t.z; af[mi][3] = t.w;
            }
            #pragma unroll
            for (int ni = 0; ni < 4; ni++) {
                uint2 t = *reinterpret_cast<const uint2*>(&sB[((wn * 4 + ni) * 4 + kt) * 64 + lane * 2]);
                bf[ni][0] = t.x; bf[ni][1] = t.y;
            }
            #pragma unroll
            for (int mi = 0; mi < 4; mi++)
                #pragma unroll
                for (int ni = 0; ni < 4; ni++)
                    mma_tf32(acc[mi][ni], af[mi], bf[ni]);
        }
        __syncthreads();
    }

    const int rb = lane >> 2;
    const int cb = (lane & 3) * 2;
    #pragma unroll
    for (int mi = 0; mi < 4; mi++) {
        int row1 = m0 + (wm * 4 + mi) * 16 + rb;
        int row2 = row1 + 8;
        #pragma unroll
        for (int ni = 0; ni < 4; ni++) {
            int colg = n0 + (wn * 4 + ni) * 8 + cb;
            float b0 = bias[colg], b1 = bias[colg + 1];
            if (row1 < M) {
                float2 o = make_float2(acc[mi][ni][0] + b0, acc[mi][ni][1] + b1);
                *reinterpret_cast<float2*>(C + (size_t)row1 * N + colg) = o;
            }
            if (row2 < M) {
                float2 o = make_float2(acc[mi][ni][2] + b0, acc[mi][ni][3] + b1);
                *reinterpret_cast<float2*>(C + (size_t)row2 * N + colg) = o;
            }
        }
    }
}

// ============================================================
// tf32 flash attention, register softmax, conflict-free staging
// CTA: 128 q rows, 8 warps (warp = 16 q rows), kv chunks of 64
// ============================================================
#define NCHUNK 17   // 17*64 = 1088 >= 1036

__global__ __launch_bounds__(256, 1) void fa2_tf32(
    const float* __restrict__ Q, const float* __restrict__ K,
    const float* __restrict__ V, float* __restrict__ O)
{
    extern __shared__ unsigned fsm[];
    unsigned* Kf = fsm;            // [nt(8)*16+kt(16)][lane*2+reg] = 8192
    unsigned* Vf = fsm + 8192;     // [nt(16)*8+kt(8)][lane*2+reg]  = 8192

    const int tid  = threadIdx.x;
    const int lane = tid & 31;
    const int wid  = tid >> 5;
    const int r    = lane >> 2;
    const int c    = lane & 3;
    const int q0   = blockIdx.x * 128;
    const int h    = blockIdx.y;
    const int b    = blockIdx.z;
    const float scale = 0.08838834764831845f;  // 1/sqrt(128)

    // ---- Q -> register A-fragments (once) ----
    unsigned qf[16][4];
    {
        const float* qb = Q + ((size_t)(b * SEQ_Q + q0 + wid * 16)) * D_E + h * D_HEAD;
        #pragma unroll
        for (int kt = 0; kt < 16; kt++) {
            int d0 = kt * 8 + c;
            qf[kt][0] = f2tf32(scale * __ldg(qb + (size_t)r * D_E + d0));
            qf[kt][1] = f2tf32(scale * __ldg(qb + (size_t)(r + 8) * D_E + d0));
            qf[kt][2] = f2tf32(scale * __ldg(qb + (size_t)r * D_E + d0 + 4));
            qf[kt][3] = f2tf32(scale * __ldg(qb + (size_t)(r + 8) * D_E + d0 + 4));
        }
    }

    float oacc[16][4];
    #pragma unroll
    for (int nt = 0; nt < 16; nt++)
        #pragma unroll
        for (int e = 0; e < 4; e++) oacc[nt][e] = 0.0f;

    float row_m0 = -1e30f, row_m1 = -1e30f;
    float row_l0 = 0.0f,   row_l1 = 0.0f;

    const float* kb = K + ((size_t)(b * SEQ_KV)) * D_E + h * D_HEAD;
    const float* vb = V + ((size_t)(b * SEQ_KV)) * D_E + h * D_HEAD;

    for (int t = 0; t < NCHUNK; t++) {
        const int kv0 = t * 64;
        __syncthreads();   // previous chunk's consumers done

        // ---- Kf: linear STS.64, gather K[kv][d] (B-frag: n=kv, k=d) ----
        // tile = nt*16+kt ; kv = kv0+nt*8+(l>>2) ; d = kt*8+(l&3)+{0,4}
        #pragma unroll
        for (int i = 0; i < 16; i++) {
            int u = tid + i * 256;          // uint2 slot, 0..4095
            int tile = u >> 5;
            int l = u & 31;
            int nt = tile >> 4, kt = tile & 15;
            int kv = kv0 + nt * 8 + (l >> 2);
            float k0v = 0.f, k1v = 0.f;
            if (kv < SEQ_KV) {
                const float* kp = kb + (size_t)kv * D_E + kt * 8 + (l & 3);
                k0v = kp[0]; k1v = kp[4];
            }
            uint2 o; o.x = f2tf32(k0v); o.y = f2tf32(k1v);
            *reinterpret_cast<uint2*>(&Kf[tile * 64 + l * 2]) = o;
        }
        // ---- Vf: linear STS.64, gather V[kv][d] (B-frag: n=d, k=kv) ----
        // tile = nt*8+kt ; d = nt*8+(l>>2) ; kv = kv0+kt*8+(l&3)+{0,4}
        #pragma unroll
        for (int i = 0; i < 16; i++) {
            int u = tid + i * 256;
            int tile = u >> 5;
            int l = u & 31;
            int nt = tile >> 3, kt = tile & 7;
            int d = nt * 8 + (l >> 2);
            int kv = kv0 + kt * 8 + (l & 3);
            float v0 = 0.f, v1 = 0.f;
            if (kv < SEQ_KV)     v0 = vb[(size_t)kv * D_E + d];
            if (kv + 4 < SEQ_KV) v1 = vb[(size_t)(kv + 4) * D_E + d];
            uint2 o; o.x = f2tf32(v0); o.y = f2tf32(v1);
            *reinterpret_cast<uint2*>(&Vf[tile * 64 + l * 2]) = o;
        }
        __syncthreads();

        // ---- S = Q @ K^T in registers ----
        float sacc[8][4];
        #pragma unroll
        for (int ni = 0; ni < 8; ni++)
            #pragma unroll
            for (int e = 0; e < 4; e++) sacc[ni][e] = 0.0f;

        #pragma unroll
        for (int kt = 0; kt < 16; kt++) {
            #pragma unroll
            for (int ni = 0; ni < 8; ni++) {
                uint2 bt = *reinterpret_cast<const uint2*>(&Kf[(ni * 16 + kt) * 64 + lane * 2]);
                unsigned bf[2] = {bt.x, bt.y};
                mma_tf32(sacc[ni], qf[kt], bf);
            }
        }

        // ---- mask + register softmax ----
        float mx0 = -1e30f, mx1 = -1e30f;
        #pragma unroll
        for (int ni = 0; ni < 8; ni++) {
            int colg = kv0 + ni * 8 + c * 2;
            if (colg >= SEQ_KV) {
                sacc[ni][0] = -1e30f; sacc[ni][1] = -1e30f;
                sacc[ni][2] = -1e30f; sacc[ni][3] = -1e30f;
            }
            mx0 = fmaxf(mx0, fmaxf(sacc[ni][0], sacc[ni][1]));
            mx1 = fmaxf(mx1, fmaxf(sacc[ni][2], sacc[ni][3]));
        }
        mx0 = fmaxf(mx0, __shfl_xor_sync(0xffffffffu, mx0, 1));
        mx0 = fmaxf(mx0, __shfl_xor_sync(0xffffffffu, mx0, 2));
        mx1 = fmaxf(mx1, __shfl_xor_sync(0xffffffffu, mx1, 1));
        mx1 = fmaxf(mx1, __shfl_xor_sync(0xffffffffu, mx1, 2));

        float mnew0 = fmaxf(row_m0, mx0);
        float mnew1 = fmaxf(row_m1, mx1);
        float sc0 = __expf(row_m0 - mnew0);
        float sc1 = __expf(row_m1 - mnew1);
        row_m0 = mnew0; row_m1 = mnew1;

        float sum0 = 0.f, sum1 = 0.f;
        #pragma unroll
        for (int ni = 0; ni < 8; ni++) {
            sacc[ni][0] = __expf(sacc[ni][0] - mnew0);
            sacc[ni][1] = __expf(sacc[ni][1] - mnew0);
            sacc[ni][2] = __expf(sacc[ni][2] - mnew1);
            sacc[ni][3] = __expf(sacc[ni][3] - mnew1);
            sum0 += sacc[ni][0] + sacc[ni][1];
            sum1 += sacc[ni][2] + sacc[ni][3];
        }
        sum0 += __shfl_xor_sync(0xffffffffu, sum0, 1);
        sum0 += __shfl_xor_sync(0xffffffffu, sum0, 2);
        sum1 += __shfl_xor_sync(0xffffffffu, sum1, 1);
        sum1 += __shfl_xor_sync(0xffffffffu, sum1, 2);
        row_l0 = row_l0 * sc0 + sum0;
        row_l1 = row_l1 * sc1 + sum1;

        #pragma unroll
        for (int nt = 0; nt < 16; nt++) {
            oacc[nt][0] *= sc0; oacc[nt][1] *= sc0;
            oacc[nt][2] *= sc1; oacc[nt][3] *= sc1;
        }

        // ---- P (C-frag) -> A-frag via quad shuffles, then O += P @ V ----
        const int qbase = lane & ~3;
        #pragma unroll
        for (int kt = 0; kt < 8; kt++) {
            float s0 = sacc[kt][0], s1 = sacc[kt][1];
            float s2 = sacc[kt][2], s3 = sacc[kt][3];
            int srcA = qbase + (c >> 1);
            int srcB = srcA + 2;
            float u0 = __shfl_sync(0xffffffffu, s0, srcA);
            float u1 = __shfl_sync(0xffffffffu, s1, srcA);
            float v0 = __shfl_sync(0xffffffffu, s0, srcB);
            float v1 = __shfl_sync(0xffffffffu, s1, srcB);
            float w0 = __shfl_sync(0xffffffffu, s2, srcA);
            float w1 = __shfl_sync(0xffffffffu, s3, srcA);
            float x0 = __shfl_sync(0xffffffffu, s2, srcB);
            float x1 = __shfl_sync(0xffffffffu, s3, srcB);
            bool odd = (c & 1);
            unsigned pa[4];
            pa[0] = f2tf32(odd ? u1 : u0);
            pa[1] = f2tf32(odd ? w1 : w0);
            pa[2] = f2tf32(odd ? v1 : v0);
            pa[3] = f2tf32(odd ? x1 : x0);

            #pragma unroll
            for (int nt = 0; nt < 16; nt++) {
                uint2 bt = *reinterpret_cast<const uint2*>(&Vf[(nt * 8 + kt) * 64 + lane * 2]);
                unsigned bf[2] = {bt.x, bt.y};
                mma_tf32(oacc[nt], pa, bf);
            }
        }
    }

    // ---- normalize + write ----
    float inv0 = 1.0f / row_l0;
    float inv1 = 1.0f / row_l1;
    float* ob = O + ((size_t)(b * SEQ_Q + q0 + wid * 16 + r)) * D_E + h * D_HEAD;
    #pragma unroll
    for (int nt = 0; nt < 16; nt++) {
        int colg = nt * 8 + c * 2;
        *reinterpret_cast<float2*>(ob + colg) =
            make_float2(oacc[nt][0] * inv0, oacc[nt][1] * inv0);
        *reinterpret_cast<float2*>(ob + (size_t)8 * D_E + colg) =
            make_float2(oacc[nt][2] * inv1, oacc[nt][3] * inv1);
    }
}

#define FA2_SMEM_BYTES (16384 * 4)

// ============================================================
// launch
// ============================================================
extern "C" void kernel_launch(void* const* d_in, const int* in_sizes, int n_in,
                              void* d_out, int out_size)
{
    const float* x  = (const float*)d_in[0];
    const float* y  = (const float*)d_in[1];
    const float* Wq = (const float*)d_in[2];
    const float* bq = (const float*)d_in[3];
    const float* Wk = (const float*)d_in[4];
    const float* bk = (const float*)d_in[5];
    const float* Wv = (const float*)d_in[6];
    const float* bv = (const float*)d_in[7];
    const float* Wo = (const float*)d_in[8];
    const float* bo = (const float*)d_in[9];
    float* out = (float*)d_out;

    float *pQ, *pK, *pV, *pO;
    cudaGetSymbolAddress((void**)&pQ, g_Q);
    cudaGetSymbolAddress((void**)&pK, g_K);
    cudaGetSymbolAddress((void**)&pV, g_V);
    cudaGetSymbolAddress((void**)&pO, g_O);

    // projections
    gemm_tf32<<<dim3(D_E / 128, (MQ + 127) / 128), 256>>>(x, Wq, bq, pQ, MQ, D_E, D_E);
    gemm_tf32<<<dim3(D_E / 128, (MKV + 127) / 128), 256>>>(y, Wk, bk, pK, MKV, D_E, D_C);
    gemm_tf32<<<dim3(D_E / 128, (MKV + 127) / 128), 256>>>(y, Wv, bv, pV, MKV, D_E, D_C);

    // attention
    cudaFuncSetAttribute(fa2_tf32, cudaFuncAttributeMaxDynamicSharedMemorySize, FA2_SMEM_BYTES);
    fa2_tf32<<<dim3(SEQ_Q / 128, N_HEADS, BATCH), 256, FA2_SMEM_BYTES>>>(pQ, pK, pV, pO);

    // output projection -> d_out
    gemm_tf32<<<dim3(D_E / 128, (MQ + 127) / 128), 256>>>(pO, Wo, bo, out, MQ, D_E, D_E);
}

// round 6
// speedup vs baseline: 2.7410x; 1.2016x over previous
#include <cuda_runtime.h>
#include <cuda_bf16.h>
#include <math.h>

// ---------------- problem constants ----------------
#define BATCH   4
#define SEQ_Q   3072
#define SEQ_KV  1036
#define D_E     1024
#define D_C     768
#define N_HEADS 8
#define D_HEAD  128

#define MQ (BATCH * SEQ_Q)    // 12288
#define MKV (BATCH * SEQ_KV)  // 4144

// ---------------- scratch ----------------
__device__ float g_Q[(size_t)MQ * D_E];
__device__ float g_K[(size_t)MKV * D_E];
__device__ float g_V[(size_t)MKV * D_E];
__device__ float g_O[(size_t)MQ * D_E];

// ---------------- helpers ----------------
__device__ __forceinline__ unsigned f2tf32(float x) {
    unsigned r;
    asm("cvt.rna.tf32.f32 %0, %1;" : "=r"(r) : "f"(x));
    return r;
}

__device__ __forceinline__ void mma_tf32(float d[4], const unsigned a[4], const unsigned b[2]) {
    asm volatile(
        "mma.sync.aligned.m16n8k8.row.col.f32.tf32.tf32.f32 "
        "{%0,%1,%2,%3}, {%4,%5,%6,%7}, {%8,%9}, {%0,%1,%2,%3};\n"
        : "+f"(d[0]), "+f"(d[1]), "+f"(d[2]), "+f"(d[3])
        : "r"(a[0]), "r"(a[1]), "r"(a[2]), "r"(a[3]),
          "r"(b[0]), "r"(b[1]));
}

// fast exp on FMA pipe: 2^n * poly(frac), |rel err| ~1e-7, valid x <= 0
__device__ __forceinline__ float fexp(float x) {
    x = fmaxf(x, -87.0f);
    float xl = x * 1.4426950408889634f;
    float y  = xl + 12582912.0f;               // round-to-nearest int in mantissa
    int   n  = __float_as_int(y) - 0x4B400000;
    float f  = xl - (y - 12582912.0f);
    float p  = 1.33335581e-3f;
    p = fmaf(p, f, 9.61812911e-3f);
    p = fmaf(p, f, 5.55041087e-2f);
    p = fmaf(p, f, 2.40226507e-1f);
    p = fmaf(p, f, 6.93147182e-1f);
    p = fmaf(p, f, 1.0f);
    return __int_as_float(__float_as_int(p) + (n << 23));
}

__device__ __forceinline__ void cp_async16(unsigned dst, const void* src, int src_bytes) {
    asm volatile("cp.async.cg.shared.global [%0], [%1], 16, %2;"
                 :: "r"(dst), "l"(src), "r"(src_bytes));
}
__device__ __forceinline__ void cp_commit() {
    asm volatile("cp.async.commit_group;");
}
template<int N>
__device__ __forceinline__ void cp_wait() {
    asm volatile("cp.async.wait_group %0;" :: "n"(N));
}

// ============================================================
// tf32 tensor-core GEMM: C[M,N] = A[M,K] @ W[N,K]^T + bias
// optional epilogue: out = tf32_round(oscale * (acc + bias))
// ============================================================
__global__ __launch_bounds__(256, 2) void gemm_tf32(
    const float* __restrict__ A, const float* __restrict__ W,
    const float* __restrict__ bias, float* __restrict__ C,
    int M, int N, int K, float oscale, int oround)
{
    __shared__ unsigned sA[8 * 4 * 128];
    __shared__ unsigned sB[16 * 4 * 64];

    const int tid  = threadIdx.x;
    const int lane = tid & 31;
    const int wid  = tid >> 5;
    const int wm   = wid >> 2;
    const int wn   = wid & 3;
    const int m0   = blockIdx.y * 128;
    const int n0   = blockIdx.x * 128;

    float acc[4][4][4];
    #pragma unroll
    for (int i = 0; i < 4; i++)
        #pragma unroll
        for (int j = 0; j < 4; j++)
            #pragma unroll
            for (int c = 0; c < 4; c++) acc[i][j][c] = 0.0f;

    for (int k0 = 0; k0 < K; k0 += 32) {
        #pragma unroll
        for (int i = 0; i < 4; i++) {
            int u = tid + i * 256;
            int tile = u >> 5;
            int l = u & 31;
            int mt = tile >> 2, kt = tile & 3;
            int rbase = m0 + mt * 16 + (l >> 2);
            const float* ap = A + (size_t)rbase * K + k0 + kt * 8 + (l & 3);
            float a0 = 0.f, a1 = 0.f, a2 = 0.f, a3 = 0.f;
            if (rbase < M)     { a0 = ap[0];              a2 = ap[4]; }
            if (rbase + 8 < M) { a1 = ap[(size_t)8 * K];  a3 = ap[(size_t)8 * K + 4]; }
            uint4 o;
            o.x = f2tf32(a0); o.y = f2tf32(a1);
            o.z = f2tf32(a2); o.w = f2tf32(a3);
            *reinterpret_cast<uint4*>(&sA[tile * 128 + l * 4]) = o;
        }
        #pragma unroll
        for (int i = 0; i < 8; i++) {
            int u = tid + i * 256;
            int tile = u >> 5;
            int l = u & 31;
            int nt = tile >> 2, kt = tile & 3;
            const float* wp = W + (size_t)(n0 + nt * 8 + (l >> 2)) * K + k0 + kt * 8 + (l & 3);
            uint2 o;
            o.x = f2tf32(wp[0]);
            o.y = f2tf32(wp[4]);
            *reinterpret_cast<uint2*>(&sB[tile * 64 + l * 2]) = o;
        }
        __syncthreads();

        #pragma unroll
        for (int kt = 0; kt < 4; kt++) {
            unsigned af[4][4];
            unsigned bf[4][2];
            #pragma unroll
            for (int mi = 0; mi < 4; mi++) {
                uint4 t = *reinterpret_cast<const uint4*>(&sA[((wm * 4 + mi) * 4 + kt) * 128 + lane * 4]);
                af[mi][0] = t.x; af[mi][1] = t.y; af[mi][2] = t.z; af[mi][3] = t.w;
            }
            #pragma unroll
            for (int ni = 0; ni < 4; ni++) {
                uint2 t = *reinterpret_cast<const uint2*>(&sB[((wn * 4 + ni) * 4 + kt) * 64 + lane * 2]);
                bf[ni][0] = t.x; bf[ni][1] = t.y;
            }
            #pragma unroll
            for (int mi = 0; mi < 4; mi++)
                #pragma unroll
                for (int ni = 0; ni < 4; ni++)
                    mma_tf32(acc[mi][ni], af[mi], bf[ni]);
        }
        __syncthreads();
    }

    const int rb = lane >> 2;
    const int cb = (lane & 3) * 2;
    #pragma unroll
    for (int mi = 0; mi < 4; mi++) {
        int row1 = m0 + (wm * 4 + mi) * 16 + rb;
        int row2 = row1 + 8;
        #pragma unroll
        for (int ni = 0; ni < 4; ni++) {
            int colg = n0 + (wn * 4 + ni) * 8 + cb;
            float b0 = bias[colg], b1 = bias[colg + 1];
            float v00 = acc[mi][ni][0] + b0, v01 = acc[mi][ni][1] + b1;
            float v10 = acc[mi][ni][2] + b0, v11 = acc[mi][ni][3] + b1;
            if (oround) {
                v00 = __uint_as_float(f2tf32(oscale * v00));
                v01 = __uint_as_float(f2tf32(oscale * v01));
                v10 = __uint_as_float(f2tf32(oscale * v10));
                v11 = __uint_as_float(f2tf32(oscale * v11));
            }
            if (row1 < M)
                *reinterpret_cast<float2*>(C + (size_t)row1 * N + colg) = make_float2(v00, v01);
            if (row2 < M)
                *reinterpret_cast<float2*>(C + (size_t)row2 * N + colg) = make_float2(v10, v11);
        }
    }
}

// ============================================================
// fa3: tf32 flash attention
//  - Q/K/V arrive pre-tf32-rounded (Q pre-scaled) from GEMM epilogues
//  - K/V staged raw via cp.async, double-buffered, XOR-swizzled so
//    mma B-fragment reads are bank-conflict-free, zero cvt
//  - register softmax with FMA-pipe exp
// CTA: 128 q rows, 8 warps (warp = 16 q rows), kv chunks of 64
// smem: Kr[2][64*128] + Vr[2][64*128] = 128KB
// ============================================================
#define NCHUNK 17   // 17*64 = 1088 >= 1036
#define TILE_W 8192 // floats per 64x128 tile

__global__ __launch_bounds__(256, 1) void fa3_tf32(
    const float* __restrict__ Q, const float* __restrict__ K,
    const float* __restrict__ V, float* __restrict__ O)
{
    extern __shared__ float sm[];
    float* Kr = sm;                 // [2][64][128] swizzled
    float* Vr = sm + 2 * TILE_W;    // [2][64][128] swizzled

    const int tid  = threadIdx.x;
    const int lane = tid & 31;
    const int wid  = tid >> 5;
    const int r4   = lane >> 2;     // 0..7
    const int c    = lane & 3;      // 0..3
    const int q0   = blockIdx.x * 128;
    const int h    = blockIdx.y;
    const int b    = blockIdx.z;

    const unsigned sbase = (unsigned)__cvta_generic_to_shared(sm);
    const unsigned kr_s  = sbase;
    const unsigned vr_s  = sbase + 2 * TILE_W * 4;

    const float* kb = K + ((size_t)(b * SEQ_KV)) * D_E + h * D_HEAD;
    const float* vb = V + ((size_t)(b * SEQ_KV)) * D_E + h * D_HEAD;

    // ---- Q -> register A-fragments (already scaled + tf32-rounded) ----
    unsigned qf[16][4];
    {
        const unsigned* qb = reinterpret_cast<const unsigned*>(
            Q + ((size_t)(b * SEQ_Q + q0 + wid * 16)) * D_E + h * D_HEAD);
        #pragma unroll
        for (int kt = 0; kt < 16; kt++) {
            int d0 = kt * 8 + c;
            qf[kt][0] = __ldg(qb + (size_t)r4 * D_E + d0);
            qf[kt][1] = __ldg(qb + (size_t)(r4 + 8) * D_E + d0);
            qf[kt][2] = __ldg(qb + (size_t)r4 * D_E + d0 + 4);
            qf[kt][3] = __ldg(qb + (size_t)(r4 + 8) * D_E + d0 + 4);
        }
    }

    float oacc[16][4];
    #pragma unroll
    for (int nt = 0; nt < 16; nt++)
        #pragma unroll
        for (int e = 0; e < 4; e++) oacc[nt][e] = 0.0f;

    float row_m0 = -1e30f, row_m1 = -1e30f;
    float row_l0 = 0.0f,   row_l1 = 0.0f;

    // ---- async copy of one chunk into buffer `buf` ----
    // K swizzle: word = kv*128 + ((g ^ (kv&7))<<2) + (d&3), g = d>>2
    // V swizzle: word = kv*128 + ((g ^ ((kv&3)<<1))<<2) + (d&3)
    auto issue_chunk = [&](int t, int buf) {
        const int kv0 = t * 64;
        #pragma unroll
        for (int i = 0; i < 8; i++) {
            int m  = tid + i * 256;         // 0..2047
            int kv = m >> 5;                // 0..63
            int g  = m & 31;                // 16B group
            int kvg = kv0 + kv;
            int sz = (kvg < SEQ_KV) ? 16 : 0;
            int kvc = (kvg < SEQ_KV) ? kvg : (SEQ_KV - 1);
            unsigned dk = kr_s + (unsigned)(buf * TILE_W + kv * 128 + ((g ^ (kv & 7)) << 2)) * 4u;
            cp_async16(dk, kb + (size_t)kvc * D_E + g * 4, sz);
            unsigned dv = vr_s + (unsigned)(buf * TILE_W + kv * 128 + ((g ^ ((kv & 3) << 1)) << 2)) * 4u;
            cp_async16(dv, vb + (size_t)kvc * D_E + g * 4, sz);
        }
        cp_commit();
    };

    issue_chunk(0, 0);

    for (int t = 0; t < NCHUNK; t++) {
        const int kv0 = t * 64;
        const int buf = t & 1;

        if (t + 1 < NCHUNK) { issue_chunk(t + 1, buf ^ 1); cp_wait<1>(); }
        else                { cp_wait<0>(); }
        __syncthreads();

        const float* Kt = Kr + buf * TILE_W;
        const float* Vt = Vr + buf * TILE_W;
        const unsigned* Ku = reinterpret_cast<const unsigned*>(Kt);
        const unsigned* Vu = reinterpret_cast<const unsigned*>(Vt);

        // ---- S = Q @ K^T in registers ----
        float sacc[8][4];
        #pragma unroll
        for (int ni = 0; ni < 8; ni++)
            #pragma unroll
            for (int e = 0; e < 4; e++) sacc[ni][e] = 0.0f;

        #pragma unroll
        for (int kt = 0; kt < 16; kt++) {
            const int g0 = ((2 * kt) ^ r4) << 2;
            const int g1 = ((2 * kt + 1) ^ r4) << 2;
            #pragma unroll
            for (int ni = 0; ni < 8; ni++) {
                int base = (ni * 8 + r4) * 128 + c;
                unsigned bf[2];
                bf[0] = Ku[base + g0];
                bf[1] = Ku[base + g1];
                mma_tf32(sacc[ni], qf[kt], bf);
            }
        }

        // ---- mask + register softmax (FMA-pipe exp) ----
        float mx0 = -1e30f, mx1 = -1e30f;
        #pragma unroll
        for (int ni = 0; ni < 8; ni++) {
            int colg = kv0 + ni * 8 + c * 2;
            if (colg >= SEQ_KV) {
                sacc[ni][0] = -1e30f; sacc[ni][1] = -1e30f;
                sacc[ni][2] = -1e30f; sacc[ni][3] = -1e30f;
            }
            mx0 = fmaxf(mx0, fmaxf(sacc[ni][0], sacc[ni][1]));
            mx1 = fmaxf(mx1, fmaxf(sacc[ni][2], sacc[ni][3]));
        }
        mx0 = fmaxf(mx0, __shfl_xor_sync(0xffffffffu, mx0, 1));
        mx0 = fmaxf(mx0, __shfl_xor_sync(0xffffffffu, mx0, 2));
        mx1 = fmaxf(mx1, __shfl_xor_sync(0xffffffffu, mx1, 1));
        mx1 = fmaxf(mx1, __shfl_xor_sync(0xffffffffu, mx1, 2));

        float mnew0 = fmaxf(row_m0, mx0);
        float mnew1 = fmaxf(row_m1, mx1);
        float sc0 = fexp(row_m0 - mnew0);
        float sc1 = fexp(row_m1 - mnew1);
        row_m0 = mnew0; row_m1 = mnew1;

        float sum0 = 0.f, sum1 = 0.f;
        #pragma unroll
        for (int ni = 0; ni < 8; ni++) {
            sacc[ni][0] = fexp(sacc[ni][0] - mnew0);
            sacc[ni][1] = fexp(sacc[ni][1] - mnew0);
            sacc[ni][2] = fexp(sacc[ni][2] - mnew1);
            sacc[ni][3] = fexp(sacc[ni][3] - mnew1);
            sum0 += sacc[ni][0] + sacc[ni][1];
            sum1 += sacc[ni][2] + sacc[ni][3];
        }
        sum0 += __shfl_xor_sync(0xffffffffu, sum0, 1);
        sum0 += __shfl_xor_sync(0xffffffffu, sum0, 2);
        sum1 += __shfl_xor_sync(0xffffffffu, sum1, 1);
        sum1 += __shfl_xor_sync(0xffffffffu, sum1, 2);
        row_l0 = row_l0 * sc0 + sum0;
        row_l1 = row_l1 * sc1 + sum1;

        #pragma unroll
        for (int nt = 0; nt < 16; nt++) {
            oacc[nt][0] *= sc0; oacc[nt][1] *= sc0;
            oacc[nt][2] *= sc1; oacc[nt][3] *= sc1;
        }

        // ---- P (C-frag) -> A-frag via quad shuffles, then O += P @ V ----
        const int qbase = lane & ~3;
        const int srcA = qbase + (c >> 1);
        const int srcB = srcA + 2;
        const bool odd = (c & 1);
        #pragma unroll
        for (int kt = 0; kt < 8; kt++) {
            float s0 = sacc[kt][0], s1 = sacc[kt][1];
            float s2 = sacc[kt][2], s3 = sacc[kt][3];
            float u0 = __shfl_sync(0xffffffffu, s0, srcA);
            float u1 = __shfl_sync(0xffffffffu, s1, srcA);
            float v0 = __shfl_sync(0xffffffffu, s0, srcB);
            float v1 = __shfl_sync(0xffffffffu, s1, srcB);
            float w0 = __shfl_sync(0xffffffffu, s2, srcA);
            float w1 = __shfl_sync(0xffffffffu, s3, srcA);
            float x0 = __shfl_sync(0xffffffffu, s2, srcB);
            float x1 = __shfl_sync(0xffffffffu, s3, srcB);
            unsigned pa[4];
            pa[0] = f2tf32(odd ? u1 : u0);
            pa[1] = f2tf32(odd ? w1 : w0);
            pa[2] = f2tf32(odd ? v1 : v0);
            pa[3] = f2tf32(odd ? x1 : x0);

            // V element (d = nt*8 + r4, kv = kt*8 + c + 4e)
            const int kva = kt * 8 + c;
            const int dl  = r4 & 3;
            const int dh  = r4 >> 2;
            #pragma unroll
            for (int nt = 0; nt < 16; nt++) {
                int gg = (2 * nt + dh) ^ (c << 1);
                unsigned bf[2];
                bf[0] = Vu[kva * 128 + (gg << 2) + dl];
                bf[1] = Vu[(kva + 4) * 128 + (gg << 2) + dl];
                mma_tf32(oacc[nt], pa, bf);
            }
        }
        __syncthreads();
    }

    // ---- normalize + write ----
    float inv0 = 1.0f / row_l0;
    float inv1 = 1.0f / row_l1;
    float* ob = O + ((size_t)(b * SEQ_Q + q0 + wid * 16 + r4)) * D_E + h * D_HEAD;
    #pragma unroll
    for (int nt = 0; nt < 16; nt++) {
        int colg = nt * 8 + c * 2;
        *reinterpret_cast<float2*>(ob + colg) =
            make_float2(oacc[nt][0] * inv0, oacc[nt][1] * inv0);
        *reinterpret_cast<float2*>(ob + (size_t)8 * D_E + colg) =
            make_float2(oacc[nt][2] * inv1, oacc[nt][3] * inv1);
    }
}

#define FA3_SMEM_BYTES (4 * TILE_W * 4)   // 128 KB

// ============================================================
// launch
// ============================================================
extern "C" void kernel_launch(void* const* d_in, const int* in_sizes, int n_in,
                              void* d_out, int out_size)
{
    const float* x  = (const float*)d_in[0];
    const float* y  = (const float*)d_in[1];
    const float* Wq = (const float*)d_in[2];
    const float* bq = (const float*)d_in[3];
    const float* Wk = (const float*)d_in[4];
    const float* bk = (const float*)d_in[5];
    const float* Wv = (const float*)d_in[6];
    const float* bv = (const float*)d_in[7];
    const float* Wo = (const float*)d_in[8];
    const float* bo = (const float*)d_in[9];
    float* out = (float*)d_out;

    float *pQ, *pK, *pV, *pO;
    cudaGetSymbolAddress((void**)&pQ, g_Q);
    cudaGetSymbolAddress((void**)&pK, g_K);
    cudaGetSymbolAddress((void**)&pV, g_V);
    cudaGetSymbolAddress((void**)&pO, g_O);

    const float qscale = 0.08838834764831845f;  // 1/sqrt(128)

    // projections (Q pre-scaled; Q/K/V tf32-rounded in epilogue)
    gemm_tf32<<<dim3(D_E / 128, (MQ + 127) / 128), 256>>>(x, Wq, bq, pQ, MQ, D_E, D_E, qscale, 1);
    gemm_tf32<<<dim3(D_E / 128, (MKV + 127) / 128), 256>>>(y, Wk, bk, pK, MKV, D_E, D_C, 1.0f, 1);
    gemm_tf32<<<dim3(D_E / 128, (MKV + 127) / 128), 256>>>(y, Wv, bv, pV, MKV, D_E, D_C, 1.0f, 1);

    // attention
    cudaFuncSetAttribute(fa3_tf32, cudaFuncAttributeMaxDynamicSharedMemorySize, FA3_SMEM_BYTES);
    fa3_tf32<<<dim3(SEQ_Q / 128, N_HEADS, BATCH), 256, FA3_SMEM_BYTES>>>(pQ, pK, pV, pO);

    // output projection -> d_out
    gemm_tf32<<<dim3(D_E / 128, (MQ + 127) / 128), 256>>>(pO, Wo, bo, out, MQ, D_E, D_E, 1.0f, 0);
}

// round 7
// speedup vs baseline: 7.0143x; 2.5590x over previous
#include <cuda_runtime.h>
#include <cuda_fp16.h>
#include <math.h>

// ---------------- problem constants ----------------
#define BATCH   4
#define SEQ_Q   3072
#define SEQ_KV  1036
#define D_E     1024
#define D_C     768
#define N_HEADS 8
#define D_HEAD  128

#define MQ (BATCH * SEQ_Q)    // 12288
#define MKV (BATCH * SEQ_KV)  // 4144
#define SKV_PAD 1088          // 34*32, >= 17*64

// ---------------- scratch ----------------
__device__ __half g_hx[(size_t)MQ * D_E];
__device__ __half g_hy[(size_t)MKV * D_C];
__device__ __half g_hWq[(size_t)D_E * D_E];
__device__ __half g_hWk[(size_t)D_E * D_C];
__device__ __half g_hWv[(size_t)D_E * D_C];
__device__ __half g_hWo[(size_t)D_E * D_E];
__device__ __half g_Q[(size_t)MQ * D_E];
__device__ __half g_K[(size_t)MKV * D_E];
__device__ __half g_V[(size_t)MKV * D_E];
__device__ __half g_Vt[(size_t)BATCH * N_HEADS * D_HEAD * SKV_PAD];
__device__ __half g_O[(size_t)MQ * D_E];

// ---------------- helpers ----------------
__device__ __forceinline__ unsigned packh2(float lo, float hi) {
    __half2 h = __floats2half2_rn(lo, hi);
    return *reinterpret_cast<unsigned*>(&h);
}

// D(16x8 f32) += A(16x16 f16, row) * B(16x8 f16, col)
__device__ __forceinline__ void mma_f16(float d[4], const unsigned a[4], const unsigned b[2]) {
    asm volatile(
        "mma.sync.aligned.m16n8k16.row.col.f32.f16.f16.f32 "
        "{%0,%1,%2,%3}, {%4,%5,%6,%7}, {%8,%9}, {%0,%1,%2,%3};\n"
        : "+f"(d[0]), "+f"(d[1]), "+f"(d[2]), "+f"(d[3])
        : "r"(a[0]), "r"(a[1]), "r"(a[2]), "r"(a[3]),
          "r"(b[0]), "r"(b[1]));
}

// fast exp on FMA pipe, valid x <= 0
__device__ __forceinline__ float fexp(float x) {
    x = fmaxf(x, -87.0f);
    float xl = x * 1.4426950408889634f;
    float y  = xl + 12582912.0f;
    int   n  = __float_as_int(y) - 0x4B400000;
    float f  = xl - (y - 12582912.0f);
    float p  = 1.33335581e-3f;
    p = fmaf(p, f, 9.61812911e-3f);
    p = fmaf(p, f, 5.55041087e-2f);
    p = fmaf(p, f, 2.40226507e-1f);
    p = fmaf(p, f, 6.93147182e-1f);
    p = fmaf(p, f, 1.0f);
    return __int_as_float(__float_as_int(p) + (n << 23));
}

__device__ __forceinline__ void cp_async16(unsigned dst, const void* src, int src_bytes) {
    asm volatile("cp.async.cg.shared.global [%0], [%1], 16, %2;"
                 :: "r"(dst), "l"(src), "r"(src_bytes));
}
__device__ __forceinline__ void cp_commit() { asm volatile("cp.async.commit_group;"); }
template<int N>
__device__ __forceinline__ void cp_wait() { asm volatile("cp.async.wait_group %0;" :: "n"(N)); }

// ============================================================
// fp32 -> fp16 conversion
// ============================================================
__global__ __launch_bounds__(256) void cvt_fp16(const float* __restrict__ in,
                                                __half* __restrict__ out, int n4)
{
    int i = blockIdx.x * 256 + threadIdx.x;
    if (i < n4) {
        float4 v = *reinterpret_cast<const float4*>(in + (size_t)i * 4);
        __half2* o = reinterpret_cast<__half2*>(out + (size_t)i * 4);
        o[0] = __floats2half2_rn(v.x, v.y);
        o[1] = __floats2half2_rn(v.z, v.w);
    }
}

// ============================================================
// V transpose: g_V [MKV][D_E] -> g_Vt [B*H][128][SKV_PAD]
// ============================================================
__global__ __launch_bounds__(256) void transpose_v(const __half* __restrict__ V,
                                                   __half* __restrict__ Vt)
{
    __shared__ __half t[32][33];
    const int tx = threadIdx.x;           // 0..31
    const int ty = threadIdx.y;           // 0..7
    const int kv0 = blockIdx.x * 32;
    const int d0  = blockIdx.y * 32;
    const int bh  = blockIdx.z;
    const int b   = bh >> 3, h = bh & 7;

    #pragma unroll
    for (int j = 0; j < 4; j++) {
        int kvL = ty * 4 + j;
        int kv  = kv0 + kvL;
        __half v = __float2half(0.0f);
        if (kv < SEQ_KV)
            v = V[(size_t)(b * SEQ_KV + kv) * D_E + h * D_HEAD + d0 + tx];
        t[kvL][tx] = v;
    }
    __syncthreads();
    #pragma unroll
    for (int j = 0; j < 4; j++) {
        int dL = ty * 4 + j;
        Vt[((size_t)bh * D_HEAD + d0 + dL) * SKV_PAD + kv0 + tx] = t[tx][dL];
    }
}

// ============================================================
// fp16 tensor-core GEMM: C[M,N] = A[M,K] @ W[N,K]^T + bias
// block 128x128x32(half), cp.async double-buffered,
// smem rows padded to 80B (conflict-free writes AND frag reads)
// epilogue: ohalf ? fp16(oscale*(acc+bias)) : fp32(acc+bias)
// ============================================================
__global__ __launch_bounds__(256, 2) void gemm_f16(
    const __half* __restrict__ A, const __half* __restrict__ W,
    const float* __restrict__ bias, void* Cv,
    int M, int N, int K, float oscale, int ohalf)
{
    __shared__ __half sA[2][128 * 40];   // 40-half (80B) row stride
    __shared__ __half sB[2][128 * 40];

    const int tid  = threadIdx.x;
    const int lane = tid & 31;
    const int wid  = tid >> 5;
    const int wm   = wid >> 2;          // 0..1
    const int wn   = wid & 3;           // 0..3
    const int r4   = lane >> 2;
    const int c    = lane & 3;
    const int m0   = blockIdx.y * 128;
    const int n0   = blockIdx.x * 128;

    const unsigned sa_s = (unsigned)__cvta_generic_to_shared(&sA[0][0]);
    const unsigned sb_s = (unsigned)__cvta_generic_to_shared(&sB[0][0]);

    float acc[4][4][4];
    #pragma unroll
    for (int i = 0; i < 4; i++)
        #pragma unroll
        for (int j = 0; j < 4; j++)
            #pragma unroll
            for (int e = 0; e < 4; e++) acc[i][j][e] = 0.0f;

    auto issue = [&](int k0, int buf) {
        #pragma unroll
        for (int i = 0; i < 2; i++) {
            int u = tid + i * 256;          // 0..511
            int row = u >> 2, g = u & 3;
            int gr = m0 + row;
            int sz = (gr < M) ? 16 : 0;
            int grc = (gr < M) ? gr : (M - 1);
            cp_async16(sa_s + (unsigned)(buf * 5120 + row * 40 + g * 8) * 2u,
                       A + (size_t)grc * K + k0 + g * 8, sz);
        }
        #pragma unroll
        for (int i = 0; i < 2; i++) {
            int u = tid + i * 256;
            int row = u >> 2, g = u & 3;
            cp_async16(sb_s + (unsigned)(buf * 5120 + row * 40 + g * 8) * 2u,
                       W + (size_t)(n0 + row) * K + k0 + g * 8, 16);
        }
        cp_commit();
    };

    issue(0, 0);
    const int nk = K / 32;
    for (int ki = 0; ki < nk; ki++) {
        const int buf = ki & 1;
        if (ki + 1 < nk) { issue((ki + 1) * 32, buf ^ 1); cp_wait<1>(); }
        else             { cp_wait<0>(); }
        __syncthreads();

        const unsigned* Au = reinterpret_cast<const unsigned*>(&sA[buf][0]);
        const unsigned* Bu = reinterpret_cast<const unsigned*>(&sB[buf][0]);

        #pragma unroll
        for (int kt = 0; kt < 2; kt++) {
            unsigned af[4][4], bf[4][2];
            #pragma unroll
            for (int mi = 0; mi < 4; mi++) {
                int base = wm * 64 + mi * 16;
                af[mi][0] = Au[(base + r4) * 20 + kt * 8 + c];
                af[mi][1] = Au[(base + r4 + 8) * 20 + kt * 8 + c];
                af[mi][2] = Au[(base + r4) * 20 + kt * 8 + c + 4];
                af[mi][3] = Au[(base + r4 + 8) * 20 + kt * 8 + c + 4];
            }
            #pragma unroll
            for (int ni = 0; ni < 4; ni++) {
                int n = wn * 32 + ni * 8 + r4;
                bf[ni][0] = Bu[n * 20 + kt * 8 + c];
                bf[ni][1] = Bu[n * 20 + kt * 8 + c + 4];
            }
            #pragma unroll
            for (int mi = 0; mi < 4; mi++)
                #pragma unroll
                for (int ni = 0; ni < 4; ni++)
                    mma_f16(acc[mi][ni], af[mi], bf[ni]);
        }
        __syncthreads();
    }

    // ---- epilogue ----
    #pragma unroll
    for (int mi = 0; mi < 4; mi++) {
        int row1 = m0 + wm * 64 + mi * 16 + r4;
        int row2 = row1 + 8;
        #pragma unroll
        for (int ni = 0; ni < 4; ni++) {
            int colg = n0 + wn * 32 + ni * 8 + c * 2;
            float b0 = bias[colg], b1 = bias[colg + 1];
            float v00 = acc[mi][ni][0] + b0, v01 = acc[mi][ni][1] + b1;
            float v10 = acc[mi][ni][2] + b0, v11 = acc[mi][ni][3] + b1;
            if (ohalf) {
                __half* C = (__half*)Cv;
                if (row1 < M)
                    *reinterpret_cast<unsigned*>(C + (size_t)row1 * N + colg) =
                        packh2(oscale * v00, oscale * v01);
                if (row2 < M)
                    *reinterpret_cast<unsigned*>(C + (size_t)row2 * N + colg) =
                        packh2(oscale * v10, oscale * v11);
            } else {
                float* C = (float*)Cv;
                if (row1 < M)
                    *reinterpret_cast<float2*>(C + (size_t)row1 * N + colg) = make_float2(v00, v01);
                if (row2 < M)
                    *reinterpret_cast<float2*>(C + (size_t)row2 * N + colg) = make_float2(v10, v11);
            }
        }
    }
}

// ============================================================
// fa4: fp16 flash attention (Q/K pre-scaled fp16, V transposed)
// CTA: 128 q rows, 8 warps (16 q rows each), kv chunks of 64
// cp.async double-buffered K [64][128]h and Vt [128][64]h tiles
// ============================================================
#define NCHUNK 17
#define KW 4096   // words per K tile (64*64)
#define VW 4096   // words per Vt tile (128*32)

__global__ __launch_bounds__(256, 1) void fa4_f16(
    const __half* __restrict__ Q, const __half* __restrict__ K,
    const __half* __restrict__ Vt, __half* __restrict__ O)
{
    extern __shared__ unsigned sm4[];
    unsigned* Ks = sm4;             // [2][KW]
    unsigned* Vs = sm4 + 2 * KW;    // [2][VW]

    const int tid  = threadIdx.x;
    const int lane = tid & 31;
    const int wid  = tid >> 5;
    const int r4   = lane >> 2;
    const int c    = lane & 3;
    const int q0   = blockIdx.x * 128;
    const int h    = blockIdx.y;
    const int b    = blockIdx.z;

    const unsigned sbase = (unsigned)__cvta_generic_to_shared(sm4);
    const unsigned k_s = sbase;
    const unsigned v_s = sbase + 2 * KW * 4;

    const __half* kb  = K + ((size_t)(b * SEQ_KV)) * D_E + h * D_HEAD;
    const __half* vtb = Vt + ((size_t)(b * N_HEADS + h)) * D_HEAD * SKV_PAD;

    // ---- Q -> register A-frags (fp16, pre-scaled) ----
    unsigned qf[8][4];
    {
        const unsigned* qb = reinterpret_cast<const unsigned*>(
            Q + ((size_t)(b * SEQ_Q + q0 + wid * 16)) * D_E + h * D_HEAD);
        #pragma unroll
        for (int kt = 0; kt < 8; kt++) {
            qf[kt][0] = __ldg(qb + (size_t)r4 * 512 + kt * 8 + c);
            qf[kt][1] = __ldg(qb + (size_t)(r4 + 8) * 512 + kt * 8 + c);
            qf[kt][2] = __ldg(qb + (size_t)r4 * 512 + kt * 8 + c + 4);
            qf[kt][3] = __ldg(qb + (size_t)(r4 + 8) * 512 + kt * 8 + c + 4);
        }
    }

    float oacc[16][4];
    #pragma unroll
    for (int nt = 0; nt < 16; nt++)
        #pragma unroll
        for (int e = 0; e < 4; e++) oacc[nt][e] = 0.0f;

    float row_m0 = -1e30f, row_m1 = -1e30f;
    float row_l0 = 0.0f,   row_l1 = 0.0f;

    // K tile: word = kv*64 + ((g ^ (kv&7))<<2) + w2   (g: 16 chunks/row)
    // Vt tile: word = d*32 + ((g ^ (d&7))<<2) + w2    (g: 8 chunks/row)
    auto issue_chunk = [&](int t, int buf) {
        const int kv0 = t * 64;
        #pragma unroll
        for (int i = 0; i < 4; i++) {
            int u = tid + i * 256;
            int kv = u >> 4, g = u & 15;
            int kvg = kv0 + kv;
            int sz = (kvg < SEQ_KV) ? 16 : 0;
            int kvc = (kvg < SEQ_KV) ? kvg : (SEQ_KV - 1);
            cp_async16(k_s + (unsigned)(buf * KW + kv * 64 + ((g ^ (kv & 7)) << 2)) * 4u,
                       kb + (size_t)kvc * D_E + g * 8, sz);
        }
        #pragma unroll
        for (int i = 0; i < 4; i++) {
            int u = tid + i * 256;
            int d = u >> 3, g = u & 7;
            cp_async16(v_s + (unsigned)(buf * VW + d * 32 + ((g ^ (d & 7)) << 2)) * 4u,
                       vtb + (size_t)d * SKV_PAD + kv0 + g * 8, 16);
        }
        cp_commit();
    };

    issue_chunk(0, 0);

    for (int t = 0; t < NCHUNK; t++) {
        const int kv0 = t * 64;
        const int buf = t & 1;

        if (t + 1 < NCHUNK) { issue_chunk(t + 1, buf ^ 1); cp_wait<1>(); }
        else                { cp_wait<0>(); }
        __syncthreads();

        const unsigned* Ku = Ks + buf * KW;
        const unsigned* Vu = Vs + buf * VW;

        // ---- S = Q @ K^T ----
        float sacc[8][4];
        #pragma unroll
        for (int ni = 0; ni < 8; ni++)
            #pragma unroll
            for (int e = 0; e < 4; e++) sacc[ni][e] = 0.0f;

        #pragma unroll
        for (int kt = 0; kt < 8; kt++) {
            #pragma unroll
            for (int ni = 0; ni < 8; ni++) {
                int row = (ni * 8 + r4) * 64;
                unsigned bf[2];
                bf[0] = Ku[row + (((2 * kt)     ^ r4) << 2) + c];
                bf[1] = Ku[row + (((2 * kt + 1) ^ r4) << 2) + c];
                mma_f16(sacc[ni], qf[kt], bf);
            }
        }

        // ---- mask + register softmax ----
        float mx0 = -1e30f, mx1 = -1e30f;
        #pragma unroll
        for (int ni = 0; ni < 8; ni++) {
            int colg = kv0 + ni * 8 + c * 2;
            if (colg >= SEQ_KV) {
                sacc[ni][0] = -1e30f; sacc[ni][1] = -1e30f;
                sacc[ni][2] = -1e30f; sacc[ni][3] = -1e30f;
            }
            mx0 = fmaxf(mx0, fmaxf(sacc[ni][0], sacc[ni][1]));
            mx1 = fmaxf(mx1, fmaxf(sacc[ni][2], sacc[ni][3]));
        }
        mx0 = fmaxf(mx0, __shfl_xor_sync(0xffffffffu, mx0, 1));
        mx0 = fmaxf(mx0, __shfl_xor_sync(0xffffffffu, mx0, 2));
        mx1 = fmaxf(mx1, __shfl_xor_sync(0xffffffffu, mx1, 1));
        mx1 = fmaxf(mx1, __shfl_xor_sync(0xffffffffu, mx1, 2));

        float mnew0 = fmaxf(row_m0, mx0);
        float mnew1 = fmaxf(row_m1, mx1);
        float sc0 = fexp(row_m0 - mnew0);
        float sc1 = fexp(row_m1 - mnew1);
        row_m0 = mnew0; row_m1 = mnew1;

        float sum0 = 0.f, sum1 = 0.f;
        #pragma unroll
        for (int ni = 0; ni < 8; ni++) {
            sacc[ni][0] = fexp(sacc[ni][0] - mnew0);
            sacc[ni][1] = fexp(sacc[ni][1] - mnew0);
            sacc[ni][2] = fexp(sacc[ni][2] - mnew1);
            sacc[ni][3] = fexp(sacc[ni][3] - mnew1);
            sum0 += sacc[ni][0] + sacc[ni][1];
            sum1 += sacc[ni][2] + sacc[ni][3];
        }
        sum0 += __shfl_xor_sync(0xffffffffu, sum0, 1);
        sum0 += __shfl_xor_sync(0xffffffffu, sum0, 2);
        sum1 += __shfl_xor_sync(0xffffffffu, sum1, 1);
        sum1 += __shfl_xor_sync(0xffffffffu, sum1, 2);
        row_l0 = row_l0 * sc0 + sum0;
        row_l1 = row_l1 * sc1 + sum1;

        #pragma unroll
        for (int nt = 0; nt < 16; nt++) {
            oacc[nt][0] *= sc0; oacc[nt][1] *= sc0;
            oacc[nt][2] *= sc1; oacc[nt][3] *= sc1;
        }

        // ---- O += P @ V : P packs directly into fp16 A-frags ----
        #pragma unroll
        for (int kt = 0; kt < 4; kt++) {
            unsigned pa[4];
            pa[0] = packh2(sacc[2 * kt][0],     sacc[2 * kt][1]);
            pa[1] = packh2(sacc[2 * kt][2],     sacc[2 * kt][3]);
            pa[2] = packh2(sacc[2 * kt + 1][0], sacc[2 * kt + 1][1]);
            pa[3] = packh2(sacc[2 * kt + 1][2], sacc[2 * kt + 1][3]);

            #pragma unroll
            for (int nt = 0; nt < 16; nt++) {
                int row = (nt * 8 + r4) * 32;
                unsigned bf[2];
                bf[0] = Vu[row + (((2 * kt)     ^ r4) << 2) + c];
                bf[1] = Vu[row + (((2 * kt + 1) ^ r4) << 2) + c];
                mma_f16(oacc[nt], pa, bf);
            }
        }
        __syncthreads();
    }

    // ---- normalize + write (fp16) ----
    float inv0 = 1.0f / row_l0;
    float inv1 = 1.0f / row_l1;
    __half* ob = O + ((size_t)(b * SEQ_Q + q0 + wid * 16 + r4)) * D_E + h * D_HEAD;
    #pragma unroll
    for (int nt = 0; nt < 16; nt++) {
        int colg = nt * 8 + c * 2;
        *reinterpret_cast<unsigned*>(ob + colg) =
            packh2(oacc[nt][0] * inv0, oacc[nt][1] * inv0);
        *reinterpret_cast<unsigned*>(ob + (size_t)8 * D_E + colg) =
            packh2(oacc[nt][2] * inv1, oacc[nt][3] * inv1);
    }
}

#define FA4_SMEM_BYTES ((2 * KW + 2 * VW) * 4)   // 64 KB

// ============================================================
// launch
// ============================================================
extern "C" void kernel_launch(void* const* d_in, const int* in_sizes, int n_in,
                              void* d_out, int out_size)
{
    const float* x  = (const float*)d_in[0];
    const float* y  = (const float*)d_in[1];
    const float* Wq = (const float*)d_in[2];
    const float* bq = (const float*)d_in[3];
    const float* Wk = (const float*)d_in[4];
    const float* bk = (const float*)d_in[5];
    const float* Wv = (const float*)d_in[6];
    const float* bv = (const float*)d_in[7];
    const float* Wo = (const float*)d_in[8];
    const float* bo = (const float*)d_in[9];
    float* out = (float*)d_out;

    __half *hx, *hy, *hWq, *hWk, *hWv, *hWo, *pQ, *pK, *pV, *pVt, *pO;
    cudaGetSymbolAddress((void**)&hx,  g_hx);
    cudaGetSymbolAddress((void**)&hy,  g_hy);
    cudaGetSymbolAddress((void**)&hWq, g_hWq);
    cudaGetSymbolAddress((void**)&hWk, g_hWk);
    cudaGetSymbolAddress((void**)&hWv, g_hWv);
    cudaGetSymbolAddress((void**)&hWo, g_hWo);
    cudaGetSymbolAddress((void**)&pQ,  g_Q);
    cudaGetSymbolAddress((void**)&pK,  g_K);
    cudaGetSymbolAddress((void**)&pV,  g_V);
    cudaGetSymbolAddress((void**)&pVt, g_Vt);
    cudaGetSymbolAddress((void**)&pO,  g_O);

    const float qscale = 0.08838834764831845f;  // 1/sqrt(128)

    // fp32 -> fp16 conversions
    auto cvt = [&](const float* src, __half* dst, size_t n) {
        int n4 = (int)(n / 4);
        cvt_fp16<<<(n4 + 255) / 256, 256>>>(src, dst, n4);
    };
    cvt(x,  hx,  (size_t)MQ * D_E);
    cvt(y,  hy,  (size_t)MKV * D_C);
    cvt(Wq, hWq, (size_t)D_E * D_E);
    cvt(Wk, hWk, (size_t)D_E * D_C);
    cvt(Wv, hWv, (size_t)D_E * D_C);
    cvt(Wo, hWo, (size_t)D_E * D_E);

    // projections (fp16 out; Q pre-scaled)
    gemm_f16<<<dim3(D_E / 128, (MQ + 127) / 128), 256>>>(hx, hWq, bq, pQ, MQ, D_E, D_E, qscale, 1);
    gemm_f16<<<dim3(D_E / 128, (MKV + 127) / 128), 256>>>(hy, hWk, bk, pK, MKV, D_E, D_C, 1.0f, 1);
    gemm_f16<<<dim3(D_E / 128, (MKV + 127) / 128), 256>>>(hy, hWv, bv, pV, MKV, D_E, D_C, 1.0f, 1);

    // V transpose
    transpose_v<<<dim3(SKV_PAD / 32, D_HEAD / 32, BATCH * N_HEADS), dim3(32, 8)>>>(pV, pVt);

    // attention
    cudaFuncSetAttribute(fa4_f16, cudaFuncAttributeMaxDynamicSharedMemorySize, FA4_SMEM_BYTES);
    fa4_f16<<<dim3(SEQ_Q / 128, N_HEADS, BATCH), 256, FA4_SMEM_BYTES>>>(pQ, pK, pVt, pO);

    // output projection -> d_out (fp32)
    gemm_f16<<<dim3(D_E / 128, (MQ + 127) / 128), 256>>>(pO, hWo, bo, out, MQ, D_E, D_E, 1.0f, 0);
}

// round 8
// speedup vs baseline: 7.4944x; 1.0684x over previous
#include <cuda_runtime.h>
#include <cuda_fp16.h>
#include <math.h>

// ---------------- problem constants ----------------
#define BATCH   4
#define SEQ_Q   3072
#define SEQ_KV  1036
#define D_E     1024
#define D_C     768
#define N_HEADS 8
#define D_HEAD  128

#define MQ (BATCH * SEQ_Q)    // 12288
#define MKV (BATCH * SEQ_KV)  // 4144
#define SKV_PAD 1088          // 34*32, >= 17*64

// ---------------- scratch ----------------
__device__ __half g_hx[(size_t)MQ * D_E];
__device__ __half g_hy[(size_t)MKV * D_C];
__device__ __half g_hWq[(size_t)D_E * D_E];
__device__ __half g_hWk[(size_t)D_E * D_C];
__device__ __half g_hWv[(size_t)D_E * D_C];
__device__ __half g_hWo[(size_t)D_E * D_E];
__device__ __half g_Q[(size_t)MQ * D_E];
__device__ __half g_K[(size_t)MKV * D_E];
__device__ __half g_V[(size_t)MKV * D_E];
__device__ __half g_Vt[(size_t)BATCH * N_HEADS * D_HEAD * SKV_PAD];
__device__ __half g_O[(size_t)MQ * D_E];

// ---------------- helpers ----------------
__device__ __forceinline__ unsigned packh2(float lo, float hi) {
    __half2 h = __floats2half2_rn(lo, hi);
    return *reinterpret_cast<unsigned*>(&h);
}

__device__ __forceinline__ void mma_f16(float d[4], const unsigned a[4], const unsigned b[2]) {
    asm volatile(
        "mma.sync.aligned.m16n8k16.row.col.f32.f16.f16.f32 "
        "{%0,%1,%2,%3}, {%4,%5,%6,%7}, {%8,%9}, {%0,%1,%2,%3};\n"
        : "+f"(d[0]), "+f"(d[1]), "+f"(d[2]), "+f"(d[3])
        : "r"(a[0]), "r"(a[1]), "r"(a[2]), "r"(a[3]),
          "r"(b[0]), "r"(b[1]));
}

__device__ __forceinline__ void ldsm_x4(unsigned& r0, unsigned& r1, unsigned& r2, unsigned& r3,
                                        unsigned saddr) {
    asm volatile("ldmatrix.sync.aligned.m8n8.x4.shared.b16 {%0,%1,%2,%3}, [%4];"
                 : "=r"(r0), "=r"(r1), "=r"(r2), "=r"(r3) : "r"(saddr));
}

// fast exp on FMA pipe, valid x <= 0
__device__ __forceinline__ float fexp(float x) {
    x = fmaxf(x, -87.0f);
    float xl = x * 1.4426950408889634f;
    float y  = xl + 12582912.0f;
    int   n  = __float_as_int(y) - 0x4B400000;
    float f  = xl - (y - 12582912.0f);
    float p  = 1.33335581e-3f;
    p = fmaf(p, f, 9.61812911e-3f);
    p = fmaf(p, f, 5.55041087e-2f);
    p = fmaf(p, f, 2.40226507e-1f);
    p = fmaf(p, f, 6.93147182e-1f);
    p = fmaf(p, f, 1.0f);
    return __int_as_float(__float_as_int(p) + (n << 23));
}

__device__ __forceinline__ void cp_async16(unsigned dst, const void* src, int src_bytes) {
    asm volatile("cp.async.cg.shared.global [%0], [%1], 16, %2;"
                 :: "r"(dst), "l"(src), "r"(src_bytes));
}
__device__ __forceinline__ void cp_commit() { asm volatile("cp.async.commit_group;"); }
template<int N>
__device__ __forceinline__ void cp_wait() { asm volatile("cp.async.wait_group %0;" :: "n"(N)); }

// ============================================================
// fp32 -> fp16 conversion
// ============================================================
__global__ __launch_bounds__(256) void cvt_fp16(const float* __restrict__ in,
                                                __half* __restrict__ out, int n4)
{
    int i = blockIdx.x * 256 + threadIdx.x;
    if (i < n4) {
        float4 v = *reinterpret_cast<const float4*>(in + (size_t)i * 4);
        __half2* o = reinterpret_cast<__half2*>(out + (size_t)i * 4);
        o[0] = __floats2half2_rn(v.x, v.y);
        o[1] = __floats2half2_rn(v.z, v.w);
    }
}

// ============================================================
// V transpose: g_V [MKV][D_E] -> g_Vt [B*H][128][SKV_PAD]
// ============================================================
__global__ __launch_bounds__(256) void transpose_v(const __half* __restrict__ V,
                                                   __half* __restrict__ Vt)
{
    __shared__ __half t[32][33];
    const int tx = threadIdx.x;
    const int ty = threadIdx.y;
    const int kv0 = blockIdx.x * 32;
    const int d0  = blockIdx.y * 32;
    const int bh  = blockIdx.z;
    const int b   = bh >> 3, h = bh & 7;

    #pragma unroll
    for (int j = 0; j < 4; j++) {
        int kvL = ty * 4 + j;
        int kv  = kv0 + kvL;
        __half v = __float2half(0.0f);
        if (kv < SEQ_KV)
            v = V[(size_t)(b * SEQ_KV + kv) * D_E + h * D_HEAD + d0 + tx];
        t[kvL][tx] = v;
    }
    __syncthreads();
    #pragma unroll
    for (int j = 0; j < 4; j++) {
        int dL = ty * 4 + j;
        Vt[((size_t)bh * D_HEAD + d0 + dL) * SKV_PAD + kv0 + tx] = t[tx][dL];
    }
}

// ============================================================
// fp16 tensor-core GEMM (optionally dual-output):
//   blocks with blockIdx.x <  nx: C  = A @ W^T  + bias
//   blocks with blockIdx.x >= nx: C2 = A @ W2^T + bias2
// block 128x128x32(half), cp.async double-buffered, ldmatrix frags
// ============================================================
__global__ __launch_bounds__(256, 2) void gemm_f16(
    const __half* __restrict__ A,
    const __half* __restrict__ W,  const float* __restrict__ bias,  void* Cv,
    const __half* __restrict__ W2, const float* __restrict__ bias2, void* Cv2,
    int nx, int M, int N, int K, float oscale, int ohalf)
{
    __shared__ __half sA[2][128 * 40];   // 80B row stride
    __shared__ __half sB[2][128 * 40];

    const int tid  = threadIdx.x;
    const int lane = tid & 31;
    const int wid  = tid >> 5;
    const int wm   = wid >> 2;
    const int wn   = wid & 3;
    const int r4   = lane >> 2;
    const int c    = lane & 3;
    const int m0   = blockIdx.y * 128;

    int bx = blockIdx.x;
    if (bx >= nx) { W = W2; bias = bias2; Cv = Cv2; bx -= nx; }
    const int n0 = bx * 128;

    const unsigned sa_s = (unsigned)__cvta_generic_to_shared(&sA[0][0]);
    const unsigned sb_s = (unsigned)__cvta_generic_to_shared(&sB[0][0]);

    float acc[4][4][4];
    #pragma unroll
    for (int i = 0; i < 4; i++)
        #pragma unroll
        for (int j = 0; j < 4; j++)
            #pragma unroll
            for (int e = 0; e < 4; e++) acc[i][j][e] = 0.0f;

    auto issue = [&](int k0, int buf) {
        #pragma unroll
        for (int i = 0; i < 2; i++) {
            int u = tid + i * 256;
            int row = u >> 2, g = u & 3;
            int gr = m0 + row;
            int sz = (gr < M) ? 16 : 0;
            int grc = (gr < M) ? gr : (M - 1);
            cp_async16(sa_s + (unsigned)(buf * 10240 + row * 80 + g * 16),
                       A + (size_t)grc * K + k0 + g * 8, sz);
        }
        #pragma unroll
        for (int i = 0; i < 2; i++) {
            int u = tid + i * 256;
            int row = u >> 2, g = u & 3;
            cp_async16(sb_s + (unsigned)(buf * 10240 + row * 80 + g * 16),
                       W + (size_t)(n0 + row) * K + k0 + g * 8, 16);
        }
        cp_commit();
    };

    // ldmatrix lane roles
    const int arow = (lane & 7) + (lane & 8);           // 0..15
    const int ahi  = (lane & 16) ? 16 : 0;
    const int brow = (lane & 7) + ((lane & 16) ? 8 : 0); // 0..15
    const int bhi  = (lane & 8) ? 16 : 0;

    issue(0, 0);
    const int nk = K / 32;
    for (int ki = 0; ki < nk; ki++) {
        const int buf = ki & 1;
        if (ki + 1 < nk) { issue((ki + 1) * 32, buf ^ 1); cp_wait<1>(); }
        else             { cp_wait<0>(); }
        __syncthreads();

        const unsigned aT = sa_s + buf * 10240;
        const unsigned bT = sb_s + buf * 10240;

        #pragma unroll
        for (int kt = 0; kt < 2; kt++) {
            unsigned af[4][4], bf[4][2];
            #pragma unroll
            for (int mi = 0; mi < 4; mi++)
                ldsm_x4(af[mi][0], af[mi][1], af[mi][2], af[mi][3],
                        aT + (unsigned)((wm * 64 + mi * 16 + arow) * 80 + kt * 32 + ahi));
            #pragma unroll
            for (int nip = 0; nip < 2; nip++)
                ldsm_x4(bf[2 * nip][0], bf[2 * nip][1], bf[2 * nip + 1][0], bf[2 * nip + 1][1],
                        bT + (unsigned)((wn * 32 + nip * 16 + brow) * 80 + kt * 32 + bhi));
            #pragma unroll
            for (int mi = 0; mi < 4; mi++)
                #pragma unroll
                for (int ni = 0; ni < 4; ni++)
                    mma_f16(acc[mi][ni], af[mi], bf[ni]);
        }
        __syncthreads();
    }

    // ---- epilogue ----
    #pragma unroll
    for (int mi = 0; mi < 4; mi++) {
        int row1 = m0 + wm * 64 + mi * 16 + r4;
        int row2 = row1 + 8;
        #pragma unroll
        for (int ni = 0; ni < 4; ni++) {
            int colg = n0 + wn * 32 + ni * 8 + c * 2;
            float b0 = bias[colg], b1 = bias[colg + 1];
            float v00 = acc[mi][ni][0] + b0, v01 = acc[mi][ni][1] + b1;
            float v10 = acc[mi][ni][2] + b0, v11 = acc[mi][ni][3] + b1;
            if (ohalf) {
                __half* C = (__half*)Cv;
                if (row1 < M)
                    *reinterpret_cast<unsigned*>(C + (size_t)row1 * N + colg) =
                        packh2(oscale * v00, oscale * v01);
                if (row2 < M)
                    *reinterpret_cast<unsigned*>(C + (size_t)row2 * N + colg) =
                        packh2(oscale * v10, oscale * v11);
            } else {
                float* C = (float*)Cv;
                if (row1 < M)
                    *reinterpret_cast<float2*>(C + (size_t)row1 * N + colg) = make_float2(v00, v01);
                if (row2 < M)
                    *reinterpret_cast<float2*>(C + (size_t)row2 * N + colg) = make_float2(v10, v11);
            }
        }
    }
}

// ============================================================
// fa5: fp16 flash attention with ldmatrix fragment loads
// CTA: 128 q rows, 8 warps (16 q rows each), kv chunks of 64
// K tile [64 kv][128 d]h (256B rows, 16B-XOR swizzle)
// Vt tile [128 d][64 kv]h (128B rows, 16B-XOR swizzle)
// ============================================================
#define NCHUNK 17
#define KTB 16384   // bytes per K tile
#define VTB 16384   // bytes per Vt tile

__global__ __launch_bounds__(256, 1) void fa5_f16(
    const __half* __restrict__ Q, const __half* __restrict__ K,
    const __half* __restrict__ Vt, __half* __restrict__ O)
{
    extern __shared__ unsigned sm4[];

    const int tid  = threadIdx.x;
    const int lane = tid & 31;
    const int wid  = tid >> 5;
    const int r4   = lane >> 2;
    const int c    = lane & 3;
    const int q0   = blockIdx.x * 128;
    const int h    = blockIdx.y;
    const int b    = blockIdx.z;

    const unsigned sbase = (unsigned)__cvta_generic_to_shared(sm4);
    const unsigned k_s = sbase;              // [2][KTB]
    const unsigned v_s = sbase + 2 * KTB;    // [2][VTB]

    const __half* kb  = K + ((size_t)(b * SEQ_KV)) * D_E + h * D_HEAD;
    const __half* vtb = Vt + ((size_t)(b * N_HEADS + h)) * D_HEAD * SKV_PAD;

    // ldmatrix lane roles (B-frag matrices)
    const int lrow = (lane & 7) + ((lane & 16) ? 8 : 0);
    const int kbit = (lane & 8) ? 1 : 0;
    const int lx   = lane & 7;

    // ---- Q -> register A-frags (fp16, pre-scaled) ----
    unsigned qf[8][4];
    {
        const unsigned* qb = reinterpret_cast<const unsigned*>(
            Q + ((size_t)(b * SEQ_Q + q0 + wid * 16)) * D_E + h * D_HEAD);
        #pragma unroll
        for (int kt = 0; kt < 8; kt++) {
            qf[kt][0] = __ldg(qb + (size_t)r4 * 512 + kt * 8 + c);
            qf[kt][1] = __ldg(qb + (size_t)(r4 + 8) * 512 + kt * 8 + c);
            qf[kt][2] = __ldg(qb + (size_t)r4 * 512 + kt * 8 + c + 4);
            qf[kt][3] = __ldg(qb + (size_t)(r4 + 8) * 512 + kt * 8 + c + 4);
        }
    }

    float oacc[16][4];
    #pragma unroll
    for (int nt = 0; nt < 16; nt++)
        #pragma unroll
        for (int e = 0; e < 4; e++) oacc[nt][e] = 0.0f;

    float row_m0 = -1e30f, row_m1 = -1e30f;
    float row_l0 = 0.0f,   row_l1 = 0.0f;

    auto issue_chunk = [&](int t, int buf) {
        const int kv0 = t * 64;
        #pragma unroll
        for (int i = 0; i < 4; i++) {
            int u = tid + i * 256;
            int kv = u >> 4, g = u & 15;
            int kvg = kv0 + kv;
            int sz = (kvg < SEQ_KV) ? 16 : 0;
            int kvc = (kvg < SEQ_KV) ? kvg : (SEQ_KV - 1);
            cp_async16(k_s + (unsigned)(buf * KTB + kv * 256 + ((g ^ (kv & 7)) << 4)),
                       kb + (size_t)kvc * D_E + g * 8, sz);
        }
        #pragma unroll
        for (int i = 0; i < 4; i++) {
            int u = tid + i * 256;
            int d = u >> 3, g = u & 7;
            cp_async16(v_s + (unsigned)(buf * VTB + d * 128 + ((g ^ (d & 7)) << 4)),
                       vtb + (size_t)d * SKV_PAD + kv0 + g * 8, 16);
        }
        cp_commit();
    };

    issue_chunk(0, 0);

    for (int t = 0; t < NCHUNK; t++) {
        const int kv0 = t * 64;
        const int buf = t & 1;

        if (t + 1 < NCHUNK) { issue_chunk(t + 1, buf ^ 1); cp_wait<1>(); }
        else                { cp_wait<0>(); }
        __syncthreads();

        const unsigned kT = k_s + buf * KTB + lrow * 256;   // this lane's row base
        const unsigned vT = v_s + buf * VTB + lrow * 128;

        // ---- S = Q @ K^T ----
        float sacc[8][4];
        #pragma unroll
        for (int ni = 0; ni < 8; ni++)
            #pragma unroll
            for (int e = 0; e < 4; e++) sacc[ni][e] = 0.0f;

        #pragma unroll
        for (int kt = 0; kt < 8; kt++) {
            const unsigned goff = (unsigned)(((2 * kt + kbit) ^ lx) << 4);
            #pragma unroll
            for (int np = 0; np < 4; np++) {
                unsigned b0, b1, b2, b3;
                ldsm_x4(b0, b1, b2, b3, kT + np * 4096 + goff);
                unsigned bfA[2] = {b0, b1};
                unsigned bfB[2] = {b2, b3};
                mma_f16(sacc[2 * np],     qf[kt], bfA);
                mma_f16(sacc[2 * np + 1], qf[kt], bfB);
            }
        }

        // ---- mask + register softmax ----
        float mx0 = -1e30f, mx1 = -1e30f;
        #pragma unroll
        for (int ni = 0; ni < 8; ni++) {
            int colg = kv0 + ni * 8 + c * 2;
            if (colg >= SEQ_KV) {
                sacc[ni][0] = -1e30f; sacc[ni][1] = -1e30f;
                sacc[ni][2] = -1e30f; sacc[ni][3] = -1e30f;
            }
            mx0 = fmaxf(mx0, fmaxf(sacc[ni][0], sacc[ni][1]));
            mx1 = fmaxf(mx1, fmaxf(sacc[ni][2], sacc[ni][3]));
        }
        mx0 = fmaxf(mx0, __shfl_xor_sync(0xffffffffu, mx0, 1));
        mx0 = fmaxf(mx0, __shfl_xor_sync(0xffffffffu, mx0, 2));
        mx1 = fmaxf(mx1, __shfl_xor_sync(0xffffffffu, mx1, 1));
        mx1 = fmaxf(mx1, __shfl_xor_sync(0xffffffffu, mx1, 2));

        float mnew0 = fmaxf(row_m0, mx0);
        float mnew1 = fmaxf(row_m1, mx1);
        float sc0 = fexp(row_m0 - mnew0);
        float sc1 = fexp(row_m1 - mnew1);
        row_m0 = mnew0; row_m1 = mnew1;

        float sum0 = 0.f, sum1 = 0.f;
        #pragma unroll
        for (int ni = 0; ni < 8; ni++) {
            sacc[ni][0] = fexp(sacc[ni][0] - mnew0);
            sacc[ni][1] = fexp(sacc[ni][1] - mnew0);
            sacc[ni][2] = fexp(sacc[ni][2] - mnew1);
            sacc[ni][3] = fexp(sacc[ni][3] - mnew1);
            sum0 += sacc[ni][0] + sacc[ni][1];
            sum1 += sacc[ni][2] + sacc[ni][3];
        }
        sum0 += __shfl_xor_sync(0xffffffffu, sum0, 1);
        sum0 += __shfl_xor_sync(0xffffffffu, sum0, 2);
        sum1 += __shfl_xor_sync(0xffffffffu, sum1, 1);
        sum1 += __shfl_xor_sync(0xffffffffu, sum1, 2);
        row_l0 = row_l0 * sc0 + sum0;
        row_l1 = row_l1 * sc1 + sum1;

        #pragma unroll
        for (int nt = 0; nt < 16; nt++) {
            oacc[nt][0] *= sc0; oacc[nt][1] *= sc0;
            oacc[nt][2] *= sc1; oacc[nt][3] *= sc1;
        }

        // ---- O += P @ V : P packs directly into fp16 A-frags ----
        #pragma unroll
        for (int kt = 0; kt < 4; kt++) {
            unsigned pa[4];
            pa[0] = packh2(sacc[2 * kt][0],     sacc[2 * kt][1]);
            pa[1] = packh2(sacc[2 * kt][2],     sacc[2 * kt][3]);
            pa[2] = packh2(sacc[2 * kt + 1][0], sacc[2 * kt + 1][1]);
            pa[3] = packh2(sacc[2 * kt + 1][2], sacc[2 * kt + 1][3]);

            const unsigned goff = (unsigned)(((2 * kt + kbit) ^ lx) << 4);
            #pragma unroll
            for (int np = 0; np < 8; np++) {
                unsigned b0, b1, b2, b3;
                ldsm_x4(b0, b1, b2, b3, vT + np * 2048 + goff);
                unsigned bfA[2] = {b0, b1};
                unsigned bfB[2] = {b2, b3};
                mma_f16(oacc[2 * np],     pa, bfA);
                mma_f16(oacc[2 * np + 1], pa, bfB);
            }
        }
        __syncthreads();
    }

    // ---- normalize + write (fp16) ----
    float inv0 = 1.0f / row_l0;
    float inv1 = 1.0f / row_l1;
    __half* ob = O + ((size_t)(b * SEQ_Q + q0 + wid * 16 + r4)) * D_E + h * D_HEAD;
    #pragma unroll
    for (int nt = 0; nt < 16; nt++) {
        int colg = nt * 8 + c * 2;
        *reinterpret_cast<unsigned*>(ob + colg) =
            packh2(oacc[nt][0] * inv0, oacc[nt][1] * inv0);
        *reinterpret_cast<unsigned*>(ob + (size_t)8 * D_E + colg) =
            packh2(oacc[nt][2] * inv1, oacc[nt][3] * inv1);
    }
}

#define FA5_SMEM_BYTES (2 * KTB + 2 * VTB)   // 64 KB

// ============================================================
// launch
// ============================================================
extern "C" void kernel_launch(void* const* d_in, const int* in_sizes, int n_in,
                              void* d_out, int out_size)
{
    const float* x  = (const float*)d_in[0];
    const float* y  = (const float*)d_in[1];
    const float* Wq = (const float*)d_in[2];
    const float* bq = (const float*)d_in[3];
    const float* Wk = (const float*)d_in[4];
    const float* bk = (const float*)d_in[5];
    const float* Wv = (const float*)d_in[6];
    const float* bv = (const float*)d_in[7];
    const float* Wo = (const float*)d_in[8];
    const float* bo = (const float*)d_in[9];
    float* out = (float*)d_out;

    __half *hx, *hy, *hWq, *hWk, *hWv, *hWo, *pQ, *pK, *pV, *pVt, *pO;
    cudaGetSymbolAddress((void**)&hx,  g_hx);
    cudaGetSymbolAddress((void**)&hy,  g_hy);
    cudaGetSymbolAddress((void**)&hWq, g_hWq);
    cudaGetSymbolAddress((void**)&hWk, g_hWk);
    cudaGetSymbolAddress((void**)&hWv, g_hWv);
    cudaGetSymbolAddress((void**)&hWo, g_hWo);
    cudaGetSymbolAddress((void**)&pQ,  g_Q);
    cudaGetSymbolAddress((void**)&pK,  g_K);
    cudaGetSymbolAddress((void**)&pV,  g_V);
    cudaGetSymbolAddress((void**)&pVt, g_Vt);
    cudaGetSymbolAddress((void**)&pO,  g_O);

    const float qscale = 0.08838834764831845f;  // 1/sqrt(128)

    auto cvt = [&](const float* src, __half* dst, size_t n) {
        int n4 = (int)(n / 4);
        cvt_fp16<<<(n4 + 255) / 256, 256>>>(src, dst, n4);
    };
    cvt(x,  hx,  (size_t)MQ * D_E);
    cvt(y,  hy,  (size_t)MKV * D_C);
    cvt(Wq, hWq, (size_t)D_E * D_E);
    cvt(Wk, hWk, (size_t)D_E * D_C);
    cvt(Wv, hWv, (size_t)D_E * D_C);
    cvt(Wo, hWo, (size_t)D_E * D_E);

    // Q projection (fp16 out, pre-scaled)
    gemm_f16<<<dim3(8, (MQ + 127) / 128), 256>>>(
        hx, hWq, bq, pQ, nullptr, nullptr, nullptr, 8, MQ, D_E, D_E, qscale, 1);
    // K and V projections fused in one launch
    gemm_f16<<<dim3(16, (MKV + 127) / 128), 256>>>(
        hy, hWk, bk, pK, hWv, bv, pV, 8, MKV, D_E, D_C, 1.0f, 1);

    // V transpose
    transpose_v<<<dim3(SKV_PAD / 32, D_HEAD / 32, BATCH * N_HEADS), dim3(32, 8)>>>(pV, pVt);

    // attention
    cudaFuncSetAttribute(fa5_f16, cudaFuncAttributeMaxDynamicSharedMemorySize, FA5_SMEM_BYTES);
    fa5_f16<<<dim3(SEQ_Q / 128, N_HEADS, BATCH), 256, FA5_SMEM_BYTES>>>(pQ, pK, pVt, pO);

    // output projection -> d_out (fp32)
    gemm_f16<<<dim3(8, (MQ + 127) / 128), 256>>>(
        pO, hWo, bo, out, nullptr, nullptr, nullptr, 8, MQ, D_E, D_E, 1.0f, 0);
}

// round 11
// speedup vs baseline: 7.5826x; 1.0118x over previous
#include <cuda_runtime.h>
#include <cuda_fp16.h>
#include <math.h>

// ---------------- problem constants ----------------
#define BATCH   4
#define SEQ_Q   3072
#define SEQ_KV  1036
#define D_E     1024
#define D_C     768
#define N_HEADS 8
#define D_HEAD  128

#define MQ (BATCH * SEQ_Q)    // 12288
#define MKV (BATCH * SEQ_KV)  // 4144
#define SKV_PAD 1088

// ---------------- scratch ----------------
__device__ __half g_hx[(size_t)MQ * D_E];
__device__ __half g_hy[(size_t)MKV * D_C];
__device__ __half g_hWq[(size_t)D_E * D_E];
__device__ __half g_hWk[(size_t)D_E * D_C];
__device__ __half g_hWv[(size_t)D_E * D_C];
__device__ __half g_hWo[(size_t)D_E * D_E];
__device__ __half g_Q[(size_t)MQ * D_E];
__device__ __half g_K[(size_t)MKV * D_E];
__device__ __half g_V[(size_t)MKV * D_E];
__device__ __half g_Vt[(size_t)BATCH * N_HEADS * D_HEAD * SKV_PAD];
__device__ __half g_O[(size_t)MQ * D_E];

// ---------------- helpers ----------------
__device__ __forceinline__ unsigned packh2(float lo, float hi) {
    __half2 h = __floats2half2_rn(lo, hi);
    return *reinterpret_cast<unsigned*>(&h);
}

__device__ __forceinline__ void mma_f16(float d[4], const unsigned a[4], const unsigned b[2]) {
    asm volatile(
        "mma.sync.aligned.m16n8k16.row.col.f32.f16.f16.f32 "
        "{%0,%1,%2,%3}, {%4,%5,%6,%7}, {%8,%9}, {%0,%1,%2,%3};\n"
        : "+f"(d[0]), "+f"(d[1]), "+f"(d[2]), "+f"(d[3])
        : "r"(a[0]), "r"(a[1]), "r"(a[2]), "r"(a[3]),
          "r"(b[0]), "r"(b[1]));
}

__device__ __forceinline__ void ldsm_x4(unsigned& r0, unsigned& r1, unsigned& r2, unsigned& r3,
                                        unsigned saddr) {
    asm volatile("ldmatrix.sync.aligned.m8n8.x4.shared.b16 {%0,%1,%2,%3}, [%4];"
                 : "=r"(r0), "=r"(r1), "=r"(r2), "=r"(r3) : "r"(saddr));
}

__device__ __forceinline__ float fexp(float x) {
    x = fmaxf(x, -87.0f);
    float xl = x * 1.4426950408889634f;
    float y  = xl + 12582912.0f;
    int   n  = __float_as_int(y) - 0x4B400000;
    float f  = xl - (y - 12582912.0f);
    float p  = 1.33335581e-3f;
    p = fmaf(p, f, 9.61812911e-3f);
    p = fmaf(p, f, 5.55041087e-2f);
    p = fmaf(p, f, 2.40226507e-1f);
    p = fmaf(p, f, 6.93147182e-1f);
    p = fmaf(p, f, 1.0f);
    return __int_as_float(__float_as_int(p) + (n << 23));
}

__device__ __forceinline__ void cp_async16(unsigned dst, const void* src, int src_bytes) {
    asm volatile("cp.async.cg.shared.global [%0], [%1], 16, %2;"
                 :: "r"(dst), "l"(src), "r"(src_bytes));
}
__device__ __forceinline__ void cp_commit() { asm volatile("cp.async.commit_group;"); }
template<int N>
__device__ __forceinline__ void cp_wait() { asm volatile("cp.async.wait_group %0;" :: "n"(N)); }

// ============================================================
// fp32 -> fp16 conversions (2 launches total)
// ============================================================
__global__ __launch_bounds__(256) void cvt_fp16(const float* __restrict__ in,
                                                __half* __restrict__ out, int n4)
{
    int i = blockIdx.x * 256 + threadIdx.x;
    if (i < n4) {
        float4 v = *reinterpret_cast<const float4*>(in + (size_t)i * 4);
        __half2* o = reinterpret_cast<__half2*>(out + (size_t)i * 4);
        o[0] = __floats2half2_rn(v.x, v.y);
        o[1] = __floats2half2_rn(v.z, v.w);
    }
}

// segmented: y, Wq, Wk, Wv, Wo in one launch (sizes in float4 units)
#define C_N0 795648    // y: 4144*768/4
#define C_N1 1057792   // +Wq 262144
#define C_N2 1254400   // +Wk 196608
#define C_N3 1451008   // +Wv 196608
#define C_N4 1713152   // +Wo 262144

__global__ __launch_bounds__(256) void cvt_rest(
    const float* __restrict__ y,  const float* __restrict__ wq,
    const float* __restrict__ wk, const float* __restrict__ wv,
    const float* __restrict__ wo,
    __half* hy, __half* hwq, __half* hwk, __half* hwv, __half* hwo)
{
    int i = blockIdx.x * 256 + threadIdx.x;
    const float* src; __half* dst; int j;
    if      (i < C_N0) { src = y;  dst = hy;  j = i; }
    else if (i < C_N1) { src = wq; dst = hwq; j = i - C_N0; }
    else if (i < C_N2) { src = wk; dst = hwk; j = i - C_N1; }
    else if (i < C_N3) { src = wv; dst = hwv; j = i - C_N2; }
    else if (i < C_N4) { src = wo; dst = hwo; j = i - C_N3; }
    else return;
    float4 v = *reinterpret_cast<const float4*>(src + (size_t)j * 4);
    __half2* o = reinterpret_cast<__half2*>(dst + (size_t)j * 4);
    o[0] = __floats2half2_rn(v.x, v.y);
    o[1] = __floats2half2_rn(v.z, v.w);
}

// ============================================================
// V transpose: g_V [MKV][D_E] -> g_Vt [B*H][128][SKV_PAD]
// ============================================================
__global__ __launch_bounds__(256) void transpose_v(const __half* __restrict__ V,
                                                   __half* __restrict__ Vt)
{
    __shared__ __half t[32][33];
    const int tx = threadIdx.x;
    const int ty = threadIdx.y;
    const int kv0 = blockIdx.x * 32;
    const int d0  = blockIdx.y * 32;
    const int bh  = blockIdx.z;
    const int b   = bh >> 3, h = bh & 7;

    #pragma unroll
    for (int j = 0; j < 4; j++) {
        int kvL = ty * 4 + j;
        int kv  = kv0 + kvL;
        __half v = __float2half(0.0f);
        if (kv < SEQ_KV)
            v = V[(size_t)(b * SEQ_KV + kv) * D_E + h * D_HEAD + d0 + tx];
        t[kvL][tx] = v;
    }
    __syncthreads();
    #pragma unroll
    for (int j = 0; j < 4; j++) {
        int dL = ty * 4 + j;
        Vt[((size_t)bh * D_HEAD + d0 + dL) * SKV_PAD + kv0 + tx] = t[tx][dL];
    }
}

// ============================================================
// fp16 tensor-core GEMM (dual-output capable):
//   blocks with blockIdx.x <  nx: C  = A @ W^T  + bias
//   blocks with blockIdx.x >= nx: C2 = A @ W2^T + bias2
// block 128x128x32(half), 3-stage cp.async pipeline, ldmatrix frags
// dynamic smem: sA[3][10240B] then sB[3][10240B]
// ============================================================
#define GEMM_STAGE 10240u
#define GEMM_SMEM  (6 * 10240)

__global__ __launch_bounds__(256, 2) void gemm_f16(
    const __half* __restrict__ A,
    const __half* __restrict__ W,  const float* __restrict__ bias,  void* Cv,
    const __half* __restrict__ W2, const float* __restrict__ bias2, void* Cv2,
    int nx, int M, int N, int K, float oscale, int ohalf)
{
    extern __shared__ __half gsm[];

    const int tid  = threadIdx.x;
    const int lane = tid & 31;
    const int wid  = tid >> 5;
    const int wm   = wid >> 2;
    const int wn   = wid & 3;
    const int r4   = lane >> 2;
    const int c    = lane & 3;
    const int m0   = blockIdx.y * 128;

    int bx = blockIdx.x;
    if (bx >= nx) { W = W2; bias = bias2; Cv = Cv2; bx -= nx; }
    const int n0 = bx * 128;

    const unsigned sa_s = (unsigned)__cvta_generic_to_shared(gsm);
    const unsigned sb_s = sa_s + 3 * GEMM_STAGE;

    float acc[4][4][4];
    #pragma unroll
    for (int i = 0; i < 4; i++)
        #pragma unroll
        for (int j = 0; j < 4; j++)
            #pragma unroll
            for (int e = 0; e < 4; e++) acc[i][j][e] = 0.0f;

    auto issue = [&](int k0, int buf) {
        #pragma unroll
        for (int i = 0; i < 2; i++) {
            int u = tid + i * 256;
            int row = u >> 2, g = u & 3;
            int gr = m0 + row;
            int sz = (gr < M) ? 16 : 0;
            int grc = (gr < M) ? gr : (M - 1);
            cp_async16(sa_s + (unsigned)buf * GEMM_STAGE + (unsigned)(row * 80 + g * 16),
                       A + (size_t)grc * K + k0 + g * 8, sz);
        }
        #pragma unroll
        for (int i = 0; i < 2; i++) {
            int u = tid + i * 256;
            int row = u >> 2, g = u & 3;
            cp_async16(sb_s + (unsigned)buf * GEMM_STAGE + (unsigned)(row * 80 + g * 16),
                       W + (size_t)(n0 + row) * K + k0 + g * 8, 16);
        }
        cp_commit();
    };

    // ldmatrix lane roles
    const int arow = (lane & 7) + (lane & 8);
    const int ahi  = (lane & 16) ? 16 : 0;
    const int brow = (lane & 7) + ((lane & 16) ? 8 : 0);
    const int bhi  = (lane & 8) ? 16 : 0;

    const int nk = K / 32;
    issue(0, 0);
    if (nk > 1) issue(32, 1);

    for (int i = 0; i < nk; i++) {
        const int buf = i % 3;
        if (i + 2 < nk) issue((i + 2) * 32, (i + 2) % 3);

        if (i + 3 <= nk) cp_wait<2>();
        else if (i + 2 == nk) cp_wait<1>();
        else cp_wait<0>();
        __syncthreads();

        const unsigned aT = sa_s + (unsigned)buf * GEMM_STAGE;
        const unsigned bT = sb_s + (unsigned)buf * GEMM_STAGE;

        #pragma unroll
        for (int kt = 0; kt < 2; kt++) {
            unsigned af[4][4], bf[4][2];
            #pragma unroll
            for (int mi = 0; mi < 4; mi++)
                ldsm_x4(af[mi][0], af[mi][1], af[mi][2], af[mi][3],
                        aT + (unsigned)((wm * 64 + mi * 16 + arow) * 80 + kt * 32 + ahi));
            #pragma unroll
            for (int nip = 0; nip < 2; nip++)
                ldsm_x4(bf[2 * nip][0], bf[2 * nip][1], bf[2 * nip + 1][0], bf[2 * nip + 1][1],
                        bT + (unsigned)((wn * 32 + nip * 16 + brow) * 80 + kt * 32 + bhi));
            #pragma unroll
            for (int mi = 0; mi < 4; mi++)
                #pragma unroll
                for (int ni = 0; ni < 4; ni++)
                    mma_f16(acc[mi][ni], af[mi], bf[ni]);
        }
        __syncthreads();
    }

    // ---- epilogue ----
    #pragma unroll
    for (int mi = 0; mi < 4; mi++) {
        int row1 = m0 + wm * 64 + mi * 16 + r4;
        int row2 = row1 + 8;
        #pragma unroll
        for (int ni = 0; ni < 4; ni++) {
            int colg = n0 + wn * 32 + ni * 8 + c * 2;
            float b0 = bias[colg], b1 = bias[colg + 1];
            float v00 = acc[mi][ni][0] + b0, v01 = acc[mi][ni][1] + b1;
            float v10 = acc[mi][ni][2] + b0, v11 = acc[mi][ni][3] + b1;
            if (ohalf) {
                __half* C = (__half*)Cv;
                if (row1 < M)
                    *reinterpret_cast<unsigned*>(C + (size_t)row1 * N + colg) =
                        packh2(oscale * v00, oscale * v01);
                if (row2 < M)
                    *reinterpret_cast<unsigned*>(C + (size_t)row2 * N + colg) =
                        packh2(oscale * v10, oscale * v11);
            } else {
                float* C = (float*)Cv;
                if (row1 < M)
                    *reinterpret_cast<float2*>(C + (size_t)row1 * N + colg) = make_float2(v00, v01);
                if (row2 < M)
                    *reinterpret_cast<float2*>(C + (size_t)row2 * N + colg) = make_float2(v10, v11);
            }
        }
    }
}

// ============================================================
// fa5: fp16 flash attention, ldmatrix frags, 3-stage cp.async
// CTA: 128 q rows, 8 warps (16 q rows each), kv chunks of 64
// K tile [64 kv][128 d]h (256B rows), Vt tile [128 d][64 kv]h (128B rows)
// smem: K stages [3][16KB] then V stages [3][16KB] = 96KB
// ============================================================
#define NCHUNK 17
#define KTB 16384u
#define VTB 16384u
#define FA5_SMEM_BYTES (3 * (16384 + 16384))

__global__ __launch_bounds__(256, 1) void fa5_f16(
    const __half* __restrict__ Q, const __half* __restrict__ K,
    const __half* __restrict__ Vt, __half* __restrict__ O)
{
    extern __shared__ unsigned sm4[];

    const int tid  = threadIdx.x;
    const int lane = tid & 31;
    const int wid  = tid >> 5;
    const int r4   = lane >> 2;
    const int c    = lane & 3;
    const int q0   = blockIdx.x * 128;
    const int h    = blockIdx.y;
    const int b    = blockIdx.z;

    const unsigned sbase = (unsigned)__cvta_generic_to_shared(sm4);
    const unsigned k_s = sbase;                // [3][KTB]
    const unsigned v_s = sbase + 3 * KTB;      // [3][VTB]

    const __half* kb  = K + ((size_t)(b * SEQ_KV)) * D_E + h * D_HEAD;
    const __half* vtb = Vt + ((size_t)(b * N_HEADS + h)) * D_HEAD * SKV_PAD;

    const int lrow = (lane & 7) + ((lane & 16) ? 8 : 0);
    const int kbit = (lane & 8) ? 1 : 0;
    const int lx   = lane & 7;

    unsigned qf[8][4];
    {
        const unsigned* qb = reinterpret_cast<const unsigned*>(
            Q + ((size_t)(b * SEQ_Q + q0 + wid * 16)) * D_E + h * D_HEAD);
        #pragma unroll
        for (int kt = 0; kt < 8; kt++) {
            qf[kt][0] = __ldg(qb + (size_t)r4 * 512 + kt * 8 + c);
            qf[kt][1] = __ldg(qb + (size_t)(r4 + 8) * 512 + kt * 8 + c);
            qf[kt][2] = __ldg(qb + (size_t)r4 * 512 + kt * 8 + c + 4);
            qf[kt][3] = __ldg(qb + (size_t)(r4 + 8) * 512 + kt * 8 + c + 4);
        }
    }

    float oacc[16][4];
    #pragma unroll
    for (int nt = 0; nt < 16; nt++)
        #pragma unroll
        for (int e = 0; e < 4; e++) oacc[nt][e] = 0.0f;

    float row_m0 = -1e30f, row_m1 = -1e30f;
    float row_l0 = 0.0f,   row_l1 = 0.0f;

    auto issue_chunk = [&](int t, int buf) {
        const int kv0 = t * 64;
        #pragma unroll
        for (int i = 0; i < 4; i++) {
            int u = tid + i * 256;
            int kv = u >> 4, g = u & 15;
            int kvg = kv0 + kv;
            int sz = (kvg < SEQ_KV) ? 16 : 0;
            int kvc = (kvg < SEQ_KV) ? kvg : (SEQ_KV - 1);
            cp_async16(k_s + (unsigned)buf * KTB + (unsigned)(kv * 256 + ((g ^ (kv & 7)) << 4)),
                       kb + (size_t)kvc * D_E + g * 8, sz);
        }
        #pragma unroll
        for (int i = 0; i < 4; i++) {
            int u = tid + i * 256;
            int d = u >> 3, g = u & 7;
            cp_async16(v_s + (unsigned)buf * VTB + (unsigned)(d * 128 + ((g ^ (d & 7)) << 4)),
                       vtb + (size_t)d * SKV_PAD + kv0 + g * 8, 16);
        }
        cp_commit();
    };

    issue_chunk(0, 0);
    issue_chunk(1, 1);

    for (int t = 0; t < NCHUNK; t++) {
        const int kv0 = t * 64;
        const int buf = t % 3;

        if (t + 2 < NCHUNK) issue_chunk(t + 2, (t + 2) % 3);

        if (t + 3 <= NCHUNK) cp_wait<2>();
        else if (t + 2 == NCHUNK) cp_wait<1>();
        else cp_wait<0>();
        __syncthreads();

        const unsigned kT = k_s + (unsigned)buf * KTB + lrow * 256;
        const unsigned vT = v_s + (unsigned)buf * VTB + lrow * 128;

        // ---- S = Q @ K^T ----
        float sacc[8][4];
        #pragma unroll
        for (int ni = 0; ni < 8; ni++)
            #pragma unroll
            for (int e = 0; e < 4; e++) sacc[ni][e] = 0.0f;

        #pragma unroll
        for (int kt = 0; kt < 8; kt++) {
            const unsigned goff = (unsigned)(((2 * kt + kbit) ^ lx) << 4);
            #pragma unroll
            for (int np = 0; np < 4; np++) {
                unsigned b0, b1, b2, b3;
                ldsm_x4(b0, b1, b2, b3, kT + np * 4096 + goff);
                unsigned bfA[2] = {b0, b1};
                unsigned bfB[2] = {b2, b3};
                mma_f16(sacc[2 * np],     qf[kt], bfA);
                mma_f16(sacc[2 * np + 1], qf[kt], bfB);
            }
        }

        // ---- mask + register softmax ----
        float mx0 = -1e30f, mx1 = -1e30f;
        #pragma unroll
        for (int ni = 0; ni < 8; ni++) {
            int colg = kv0 + ni * 8 + c * 2;
            if (colg >= SEQ_KV) {
                sacc[ni][0] = -1e30f; sacc[ni][1] = -1e30f;
                sacc[ni][2] = -1e30f; sacc[ni][3] = -1e30f;
            }
            mx0 = fmaxf(mx0, fmaxf(sacc[ni][0], sacc[ni][1]));
            mx1 = fmaxf(mx1, fmaxf(sacc[ni][2], sacc[ni][3]));
        }
        mx0 = fmaxf(mx0, __shfl_xor_sync(0xffffffffu, mx0, 1));
        mx0 = fmaxf(mx0, __shfl_xor_sync(0xffffffffu, mx0, 2));
        mx1 = fmaxf(mx1, __shfl_xor_sync(0xffffffffu, mx1, 1));
        mx1 = fmaxf(mx1, __shfl_xor_sync(0xffffffffu, mx1, 2));

        float mnew0 = fmaxf(row_m0, mx0);
        float mnew1 = fmaxf(row_m1, mx1);
        float sc0 = fexp(row_m0 - mnew0);
        float sc1 = fexp(row_m1 - mnew1);
        row_m0 = mnew0; row_m1 = mnew1;

        float sum0 = 0.f, sum1 = 0.f;
        #pragma unroll
        for (int ni = 0; ni < 8; ni++) {
            sacc[ni][0] = fexp(sacc[ni][0] - mnew0);
            sacc[ni][1] = fexp(sacc[ni][1] - mnew0);
            sacc[ni][2] = fexp(sacc[ni][2] - mnew1);
            sacc[ni][3] = fexp(sacc[ni][3] - mnew1);
            sum0 += sacc[ni][0] + sacc[ni][1];
            sum1 += sacc[ni][2] + sacc[ni][3];
        }
        sum0 += __shfl_xor_sync(0xffffffffu, sum0, 1);
        sum0 += __shfl_xor_sync(0xffffffffu, sum0, 2);
        sum1 += __shfl_xor_sync(0xffffffffu, sum1, 1);
        sum1 += __shfl_xor_sync(0xffffffffu, sum1, 2);
        row_l0 = row_l0 * sc0 + sum0;
        row_l1 = row_l1 * sc1 + sum1;

        #pragma unroll
        for (int nt = 0; nt < 16; nt++) {
            oacc[nt][0] *= sc0; oacc[nt][1] *= sc0;
            oacc[nt][2] *= sc1; oacc[nt][3] *= sc1;
        }

        // ---- O += P @ V : P packs directly into fp16 A-frags ----
        #pragma unroll
        for (int kt = 0; kt < 4; kt++) {
            unsigned pa[4];
            pa[0] = packh2(sacc[2 * kt][0],     sacc[2 * kt][1]);
            pa[1] = packh2(sacc[2 * kt][2],     sacc[2 * kt][3]);
            pa[2] = packh2(sacc[2 * kt + 1][0], sacc[2 * kt + 1][1]);
            pa[3] = packh2(sacc[2 * kt + 1][2], sacc[2 * kt + 1][3]);

            const unsigned goff = (unsigned)(((2 * kt + kbit) ^ lx) << 4);
            #pragma unroll
            for (int np = 0; np < 8; np++) {
                unsigned b0, b1, b2, b3;
                ldsm_x4(b0, b1, b2, b3, vT + np * 2048 + goff);
                unsigned bfA[2] = {b0, b1};
                unsigned bfB[2] = {b2, b3};
                mma_f16(oacc[2 * np],     pa, bfA);
                mma_f16(oacc[2 * np + 1], pa, bfB);
            }
        }
        __syncthreads();
    }

    float inv0 = 1.0f / row_l0;
    float inv1 = 1.0f / row_l1;
    __half* ob = O + ((size_t)(b * SEQ_Q + q0 + wid * 16 + r4)) * D_E + h * D_HEAD;
    #pragma unroll
    for (int nt = 0; nt < 16; nt++) {
        int colg = nt * 8 + c * 2;
        *reinterpret_cast<unsigned*>(ob + colg) =
            packh2(oacc[nt][0] * inv0, oacc[nt][1] * inv0);
        *reinterpret_cast<unsigned*>(ob + (size_t)8 * D_E + colg) =
            packh2(oacc[nt][2] * inv1, oacc[nt][3] * inv1);
    }
}

// ============================================================
// launch
// ============================================================
extern "C" void kernel_launch(void* const* d_in, const int* in_sizes, int n_in,
                              void* d_out, int out_size)
{
    const float* x  = (const float*)d_in[0];
    const float* y  = (const float*)d_in[1];
    const float* Wq = (const float*)d_in[2];
    const float* bq = (const float*)d_in[3];
    const float* Wk = (const float*)d_in[4];
    const float* bk = (const float*)d_in[5];
    const float* Wv = (const float*)d_in[6];
    const float* bv = (const float*)d_in[7];
    const float* Wo = (const float*)d_in[8];
    const float* bo = (const float*)d_in[9];
    float* out = (float*)d_out;

    __half *hx, *hy, *hWq, *hWk, *hWv, *hWo, *pQ, *pK, *pV, *pVt, *pO;
    cudaGetSymbolAddress((void**)&hx,  g_hx);
    cudaGetSymbolAddress((void**)&hy,  g_hy);
    cudaGetSymbolAddress((void**)&hWq, g_hWq);
    cudaGetSymbolAddress((void**)&hWk, g_hWk);
    cudaGetSymbolAddress((void**)&hWv, g_hWv);
    cudaGetSymbolAddress((void**)&hWo, g_hWo);
    cudaGetSymbolAddress((void**)&pQ,  g_Q);
    cudaGetSymbolAddress((void**)&pK,  g_K);
    cudaGetSymbolAddress((void**)&pV,  g_V);
    cudaGetSymbolAddress((void**)&pVt, g_Vt);
    cudaGetSymbolAddress((void**)&pO,  g_O);

    const float qscale = 0.08838834764831845f;  // 1/sqrt(128)

    // launch 0: cvt x ; launch 1: cvt y + all weights (segmented)
    {
        int n4 = (int)((size_t)MQ * D_E / 4);
        cvt_fp16<<<(n4 + 255) / 256, 256>>>(x, hx, n4);
        cvt_rest<<<(C_N4 + 255) / 256, 256>>>(y, Wq, Wk, Wv, Wo, hy, hWq, hWk, hWv, hWo);
    }

    cudaFuncSetAttribute(gemm_f16, cudaFuncAttributeMaxDynamicSharedMemorySize, GEMM_SMEM);

    // launch 2: Q projection (fp16 out, pre-scaled)
    gemm_f16<<<dim3(8, (MQ + 127) / 128), 256, GEMM_SMEM>>>(
        hx, hWq, bq, pQ, nullptr, nullptr, nullptr, 8, MQ, D_E, D_E, qscale, 1);
    // launch 3: K and V projections fused
    gemm_f16<<<dim3(16, (MKV + 127) / 128), 256, GEMM_SMEM>>>(
        hy, hWk, bk, pK, hWv, bv, pV, 8, MKV, D_E, D_C, 1.0f, 1);

    // launch 4: V transpose
    transpose_v<<<dim3(SKV_PAD / 32, D_HEAD / 32, BATCH * N_HEADS), dim3(32, 8)>>>(pV, pVt);

    // launch 5: attention (ncu -s 5 captures this)
    cudaFuncSetAttribute(fa5_f16, cudaFuncAttributeMaxDynamicSharedMemorySize, FA5_SMEM_BYTES);
    fa5_f16<<<dim3(SEQ_Q / 128, N_HEADS, BATCH), 256, FA5_SMEM_BYTES>>>(pQ, pK, pVt, pO);

    // launch 6: output projection -> d_out (fp32)
    gemm_f16<<<dim3(8, (MQ + 127) / 128), 256, GEMM_SMEM>>>(
        pO, hWo, bo, out, nullptr, nullptr, nullptr, 8, MQ, D_E, D_E, 1.0f, 0);
}

// round 12
// speedup vs baseline: 8.1488x; 1.0747x over previous
#include <cuda_runtime.h>
#include <cuda_fp16.h>
#include <math.h>

// ---------------- problem constants ----------------
#define BATCH   4
#define SEQ_Q   3072
#define SEQ_KV  1036
#define D_E     1024
#define D_C     768
#define N_HEADS 8
#define D_HEAD  128

#define MQ (BATCH * SEQ_Q)    // 12288
#define MKV (BATCH * SEQ_KV)  // 4144
#define SKV_PAD 1088

// ---------------- scratch ----------------
__device__ __half g_hx[(size_t)MQ * D_E];
__device__ __half g_hy[(size_t)MKV * D_C];
__device__ __half g_hWq[(size_t)D_E * D_E];
__device__ __half g_hWk[(size_t)D_E * D_C];
__device__ __half g_hWv[(size_t)D_E * D_C];
__device__ __half g_hWo[(size_t)D_E * D_E];
__device__ __half g_Q[(size_t)MQ * D_E];
__device__ __half g_K[(size_t)MKV * D_E];
__device__ __half g_V[(size_t)MKV * D_E];
__device__ __half g_Vt[(size_t)BATCH * N_HEADS * D_HEAD * SKV_PAD];
__device__ __half g_O[(size_t)MQ * D_E];

// ---------------- helpers ----------------
__device__ __forceinline__ unsigned packh2(float lo, float hi) {
    __half2 h = __floats2half2_rn(lo, hi);
    return *reinterpret_cast<unsigned*>(&h);
}

__device__ __forceinline__ void mma_f16(float d[4], const unsigned a[4], const unsigned b[2]) {
    asm volatile(
        "mma.sync.aligned.m16n8k16.row.col.f32.f16.f16.f32 "
        "{%0,%1,%2,%3}, {%4,%5,%6,%7}, {%8,%9}, {%0,%1,%2,%3};\n"
        : "+f"(d[0]), "+f"(d[1]), "+f"(d[2]), "+f"(d[3])
        : "r"(a[0]), "r"(a[1]), "r"(a[2]), "r"(a[3]),
          "r"(b[0]), "r"(b[1]));
}

__device__ __forceinline__ void ldsm_x4(unsigned& r0, unsigned& r1, unsigned& r2, unsigned& r3,
                                        unsigned saddr) {
    asm volatile("ldmatrix.sync.aligned.m8n8.x4.shared.b16 {%0,%1,%2,%3}, [%4];"
                 : "=r"(r0), "=r"(r1), "=r"(r2), "=r"(r3) : "r"(saddr));
}

__device__ __forceinline__ float fexp(float x) {
    x = fmaxf(x, -87.0f);
    float xl = x * 1.4426950408889634f;
    float y  = xl + 12582912.0f;
    int   n  = __float_as_int(y) - 0x4B400000;
    float f  = xl - (y - 12582912.0f);
    float p  = 1.33335581e-3f;
    p = fmaf(p, f, 9.61812911e-3f);
    p = fmaf(p, f, 5.55041087e-2f);
    p = fmaf(p, f, 2.40226507e-1f);
    p = fmaf(p, f, 6.93147182e-1f);
    p = fmaf(p, f, 1.0f);
    return __int_as_float(__float_as_int(p) + (n << 23));
}

__device__ __forceinline__ void cp_async16(unsigned dst, const void* src, int src_bytes) {
    asm volatile("cp.async.cg.shared.global [%0], [%1], 16, %2;"
                 :: "r"(dst), "l"(src), "r"(src_bytes));
}
__device__ __forceinline__ void cp_commit() { asm volatile("cp.async.commit_group;"); }
template<int N>
__device__ __forceinline__ void cp_wait() { asm volatile("cp.async.wait_group %0;" :: "n"(N)); }

// ============================================================
// fp32 -> fp16 conversion: all 6 tensors in ONE launch (segmented)
// ============================================================
#define C_NX 3145728   // x: 12288*1024/4
#define C_N0 (C_NX + 795648)    // +y 4144*768/4
#define C_N1 (C_N0 + 262144)    // +Wq
#define C_N2 (C_N1 + 196608)    // +Wk
#define C_N3 (C_N2 + 196608)    // +Wv
#define C_N4 (C_N3 + 262144)    // +Wo

__global__ __launch_bounds__(256) void cvt_all(
    const float* __restrict__ x,  const float* __restrict__ y,
    const float* __restrict__ wq, const float* __restrict__ wk,
    const float* __restrict__ wv, const float* __restrict__ wo,
    __half* hx, __half* hy, __half* hwq, __half* hwk, __half* hwv, __half* hwo)
{
    int i = blockIdx.x * 256 + threadIdx.x;
    const float* src; __half* dst; int j;
    if      (i < C_NX) { src = x;  dst = hx;  j = i; }
    else if (i < C_N0) { src = y;  dst = hy;  j = i - C_NX; }
    else if (i < C_N1) { src = wq; dst = hwq; j = i - C_N0; }
    else if (i < C_N2) { src = wk; dst = hwk; j = i - C_N1; }
    else if (i < C_N3) { src = wv; dst = hwv; j = i - C_N2; }
    else if (i < C_N4) { src = wo; dst = hwo; j = i - C_N3; }
    else return;
    float4 v = *reinterpret_cast<const float4*>(src + (size_t)j * 4);
    __half2* o = reinterpret_cast<__half2*>(dst + (size_t)j * 4);
    o[0] = __floats2half2_rn(v.x, v.y);
    o[1] = __floats2half2_rn(v.z, v.w);
}

// ============================================================
// V transpose: g_V [MKV][D_E] -> g_Vt [B*H][128][SKV_PAD]
// ============================================================
__global__ __launch_bounds__(256) void transpose_v(const __half* __restrict__ V,
                                                   __half* __restrict__ Vt)
{
    __shared__ __half t[32][33];
    const int tx = threadIdx.x;
    const int ty = threadIdx.y;
    const int kv0 = blockIdx.x * 32;
    const int d0  = blockIdx.y * 32;
    const int bh  = blockIdx.z;
    const int b   = bh >> 3, h = bh & 7;

    #pragma unroll
    for (int j = 0; j < 4; j++) {
        int kvL = ty * 4 + j;
        int kv  = kv0 + kvL;
        __half v = __float2half(0.0f);
        if (kv < SEQ_KV)
            v = V[(size_t)(b * SEQ_KV + kv) * D_E + h * D_HEAD + d0 + tx];
        t[kvL][tx] = v;
    }
    __syncthreads();
    #pragma unroll
    for (int j = 0; j < 4; j++) {
        int dL = ty * 4 + j;
        Vt[((size_t)bh * D_HEAD + d0 + dL) * SKV_PAD + kv0 + tx] = t[tx][dL];
    }
}

// ============================================================
// fp16 tensor-core GEMM (dual-output capable):
// block 128x128x32(half), 4-stage cp.async pipeline, single sync/iter,
// ldmatrix frags. dynamic smem: sA[4][10240B] then sB[4][10240B] = 80KB
// ============================================================
#define GEMM_STAGE 10240u
#define GEMM_SMEM  (8 * 10240)

__global__ __launch_bounds__(256, 2) void gemm_f16(
    const __half* __restrict__ A,
    const __half* __restrict__ W,  const float* __restrict__ bias,  void* Cv,
    const __half* __restrict__ W2, const float* __restrict__ bias2, void* Cv2,
    int nx, int M, int N, int K, float oscale, int ohalf)
{
    extern __shared__ __half gsm[];

    const int tid  = threadIdx.x;
    const int lane = tid & 31;
    const int wid  = tid >> 5;
    const int wm   = wid >> 2;
    const int wn   = wid & 3;
    const int r4   = lane >> 2;
    const int c    = lane & 3;
    const int m0   = blockIdx.y * 128;

    int bx = blockIdx.x;
    if (bx >= nx) { W = W2; bias = bias2; Cv = Cv2; bx -= nx; }
    const int n0 = bx * 128;

    const unsigned sa_s = (unsigned)__cvta_generic_to_shared(gsm);
    const unsigned sb_s = sa_s + 4 * GEMM_STAGE;

    float acc[4][4][4];
    #pragma unroll
    for (int i = 0; i < 4; i++)
        #pragma unroll
        for (int j = 0; j < 4; j++)
            #pragma unroll
            for (int e = 0; e < 4; e++) acc[i][j][e] = 0.0f;

    auto issue = [&](int k0, int buf) {
        #pragma unroll
        for (int i = 0; i < 2; i++) {
            int u = tid + i * 256;
            int row = u >> 2, g = u & 3;
            int gr = m0 + row;
            int sz = (gr < M) ? 16 : 0;
            int grc = (gr < M) ? gr : (M - 1);
            cp_async16(sa_s + (unsigned)buf * GEMM_STAGE + (unsigned)(row * 80 + g * 16),
                       A + (size_t)grc * K + k0 + g * 8, sz);
        }
        #pragma unroll
        for (int i = 0; i < 2; i++) {
            int u = tid + i * 256;
            int row = u >> 2, g = u & 3;
            cp_async16(sb_s + (unsigned)buf * GEMM_STAGE + (unsigned)(row * 80 + g * 16),
                       W + (size_t)(n0 + row) * K + k0 + g * 8, 16);
        }
        cp_commit();
    };

    // ldmatrix lane roles
    const int arow = (lane & 7) + (lane & 8);
    const int ahi  = (lane & 16) ? 16 : 0;
    const int brow = (lane & 7) + ((lane & 16) ? 8 : 0);
    const int bhi  = (lane & 8) ? 16 : 0;

    const int nk = K / 32;
    issue(0, 0);
    if (nk > 1) issue(32, 1);
    if (nk > 2) issue(64, 2);

    for (int i = 0; i < nk; i++) {
        const int buf = i & 3;

        // entering iter i: outstanding groups {i .. min(i+2, nk-1)}
        if (i + 3 <= nk) cp_wait<2>();
        else if (i + 2 == nk) cp_wait<1>();
        else cp_wait<0>();
        __syncthreads();   // single barrier per iteration

        const unsigned aT = sa_s + (unsigned)buf * GEMM_STAGE;
        const unsigned bT = sb_s + (unsigned)buf * GEMM_STAGE;

        #pragma unroll
        for (int kt = 0; kt < 2; kt++) {
            unsigned af[4][4], bf[4][2];
            #pragma unroll
            for (int mi = 0; mi < 4; mi++)
                ldsm_x4(af[mi][0], af[mi][1], af[mi][2], af[mi][3],
                        aT + (unsigned)((wm * 64 + mi * 16 + arow) * 80 + kt * 32 + ahi));
            #pragma unroll
            for (int nip = 0; nip < 2; nip++)
                ldsm_x4(bf[2 * nip][0], bf[2 * nip][1], bf[2 * nip + 1][0], bf[2 * nip + 1][1],
                        bT + (unsigned)((wn * 32 + nip * 16 + brow) * 80 + kt * 32 + bhi));
            #pragma unroll
            for (int mi = 0; mi < 4; mi++)
                #pragma unroll
                for (int ni = 0; ni < 4; ni++)
                    mma_f16(acc[mi][ni], af[mi], bf[ni]);
        }

        // issue chunk i+3 into buffer (i+3)&3 = (i-1)&3: all warps finished
        // reading it before the barrier at the top of this iteration.
        if (i + 3 < nk) issue((i + 3) * 32, (i + 3) & 3);
    }

    // ---- epilogue ----
    #pragma unroll
    for (int mi = 0; mi < 4; mi++) {
        int row1 = m0 + wm * 64 + mi * 16 + r4;
        int row2 = row1 + 8;
        #pragma unroll
        for (int ni = 0; ni < 4; ni++) {
            int colg = n0 + wn * 32 + ni * 8 + c * 2;
            float b0 = bias[colg], b1 = bias[colg + 1];
            float v00 = acc[mi][ni][0] + b0, v01 = acc[mi][ni][1] + b1;
            float v10 = acc[mi][ni][2] + b0, v11 = acc[mi][ni][3] + b1;
            if (ohalf) {
                __half* C = (__half*)Cv;
                if (row1 < M)
                    *reinterpret_cast<unsigned*>(C + (size_t)row1 * N + colg) =
                        packh2(oscale * v00, oscale * v01);
                if (row2 < M)
                    *reinterpret_cast<unsigned*>(C + (size_t)row2 * N + colg) =
                        packh2(oscale * v10, oscale * v11);
            } else {
                float* C = (float*)Cv;
                if (row1 < M)
                    *reinterpret_cast<float2*>(C + (size_t)row1 * N + colg) = make_float2(v00, v01);
                if (row2 < M)
                    *reinterpret_cast<float2*>(C + (size_t)row2 * N + colg) = make_float2(v10, v11);
            }
        }
    }
}

// ============================================================
// fa6: fp16 flash attention, ldmatrix frags, 4-stage cp.async,
// single sync/iter, QK fragment double-buffering
// CTA: 128 q rows, 8 warps, kv chunks of 64
// smem: K stages [4][16KB] then V stages [4][16KB] = 128KB
// ============================================================
#define NCHUNK 17
#define KTB 16384u
#define VTB 16384u
#define FA6_SMEM_BYTES (4 * (16384 + 16384))

__global__ __launch_bounds__(256, 1) void fa6_f16(
    const __half* __restrict__ Q, const __half* __restrict__ K,
    const __half* __restrict__ Vt, __half* __restrict__ O)
{
    extern __shared__ unsigned sm4[];

    const int tid  = threadIdx.x;
    const int lane = tid & 31;
    const int wid  = tid >> 5;
    const int r4   = lane >> 2;
    const int c    = lane & 3;
    const int q0   = blockIdx.x * 128;
    const int h    = blockIdx.y;
    const int b    = blockIdx.z;

    const unsigned sbase = (unsigned)__cvta_generic_to_shared(sm4);
    const unsigned k_s = sbase;                // [4][KTB]
    const unsigned v_s = sbase + 4 * KTB;      // [4][VTB]

    const __half* kb  = K + ((size_t)(b * SEQ_KV)) * D_E + h * D_HEAD;
    const __half* vtb = Vt + ((size_t)(b * N_HEADS + h)) * D_HEAD * SKV_PAD;

    const int lrow = (lane & 7) + ((lane & 16) ? 8 : 0);
    const int kbit = (lane & 8) ? 1 : 0;
    const int lx   = lane & 7;

    unsigned qf[8][4];
    {
        const unsigned* qb = reinterpret_cast<const unsigned*>(
            Q + ((size_t)(b * SEQ_Q + q0 + wid * 16)) * D_E + h * D_HEAD);
        #pragma unroll
        for (int kt = 0; kt < 8; kt++) {
            qf[kt][0] = __ldg(qb + (size_t)r4 * 512 + kt * 8 + c);
            qf[kt][1] = __ldg(qb + (size_t)(r4 + 8) * 512 + kt * 8 + c);
            qf[kt][2] = __ldg(qb + (size_t)r4 * 512 + kt * 8 + c + 4);
            qf[kt][3] = __ldg(qb + (size_t)(r4 + 8) * 512 + kt * 8 + c + 4);
        }
    }

    float oacc[16][4];
    #pragma unroll
    for (int nt = 0; nt < 16; nt++)
        #pragma unroll
        for (int e = 0; e < 4; e++) oacc[nt][e] = 0.0f;

    float row_m0 = -1e30f, row_m1 = -1e30f;
    float row_l0 = 0.0f,   row_l1 = 0.0f;

    auto issue_chunk = [&](int t, int buf) {
        const int kv0 = t * 64;
        #pragma unroll
        for (int i = 0; i < 4; i++) {
            int u = tid + i * 256;
            int kv = u >> 4, g = u & 15;
            int kvg = kv0 + kv;
            int sz = (kvg < SEQ_KV) ? 16 : 0;
            int kvc = (kvg < SEQ_KV) ? kvg : (SEQ_KV - 1);
            cp_async16(k_s + (unsigned)buf * KTB + (unsigned)(kv * 256 + ((g ^ (kv & 7)) << 4)),
                       kb + (size_t)kvc * D_E + g * 8, sz);
        }
        #pragma unroll
        for (int i = 0; i < 4; i++) {
            int u = tid + i * 256;
            int d = u >> 3, g = u & 7;
            cp_async16(v_s + (unsigned)buf * VTB + (unsigned)(d * 128 + ((g ^ (d & 7)) << 4)),
                       vtb + (size_t)d * SKV_PAD + kv0 + g * 8, 16);
        }
        cp_commit();
    };

    issue_chunk(0, 0);
    issue_chunk(1, 1);
    issue_chunk(2, 2);

    for (int t = 0; t < NCHUNK; t++) {
        const int kv0 = t * 64;
        const int buf = t & 3;

        if (t + 3 <= NCHUNK) cp_wait<2>();
        else if (t + 2 == NCHUNK) cp_wait<1>();
        else cp_wait<0>();
        __syncthreads();   // single barrier per chunk

        const unsigned kT = k_s + (unsigned)buf * KTB + lrow * 256;
        const unsigned vT = v_s + (unsigned)buf * VTB + lrow * 128;

        // ---- S = Q @ K^T, K-frags double-buffered ----
        float sacc[8][4];
        #pragma unroll
        for (int ni = 0; ni < 8; ni++)
            #pragma unroll
            for (int e = 0; e < 4; e++) sacc[ni][e] = 0.0f;

        unsigned kf[2][4][4];
        {
            const unsigned g0 = (unsigned)(((kbit) ^ lx) << 4);   // kt=0
            #pragma unroll
            for (int np = 0; np < 4; np++)
                ldsm_x4(kf[0][np][0], kf[0][np][1], kf[0][np][2], kf[0][np][3],
                        kT + np * 4096 + g0);
        }
        #pragma unroll
        for (int kt = 0; kt < 8; kt++) {
            const int cur = kt & 1;
            if (kt < 7) {
                const unsigned gn = (unsigned)(((2 * (kt + 1) + kbit) ^ lx) << 4);
                #pragma unroll
                for (int np = 0; np < 4; np++)
                    ldsm_x4(kf[cur ^ 1][np][0], kf[cur ^ 1][np][1],
                            kf[cur ^ 1][np][2], kf[cur ^ 1][np][3],
                            kT + np * 4096 + gn);
            }
            #pragma unroll
            for (int np = 0; np < 4; np++) {
                unsigned bfA[2] = {kf[cur][np][0], kf[cur][np][1]};
                unsigned bfB[2] = {kf[cur][np][2], kf[cur][np][3]};
                mma_f16(sacc[2 * np],     qf[kt], bfA);
                mma_f16(sacc[2 * np + 1], qf[kt], bfB);
            }
        }

        // ---- mask + register softmax ----
        float mx0 = -1e30f, mx1 = -1e30f;
        #pragma unroll
        for (int ni = 0; ni < 8; ni++) {
            int colg = kv0 + ni * 8 + c * 2;
            if (colg >= SEQ_KV) {
                sacc[ni][0] = -1e30f; sacc[ni][1] = -1e30f;
                sacc[ni][2] = -1e30f; sacc[ni][3] = -1e30f;
            }
            mx0 = fmaxf(mx0, fmaxf(sacc[ni][0], sacc[ni][1]));
            mx1 = fmaxf(mx1, fmaxf(sacc[ni][2], sacc[ni][3]));
        }
        mx0 = fmaxf(mx0, __shfl_xor_sync(0xffffffffu, mx0, 1));
        mx0 = fmaxf(mx0, __shfl_xor_sync(0xffffffffu, mx0, 2));
        mx1 = fmaxf(mx1, __shfl_xor_sync(0xffffffffu, mx1, 1));
        mx1 = fmaxf(mx1, __shfl_xor_sync(0xffffffffu, mx1, 2));

        float mnew0 = fmaxf(row_m0, mx0);
        float mnew1 = fmaxf(row_m1, mx1);
        float sc0 = fexp(row_m0 - mnew0);
        float sc1 = fexp(row_m1 - mnew1);
        row_m0 = mnew0; row_m1 = mnew1;

        float sum0 = 0.f, sum1 = 0.f;
        #pragma unroll
        for (int ni = 0; ni < 8; ni++) {
            sacc[ni][0] = fexp(sacc[ni][0] - mnew0);
            sacc[ni][1] = fexp(sacc[ni][1] - mnew0);
            sacc[ni][2] = fexp(sacc[ni][2] - mnew1);
            sacc[ni][3] = fexp(sacc[ni][3] - mnew1);
            sum0 += sacc[ni][0] + sacc[ni][1];
            sum1 += sacc[ni][2] + sacc[ni][3];
        }
        sum0 += __shfl_xor_sync(0xffffffffu, sum0, 1);
        sum0 += __shfl_xor_sync(0xffffffffu, sum0, 2);
        sum1 += __shfl_xor_sync(0xffffffffu, sum1, 1);
        sum1 += __shfl_xor_sync(0xffffffffu, sum1, 2);
        row_l0 = row_l0 * sc0 + sum0;
        row_l1 = row_l1 * sc1 + sum1;

        #pragma unroll
        for (int nt = 0; nt < 16; nt++) {
            oacc[nt][0] *= sc0; oacc[nt][1] *= sc0;
            oacc[nt][2] *= sc1; oacc[nt][3] *= sc1;
        }

        // ---- O += P @ V ----
        #pragma unroll
        for (int kt = 0; kt < 4; kt++) {
            unsigned pa[4];
            pa[0] = packh2(sacc[2 * kt][0],     sacc[2 * kt][1]);
            pa[1] = packh2(sacc[2 * kt][2],     sacc[2 * kt][3]);
            pa[2] = packh2(sacc[2 * kt + 1][0], sacc[2 * kt + 1][1]);
            pa[3] = packh2(sacc[2 * kt + 1][2], sacc[2 * kt + 1][3]);

            const unsigned goff = (unsigned)(((2 * kt + kbit) ^ lx) << 4);
            #pragma unroll
            for (int np = 0; np < 8; np++) {
                unsigned b0, b1, b2, b3;
                ldsm_x4(b0, b1, b2, b3, vT + np * 2048 + goff);
                unsigned bfA[2] = {b0, b1};
                unsigned bfB[2] = {b2, b3};
                mma_f16(oacc[2 * np],     pa, bfA);
                mma_f16(oacc[2 * np + 1], pa, bfB);
            }
        }

        // issue chunk t+3 into buffer (t+3)&3 = (t-1)&3 (safe: see gemm note)
        if (t + 3 < NCHUNK) issue_chunk(t + 3, (t + 3) & 3);
    }

    float inv0 = 1.0f / row_l0;
    float inv1 = 1.0f / row_l1;
    __half* ob = O + ((size_t)(b * SEQ_Q + q0 + wid * 16 + r4)) * D_E + h * D_HEAD;
    #pragma unroll
    for (int nt = 0; nt < 16; nt++) {
        int colg = nt * 8 + c * 2;
        *reinterpret_cast<unsigned*>(ob + colg) =
            packh2(oacc[nt][0] * inv0, oacc[nt][1] * inv0);
        *reinterpret_cast<unsigned*>(ob + (size_t)8 * D_E + colg) =
            packh2(oacc[nt][2] * inv1, oacc[nt][3] * inv1);
    }
}

// ============================================================
// launch
// ============================================================
extern "C" void kernel_launch(void* const* d_in, const int* in_sizes, int n_in,
                              void* d_out, int out_size)
{
    const float* x  = (const float*)d_in[0];
    const float* y  = (const float*)d_in[1];
    const float* Wq = (const float*)d_in[2];
    const float* bq = (const float*)d_in[3];
    const float* Wk = (const float*)d_in[4];
    const float* bk = (const float*)d_in[5];
    const float* Wv = (const float*)d_in[6];
    const float* bv = (const float*)d_in[7];
    const float* Wo = (const float*)d_in[8];
    const float* bo = (const float*)d_in[9];
    float* out = (float*)d_out;

    __half *hx, *hy, *hWq, *hWk, *hWv, *hWo, *pQ, *pK, *pV, *pVt, *pO;
    cudaGetSymbolAddress((void**)&hx,  g_hx);
    cudaGetSymbolAddress((void**)&hy,  g_hy);
    cudaGetSymbolAddress((void**)&hWq, g_hWq);
    cudaGetSymbolAddress((void**)&hWk, g_hWk);
    cudaGetSymbolAddress((void**)&hWv, g_hWv);
    cudaGetSymbolAddress((void**)&hWo, g_hWo);
    cudaGetSymbolAddress((void**)&pQ,  g_Q);
    cudaGetSymbolAddress((void**)&pK,  g_K);
    cudaGetSymbolAddress((void**)&pV,  g_V);
    cudaGetSymbolAddress((void**)&pVt, g_Vt);
    cudaGetSymbolAddress((void**)&pO,  g_O);

    const float qscale = 0.08838834764831845f;  // 1/sqrt(128)

    // launch 0: all fp32->fp16 conversions
    cvt_all<<<(C_N4 + 255) / 256, 256>>>(x, y, Wq, Wk, Wv, Wo,
                                         hx, hy, hWq, hWk, hWv, hWo);

    cudaFuncSetAttribute(gemm_f16, cudaFuncAttributeMaxDynamicSharedMemorySize, GEMM_SMEM);

    // launch 1: Q projection (fp16 out, pre-scaled)
    gemm_f16<<<dim3(8, (MQ + 127) / 128), 256, GEMM_SMEM>>>(
        hx, hWq, bq, pQ, nullptr, nullptr, nullptr, 8, MQ, D_E, D_E, qscale, 1);
    // launch 2: K and V projections fused
    gemm_f16<<<dim3(16, (MKV + 127) / 128), 256, GEMM_SMEM>>>(
        hy, hWk, bk, pK, hWv, bv, pV, 8, MKV, D_E, D_C, 1.0f, 1);

    // launch 3: V transpose
    transpose_v<<<dim3(SKV_PAD / 32, D_HEAD / 32, BATCH * N_HEADS), dim3(32, 8)>>>(pV, pVt);

    // launch 4: attention
    cudaFuncSetAttribute(fa6_f16, cudaFuncAttributeMaxDynamicSharedMemorySize, FA6_SMEM_BYTES);
    fa6_f16<<<dim3(SEQ_Q / 128, N_HEADS, BATCH), 256, FA6_SMEM_BYTES>>>(pQ, pK, pVt, pO);

    // launch 5: output projection -> d_out (fp32)
    gemm_f16<<<dim3(8, (MQ + 127) / 128), 256, GEMM_SMEM>>>(
        pO, hWo, bo, out, nullptr, nullptr, nullptr, 8, MQ, D_E, D_E, 1.0f, 0);
}

// round 13
// speedup vs baseline: 8.8762x; 1.0893x over previous
#include <cuda_runtime.h>
#include <cuda_fp16.h>
#include <math.h>

// ---------------- problem constants ----------------
#define BATCH   4
#define SEQ_Q   3072
#define SEQ_KV  1036
#define D_E     1024
#define D_C     768
#define N_HEADS 8
#define D_HEAD  128

#define MQ (BATCH * SEQ_Q)    // 12288
#define MKV (BATCH * SEQ_KV)  // 4144
#define SKV_PAD 1088

// ---------------- scratch ----------------
__device__ __half g_hx[(size_t)MQ * D_E];
__device__ __half g_hy[(size_t)MKV * D_C];
__device__ __half g_hWq[(size_t)D_E * D_E];
__device__ __half g_hWk[(size_t)D_E * D_C];
__device__ __half g_hWv[(size_t)D_E * D_C];
__device__ __half g_hWo[(size_t)D_E * D_E];
__device__ __half g_Q[(size_t)MQ * D_E];
__device__ __half g_K[(size_t)MKV * D_E];
__device__ __half g_V[(size_t)MKV * D_E];
__device__ __half g_Vt[(size_t)BATCH * N_HEADS * D_HEAD * SKV_PAD];
__device__ __half g_O[(size_t)MQ * D_E];

// ---------------- helpers ----------------
__device__ __forceinline__ unsigned packh2(float lo, float hi) {
    __half2 h = __floats2half2_rn(lo, hi);
    return *reinterpret_cast<unsigned*>(&h);
}

__device__ __forceinline__ void mma_f16(float d[4], const unsigned a[4], const unsigned b[2]) {
    asm volatile(
        "mma.sync.aligned.m16n8k16.row.col.f32.f16.f16.f32 "
        "{%0,%1,%2,%3}, {%4,%5,%6,%7}, {%8,%9}, {%0,%1,%2,%3};\n"
        : "+f"(d[0]), "+f"(d[1]), "+f"(d[2]), "+f"(d[3])
        : "r"(a[0]), "r"(a[1]), "r"(a[2]), "r"(a[3]),
          "r"(b[0]), "r"(b[1]));
}

__device__ __forceinline__ void ldsm_x4(unsigned& r0, unsigned& r1, unsigned& r2, unsigned& r3,
                                        unsigned saddr) {
    asm volatile("ldmatrix.sync.aligned.m8n8.x4.shared.b16 {%0,%1,%2,%3}, [%4];"
                 : "=r"(r0), "=r"(r1), "=r"(r2), "=r"(r3) : "r"(saddr));
}

__device__ __forceinline__ float fexp(float x) {
    x = fmaxf(x, -87.0f);
    float xl = x * 1.4426950408889634f;
    float y  = xl + 12582912.0f;
    int   n  = __float_as_int(y) - 0x4B400000;
    float f  = xl - (y - 12582912.0f);
    float p  = 1.33335581e-3f;
    p = fmaf(p, f, 9.61812911e-3f);
    p = fmaf(p, f, 5.55041087e-2f);
    p = fmaf(p, f, 2.40226507e-1f);
    p = fmaf(p, f, 6.93147182e-1f);
    p = fmaf(p, f, 1.0f);
    return __int_as_float(__float_as_int(p) + (n << 23));
}

__device__ __forceinline__ void cp_async16(unsigned dst, const void* src, int src_bytes) {
    asm volatile("cp.async.cg.shared.global [%0], [%1], 16, %2;"
                 :: "r"(dst), "l"(src), "r"(src_bytes));
}
__device__ __forceinline__ void cp_commit() { asm volatile("cp.async.commit_group;"); }
template<int N>
__device__ __forceinline__ void cp_wait() { asm volatile("cp.async.wait_group %0;" :: "n"(N)); }

// ============================================================
// fp32 -> fp16 conversion: all 6 tensors in ONE launch (segmented)
// ============================================================
#define C_NX 3145728   // x: 12288*1024/4
#define C_N0 (C_NX + 795648)    // +y 4144*768/4
#define C_N1 (C_N0 + 262144)    // +Wq
#define C_N2 (C_N1 + 196608)    // +Wk
#define C_N3 (C_N2 + 196608)    // +Wv
#define C_N4 (C_N3 + 262144)    // +Wo

__global__ __launch_bounds__(256) void cvt_all(
    const float* __restrict__ x,  const float* __restrict__ y,
    const float* __restrict__ wq, const float* __restrict__ wk,
    const float* __restrict__ wv, const float* __restrict__ wo,
    __half* hx, __half* hy, __half* hwq, __half* hwk, __half* hwv, __half* hwo)
{
    int i = blockIdx.x * 256 + threadIdx.x;
    const float* src; __half* dst; int j;
    if      (i < C_NX) { src = x;  dst = hx;  j = i; }
    else if (i < C_N0) { src = y;  dst = hy;  j = i - C_NX; }
    else if (i < C_N1) { src = wq; dst = hwq; j = i - C_N0; }
    else if (i < C_N2) { src = wk; dst = hwk; j = i - C_N1; }
    else if (i < C_N3) { src = wv; dst = hwv; j = i - C_N2; }
    else if (i < C_N4) { src = wo; dst = hwo; j = i - C_N3; }
    else return;
    float4 v = *reinterpret_cast<const float4*>(src + (size_t)j * 4);
    __half2* o = reinterpret_cast<__half2*>(dst + (size_t)j * 4);
    o[0] = __floats2half2_rn(v.x, v.y);
    o[1] = __floats2half2_rn(v.z, v.w);
}

// ============================================================
// V transpose: g_V [MKV][D_E] -> g_Vt [B*H][128][SKV_PAD]
// ============================================================
__global__ __launch_bounds__(256) void transpose_v(const __half* __restrict__ V,
                                                   __half* __restrict__ Vt)
{
    __shared__ __half t[32][33];
    const int tx = threadIdx.x;
    const int ty = threadIdx.y;
    const int kv0 = blockIdx.x * 32;
    const int d0  = blockIdx.y * 32;
    const int bh  = blockIdx.z;
    const int b   = bh >> 3, h = bh & 7;

    #pragma unroll
    for (int j = 0; j < 4; j++) {
        int kvL = ty * 4 + j;
        int kv  = kv0 + kvL;
        __half v = __float2half(0.0f);
        if (kv < SEQ_KV)
            v = V[(size_t)(b * SEQ_KV + kv) * D_E + h * D_HEAD + d0 + tx];
        t[kvL][tx] = v;
    }
    __syncthreads();
    #pragma unroll
    for (int j = 0; j < 4; j++) {
        int dL = ty * 4 + j;
        Vt[((size_t)bh * D_HEAD + d0 + dL) * SKV_PAD + kv0 + tx] = t[tx][dL];
    }
}

// ============================================================
// fp16 tensor-core GEMM (dual-output capable):
// block 128x128x64(half), 3-stage cp.async pipeline, 1 sync/iter,
// ldmatrix frags, XOR-16B swizzled 128B rows.
// smem: sA[3][16KB] then sB[3][16KB] = 96KB, 2 CTAs/SM
// ============================================================
#define GSTG 16384u
#define GEMM_SMEM (6 * 16384)

__global__ __launch_bounds__(256, 2) void gemm_f16(
    const __half* __restrict__ A,
    const __half* __restrict__ W,  const float* __restrict__ bias,  void* Cv,
    const __half* __restrict__ W2, const float* __restrict__ bias2, void* Cv2,
    int nx, int M, int N, int K, float oscale, int ohalf)
{
    extern __shared__ __half gsm[];

    const int tid  = threadIdx.x;
    const int lane = tid & 31;
    const int wid  = tid >> 5;
    const int wm   = wid >> 2;
    const int wn   = wid & 3;
    const int r4   = lane >> 2;
    const int c    = lane & 3;
    const int m0   = blockIdx.y * 128;

    int bx = blockIdx.x;
    if (bx >= nx) { W = W2; bias = bias2; Cv = Cv2; bx -= nx; }
    const int n0 = bx * 128;

    const unsigned sa_s = (unsigned)__cvta_generic_to_shared(gsm);
    const unsigned sb_s = sa_s + 3 * GSTG;

    float acc[4][4][4];
    #pragma unroll
    for (int i = 0; i < 4; i++)
        #pragma unroll
        for (int j = 0; j < 4; j++)
            #pragma unroll
            for (int e = 0; e < 4; e++) acc[i][j][e] = 0.0f;

    // chunk = 64 halfs (128B/row). 128 rows x 8 groups of 16B, swizzle g^(row&7).
    auto issue = [&](int ch, int buf) {
        const int k0 = ch * 64;
        #pragma unroll
        for (int i = 0; i < 4; i++) {
            int u = tid + i * 256;           // 1024 slots
            int row = u >> 3, g = u & 7;
            int gr = m0 + row;
            int sz = (gr < M) ? 16 : 0;
            int grc = (gr < M) ? gr : (M - 1);
            cp_async16(sa_s + (unsigned)buf * GSTG + (unsigned)(row * 128 + ((g ^ (row & 7)) << 4)),
                       A + (size_t)grc * K + k0 + g * 8, sz);
        }
        #pragma unroll
        for (int i = 0; i < 4; i++) {
            int u = tid + i * 256;
            int row = u >> 3, g = u & 7;
            cp_async16(sb_s + (unsigned)buf * GSTG + (unsigned)(row * 128 + ((g ^ (row & 7)) << 4)),
                       W + (size_t)(n0 + row) * K + k0 + g * 8, 16);
        }
        cp_commit();
    };

    // ldmatrix lane roles
    const int arow = (lane & 7) + (lane & 8);              // row within 16
    const int ahib = (lane & 16) ? 1 : 0;                  // k-half select
    const int brow = (lane & 7) + ((lane & 16) ? 8 : 0);
    const int bhib = (lane & 8) ? 1 : 0;
    const int l7   = lane & 7;

    const int nk = K >> 6;   // 16 or 12
    issue(0, 0);
    if (nk > 1) issue(1, 1);

    for (int i = 0; i < nk; i++) {
        const int buf = i % 3;
        if (i + 1 < nk) cp_wait<1>(); else cp_wait<0>();
        __syncthreads();   // single barrier per iteration

        const unsigned aT = sa_s + (unsigned)buf * GSTG;
        const unsigned bT = sb_s + (unsigned)buf * GSTG;

        #pragma unroll
        for (int kt = 0; kt < 4; kt++) {
            unsigned af[4][4], bf[4][2];
            const unsigned ga = (unsigned)(((2 * kt + ahib) ^ l7) << 4);
            const unsigned gb = (unsigned)(((2 * kt + bhib) ^ l7) << 4);
            #pragma unroll
            for (int mi = 0; mi < 4; mi++)
                ldsm_x4(af[mi][0], af[mi][1], af[mi][2], af[mi][3],
                        aT + (unsigned)((wm * 64 + mi * 16 + arow) * 128) + ga);
            #pragma unroll
            for (int nip = 0; nip < 2; nip++)
                ldsm_x4(bf[2 * nip][0], bf[2 * nip][1], bf[2 * nip + 1][0], bf[2 * nip + 1][1],
                        bT + (unsigned)((wn * 32 + nip * 16 + brow) * 128) + gb);
            #pragma unroll
            for (int mi = 0; mi < 4; mi++)
                #pragma unroll
                for (int ni = 0; ni < 4; ni++)
                    mma_f16(acc[mi][ni], af[mi], bf[ni]);
        }

        // chunk i+2 -> buf (i+2)%3 = (i-1)%3: consumed at iter i-1,
        // all warps passed this iteration's barrier => safe to overwrite.
        if (i + 2 < nk) issue(i + 2, (i + 2) % 3);
    }

    // ---- epilogue ----
    #pragma unroll
    for (int mi = 0; mi < 4; mi++) {
        int row1 = m0 + wm * 64 + mi * 16 + r4;
        int row2 = row1 + 8;
        #pragma unroll
        for (int ni = 0; ni < 4; ni++) {
            int colg = n0 + wn * 32 + ni * 8 + c * 2;
            float b0 = bias[colg], b1 = bias[colg + 1];
            float v00 = acc[mi][ni][0] + b0, v01 = acc[mi][ni][1] + b1;
            float v10 = acc[mi][ni][2] + b0, v11 = acc[mi][ni][3] + b1;
            if (ohalf) {
                __half* C = (__half*)Cv;
                if (row1 < M)
                    *reinterpret_cast<unsigned*>(C + (size_t)row1 * N + colg) =
                        packh2(oscale * v00, oscale * v01);
                if (row2 < M)
                    *reinterpret_cast<unsigned*>(C + (size_t)row2 * N + colg) =
                        packh2(oscale * v10, oscale * v11);
            } else {
                float* C = (float*)Cv;
                if (row1 < M)
                    *reinterpret_cast<float2*>(C + (size_t)row1 * N + colg) = make_float2(v00, v01);
                if (row2 < M)
                    *reinterpret_cast<float2*>(C + (size_t)row2 * N + colg) = make_float2(v10, v11);
            }
        }
    }
}

// ============================================================
// fa6: fp16 flash attention, ldmatrix frags, 4-stage cp.async,
// single sync/iter, QK fragment double-buffering, OOB mask hoisted
// CTA: 128 q rows, 8 warps, kv chunks of 64; smem 128KB
// ============================================================
#define NCHUNK 17
#define KTB 16384u
#define VTB 16384u
#define FA6_SMEM_BYTES (4 * (16384 + 16384))

__global__ __launch_bounds__(256, 1) void fa6_f16(
    const __half* __restrict__ Q, const __half* __restrict__ K,
    const __half* __restrict__ Vt, __half* __restrict__ O)
{
    extern __shared__ unsigned sm4[];

    const int tid  = threadIdx.x;
    const int lane = tid & 31;
    const int wid  = tid >> 5;
    const int r4   = lane >> 2;
    const int c    = lane & 3;
    const int q0   = blockIdx.x * 128;
    const int h    = blockIdx.y;
    const int b    = blockIdx.z;

    const unsigned sbase = (unsigned)__cvta_generic_to_shared(sm4);
    const unsigned k_s = sbase;
    const unsigned v_s = sbase + 4 * KTB;

    const __half* kb  = K + ((size_t)(b * SEQ_KV)) * D_E + h * D_HEAD;
    const __half* vtb = Vt + ((size_t)(b * N_HEADS + h)) * D_HEAD * SKV_PAD;

    const int lrow = (lane & 7) + ((lane & 16) ? 8 : 0);
    const int kbit = (lane & 8) ? 1 : 0;
    const int lx   = lane & 7;

    unsigned qf[8][4];
    {
        const unsigned* qb = reinterpret_cast<const unsigned*>(
            Q + ((size_t)(b * SEQ_Q + q0 + wid * 16)) * D_E + h * D_HEAD);
        #pragma unroll
        for (int kt = 0; kt < 8; kt++) {
            qf[kt][0] = __ldg(qb + (size_t)r4 * 512 + kt * 8 + c);
            qf[kt][1] = __ldg(qb + (size_t)(r4 + 8) * 512 + kt * 8 + c);
            qf[kt][2] = __ldg(qb + (size_t)r4 * 512 + kt * 8 + c + 4);
            qf[kt][3] = __ldg(qb + (size_t)(r4 + 8) * 512 + kt * 8 + c + 4);
        }
    }

    float oacc[16][4];
    #pragma unroll
    for (int nt = 0; nt < 16; nt++)
        #pragma unroll
        for (int e = 0; e < 4; e++) oacc[nt][e] = 0.0f;

    float row_m0 = -1e30f, row_m1 = -1e30f;
    float row_l0 = 0.0f,   row_l1 = 0.0f;

    auto issue_chunk = [&](int t, int buf) {
        const int kv0 = t * 64;
        #pragma unroll
        for (int i = 0; i < 4; i++) {
            int u = tid + i * 256;
            int kv = u >> 4, g = u & 15;
            int kvg = kv0 + kv;
            int sz = (kvg < SEQ_KV) ? 16 : 0;
            int kvc = (kvg < SEQ_KV) ? kvg : (SEQ_KV - 1);
            cp_async16(k_s + (unsigned)buf * KTB + (unsigned)(kv * 256 + ((g ^ (kv & 7)) << 4)),
                       kb + (size_t)kvc * D_E + g * 8, sz);
        }
        #pragma unroll
        for (int i = 0; i < 4; i++) {
            int u = tid + i * 256;
            int d = u >> 3, g = u & 7;
            cp_async16(v_s + (unsigned)buf * VTB + (unsigned)(d * 128 + ((g ^ (d & 7)) << 4)),
                       vtb + (size_t)d * SKV_PAD + kv0 + g * 8, 16);
        }
        cp_commit();
    };

    issue_chunk(0, 0);
    issue_chunk(1, 1);
    issue_chunk(2, 2);

    for (int t = 0; t < NCHUNK; t++) {
        const int kv0 = t * 64;
        const int buf = t & 3;

        if (t + 3 <= NCHUNK) cp_wait<2>();
        else if (t + 2 == NCHUNK) cp_wait<1>();
        else cp_wait<0>();
        __syncthreads();

        const unsigned kT = k_s + (unsigned)buf * KTB + lrow * 256;
        const unsigned vT = v_s + (unsigned)buf * VTB + lrow * 128;

        // ---- S = Q @ K^T, K-frags double-buffered ----
        float sacc[8][4];
        #pragma unroll
        for (int ni = 0; ni < 8; ni++)
            #pragma unroll
            for (int e = 0; e < 4; e++) sacc[ni][e] = 0.0f;

        unsigned kf[2][4][4];
        {
            const unsigned g0 = (unsigned)(((kbit) ^ lx) << 4);
            #pragma unroll
            for (int np = 0; np < 4; np++)
                ldsm_x4(kf[0][np][0], kf[0][np][1], kf[0][np][2], kf[0][np][3],
                        kT + np * 4096 + g0);
        }
        #pragma unroll
        for (int kt = 0; kt < 8; kt++) {
            const int cur = kt & 1;
            if (kt < 7) {
                const unsigned gn = (unsigned)(((2 * (kt + 1) + kbit) ^ lx) << 4);
                #pragma unroll
                for (int np = 0; np < 4; np++)
                    ldsm_x4(kf[cur ^ 1][np][0], kf[cur ^ 1][np][1],
                            kf[cur ^ 1][np][2], kf[cur ^ 1][np][3],
                            kT + np * 4096 + gn);
            }
            #pragma unroll
            for (int np = 0; np < 4; np++) {
                unsigned bfA[2] = {kf[cur][np][0], kf[cur][np][1]};
                unsigned bfB[2] = {kf[cur][np][2], kf[cur][np][3]};
                mma_f16(sacc[2 * np],     qf[kt], bfA);
                mma_f16(sacc[2 * np + 1], qf[kt], bfB);
            }
        }

        // ---- softmax (OOB mask only on the final partial chunk) ----
        float mx0 = -1e30f, mx1 = -1e30f;
        if (t == NCHUNK - 1) {
            #pragma unroll
            for (int ni = 0; ni < 8; ni++) {
                int colg = kv0 + ni * 8 + c * 2;
                if (colg >= SEQ_KV) {
                    sacc[ni][0] = -1e30f; sacc[ni][1] = -1e30f;
                    sacc[ni][2] = -1e30f; sacc[ni][3] = -1e30f;
                }
                mx0 = fmaxf(mx0, fmaxf(sacc[ni][0], sacc[ni][1]));
                mx1 = fmaxf(mx1, fmaxf(sacc[ni][2], sacc[ni][3]));
            }
        } else {
            #pragma unroll
            for (int ni = 0; ni < 8; ni++) {
                mx0 = fmaxf(mx0, fmaxf(sacc[ni][0], sacc[ni][1]));
                mx1 = fmaxf(mx1, fmaxf(sacc[ni][2], sacc[ni][3]));
            }
        }
        mx0 = fmaxf(mx0, __shfl_xor_sync(0xffffffffu, mx0, 1));
        mx0 = fmaxf(mx0, __shfl_xor_sync(0xffffffffu, mx0, 2));
        mx1 = fmaxf(mx1, __shfl_xor_sync(0xffffffffu, mx1, 1));
        mx1 = fmaxf(mx1, __shfl_xor_sync(0xffffffffu, mx1, 2));

        float mnew0 = fmaxf(row_m0, mx0);
        float mnew1 = fmaxf(row_m1, mx1);
        float sc0 = fexp(row_m0 - mnew0);
        float sc1 = fexp(row_m1 - mnew1);
        row_m0 = mnew0; row_m1 = mnew1;

        float sum0 = 0.f, sum1 = 0.f;
        #pragma unroll
        for (int ni = 0; ni < 8; ni++) {
            sacc[ni][0] = fexp(sacc[ni][0] - mnew0);
            sacc[ni][1] = fexp(sacc[ni][1] - mnew0);
            sacc[ni][2] = fexp(sacc[ni][2] - mnew1);
            sacc[ni][3] = fexp(sacc[ni][3] - mnew1);
            sum0 += sacc[ni][0] + sacc[ni][1];
            sum1 += sacc[ni][2] + sacc[ni][3];
        }
        sum0 += __shfl_xor_sync(0xffffffffu, sum0, 1);
        sum0 += __shfl_xor_sync(0xffffffffu, sum0, 2);
        sum1 += __shfl_xor_sync(0xffffffffu, sum1, 1);
        sum1 += __shfl_xor_sync(0xffffffffu, sum1, 2);
        row_l0 = row_l0 * sc0 + sum0;
        row_l1 = row_l1 * sc1 + sum1;

        #pragma unroll
        for (int nt = 0; nt < 16; nt++) {
            oacc[nt][0] *= sc0; oacc[nt][1] *= sc0;
            oacc[nt][2] *= sc1; oacc[nt][3] *= sc1;
        }

        // ---- O += P @ V ----
        #pragma unroll
        for (int kt = 0; kt < 4; kt++) {
            unsigned pa[4];
            pa[0] = packh2(sacc[2 * kt][0],     sacc[2 * kt][1]);
            pa[1] = packh2(sacc[2 * kt][2],     sacc[2 * kt][3]);
            pa[2] = packh2(sacc[2 * kt + 1][0], sacc[2 * kt + 1][1]);
            pa[3] = packh2(sacc[2 * kt + 1][2], sacc[2 * kt + 1][3]);

            const unsigned goff = (unsigned)(((2 * kt + kbit) ^ lx) << 4);
            #pragma unroll
            for (int np = 0; np < 8; np++) {
                unsigned b0, b1, b2, b3;
                ldsm_x4(b0, b1, b2, b3, vT + np * 2048 + goff);
                unsigned bfA[2] = {b0, b1};
                unsigned bfB[2] = {b2, b3};
                mma_f16(oacc[2 * np],     pa, bfA);
                mma_f16(oacc[2 * np + 1], pa, bfB);
            }
        }

        if (t + 3 < NCHUNK) issue_chunk(t + 3, (t + 3) & 3);
    }

    float inv0 = 1.0f / row_l0;
    float inv1 = 1.0f / row_l1;
    __half* ob = O + ((size_t)(b * SEQ_Q + q0 + wid * 16 + r4)) * D_E + h * D_HEAD;
    #pragma unroll
    for (int nt = 0; nt < 16; nt++) {
        int colg = nt * 8 + c * 2;
        *reinterpret_cast<unsigned*>(ob + colg) =
            packh2(oacc[nt][0] * inv0, oacc[nt][1] * inv0);
        *reinterpret_cast<unsigned*>(ob + (size_t)8 * D_E + colg) =
            packh2(oacc[nt][2] * inv1, oacc[nt][3] * inv1);
    }
}

// ============================================================
// launch
// ============================================================
extern "C" void kernel_launch(void* const* d_in, const int* in_sizes, int n_in,
                              void* d_out, int out_size)
{
    const float* x  = (const float*)d_in[0];
    const float* y  = (const float*)d_in[1];
    const float* Wq = (const float*)d_in[2];
    const float* bq = (const float*)d_in[3];
    const float* Wk = (const float*)d_in[4];
    const float* bk = (const float*)d_in[5];
    const float* Wv = (const float*)d_in[6];
    const float* bv = (const float*)d_in[7];
    const float* Wo = (const float*)d_in[8];
    const float* bo = (const float*)d_in[9];
    float* out = (float*)d_out;

    __half *hx, *hy, *hWq, *hWk, *hWv, *hWo, *pQ, *pK, *pV, *pVt, *pO;
    cudaGetSymbolAddress((void**)&hx,  g_hx);
    cudaGetSymbolAddress((void**)&hy,  g_hy);
    cudaGetSymbolAddress((void**)&hWq, g_hWq);
    cudaGetSymbolAddress((void**)&hWk, g_hWk);
    cudaGetSymbolAddress((void**)&hWv, g_hWv);
    cudaGetSymbolAddress((void**)&hWo, g_hWo);
    cudaGetSymbolAddress((void**)&pQ,  g_Q);
    cudaGetSymbolAddress((void**)&pK,  g_K);
    cudaGetSymbolAddress((void**)&pV,  g_V);
    cudaGetSymbolAddress((void**)&pVt, g_Vt);
    cudaGetSymbolAddress((void**)&pO,  g_O);

    const float qscale = 0.08838834764831845f;  // 1/sqrt(128)

    // launch 0: all fp32->fp16 conversions
    cvt_all<<<(C_N4 + 255) / 256, 256>>>(x, y, Wq, Wk, Wv, Wo,
                                         hx, hy, hWq, hWk, hWv, hWo);

    cudaFuncSetAttribute(gemm_f16, cudaFuncAttributeMaxDynamicSharedMemorySize, GEMM_SMEM);

    // launch 1: Q projection (fp16 out, pre-scaled)
    gemm_f16<<<dim3(8, (MQ + 127) / 128), 256, GEMM_SMEM>>>(
        hx, hWq, bq, pQ, nullptr, nullptr, nullptr, 8, MQ, D_E, D_E, qscale, 1);
    // launch 2: K and V projections fused
    gemm_f16<<<dim3(16, (MKV + 127) / 128), 256, GEMM_SMEM>>>(
        hy, hWk, bk, pK, hWv, bv, pV, 8, MKV, D_E, D_C, 1.0f, 1);

    // launch 3: V transpose
    transpose_v<<<dim3(SKV_PAD / 32, D_HEAD / 32, BATCH * N_HEADS), dim3(32, 8)>>>(pV, pVt);

    // launch 4: attention
    cudaFuncSetAttribute(fa6_f16, cudaFuncAttributeMaxDynamicSharedMemorySize, FA6_SMEM_BYTES);
    fa6_f16<<<dim3(SEQ_Q / 128, N_HEADS, BATCH), 256, FA6_SMEM_BYTES>>>(pQ, pK, pVt, pO);

    // launch 5: output projection -> d_out (fp32)
    gemm_f16<<<dim3(8, (MQ + 127) / 128), 256, GEMM_SMEM>>>(
        pO, hWo, bo, out, nullptr, nullptr, nullptr, 8, MQ, D_E, D_E, 1.0f, 0);
}

// round 14
// speedup vs baseline: 9.1649x; 1.0325x over previous
#include <cuda_runtime.h>
#include <cuda_fp16.h>
#include <math.h>

// ---------------- problem constants ----------------
#define BATCH   4
#define SEQ_Q   3072
#define SEQ_KV  1036
#define D_E     1024
#define D_C     768
#define N_HEADS 8
#define D_HEAD  128

#define MQ (BATCH * SEQ_Q)    // 12288
#define MKV (BATCH * SEQ_KV)  // 4144
#define SKV_PAD 1088

// ---------------- scratch ----------------
__device__ __half g_hx[(size_t)MQ * D_E];
__device__ __half g_hy[(size_t)MKV * D_C];
__device__ __half g_hWq[(size_t)D_E * D_E];
__device__ __half g_hWk[(size_t)D_E * D_C];
__device__ __half g_hWv[(size_t)D_E * D_C];
__device__ __half g_hWo[(size_t)D_E * D_E];
__device__ __half g_Q[(size_t)MQ * D_E];
__device__ __half g_K[(size_t)MKV * D_E];
__device__ __half g_V[(size_t)MKV * D_E];
__device__ __half g_Vt[(size_t)BATCH * N_HEADS * D_HEAD * SKV_PAD];
__device__ __half g_O[(size_t)MQ * D_E];

// ---------------- helpers ----------------
__device__ __forceinline__ unsigned packh2(float lo, float hi) {
    __half2 h = __floats2half2_rn(lo, hi);
    return *reinterpret_cast<unsigned*>(&h);
}

__device__ __forceinline__ void mma_f16(float d[4], const unsigned a[4], const unsigned b[2]) {
    asm volatile(
        "mma.sync.aligned.m16n8k16.row.col.f32.f16.f16.f32 "
        "{%0,%1,%2,%3}, {%4,%5,%6,%7}, {%8,%9}, {%0,%1,%2,%3};\n"
        : "+f"(d[0]), "+f"(d[1]), "+f"(d[2]), "+f"(d[3])
        : "r"(a[0]), "r"(a[1]), "r"(a[2]), "r"(a[3]),
          "r"(b[0]), "r"(b[1]));
}

__device__ __forceinline__ void ldsm_x4(unsigned& r0, unsigned& r1, unsigned& r2, unsigned& r3,
                                        unsigned saddr) {
    asm volatile("ldmatrix.sync.aligned.m8n8.x4.shared.b16 {%0,%1,%2,%3}, [%4];"
                 : "=r"(r0), "=r"(r1), "=r"(r2), "=r"(r3) : "r"(saddr));
}

__device__ __forceinline__ float fexp(float x) {
    x = fmaxf(x, -87.0f);
    float xl = x * 1.4426950408889634f;
    float y  = xl + 12582912.0f;
    int   n  = __float_as_int(y) - 0x4B400000;
    float f  = xl - (y - 12582912.0f);
    float p  = 1.33335581e-3f;
    p = fmaf(p, f, 9.61812911e-3f);
    p = fmaf(p, f, 5.55041087e-2f);
    p = fmaf(p, f, 2.40226507e-1f);
    p = fmaf(p, f, 6.93147182e-1f);
    p = fmaf(p, f, 1.0f);
    return __int_as_float(__float_as_int(p) + (n << 23));
}

__device__ __forceinline__ void cp_async16(unsigned dst, const void* src, int src_bytes) {
    asm volatile("cp.async.cg.shared.global [%0], [%1], 16, %2;"
                 :: "r"(dst), "l"(src), "r"(src_bytes));
}
__device__ __forceinline__ void cp_commit() { asm volatile("cp.async.commit_group;"); }
template<int N>
__device__ __forceinline__ void cp_wait() { asm volatile("cp.async.wait_group %0;" :: "n"(N)); }

// ============================================================
// fp32 -> fp16 conversion: all 6 tensors in ONE launch (segmented)
// ============================================================
#define C_NX 3145728
#define C_N0 (C_NX + 795648)
#define C_N1 (C_N0 + 262144)
#define C_N2 (C_N1 + 196608)
#define C_N3 (C_N2 + 196608)
#define C_N4 (C_N3 + 262144)

__global__ __launch_bounds__(256) void cvt_all(
    const float* __restrict__ x,  const float* __restrict__ y,
    const float* __restrict__ wq, const float* __restrict__ wk,
    const float* __restrict__ wv, const float* __restrict__ wo,
    __half* hx, __half* hy, __half* hwq, __half* hwk, __half* hwv, __half* hwo)
{
    int i = blockIdx.x * 256 + threadIdx.x;
    const float* src; __half* dst; int j;
    if      (i < C_NX) { src = x;  dst = hx;  j = i; }
    else if (i < C_N0) { src = y;  dst = hy;  j = i - C_NX; }
    else if (i < C_N1) { src = wq; dst = hwq; j = i - C_N0; }
    else if (i < C_N2) { src = wk; dst = hwk; j = i - C_N1; }
    else if (i < C_N3) { src = wv; dst = hwv; j = i - C_N2; }
    else if (i < C_N4) { src = wo; dst = hwo; j = i - C_N3; }
    else return;
    float4 v = *reinterpret_cast<const float4*>(src + (size_t)j * 4);
    __half2* o = reinterpret_cast<__half2*>(dst + (size_t)j * 4);
    o[0] = __floats2half2_rn(v.x, v.y);
    o[1] = __floats2half2_rn(v.z, v.w);
}

// ============================================================
// V transpose: g_V [MKV][D_E] -> g_Vt [B*H][128][SKV_PAD]
// ============================================================
__global__ __launch_bounds__(256) void transpose_v(const __half* __restrict__ V,
                                                   __half* __restrict__ Vt)
{
    __shared__ __half t[32][33];
    const int tx = threadIdx.x;
    const int ty = threadIdx.y;
    const int kv0 = blockIdx.x * 32;
    const int d0  = blockIdx.y * 32;
    const int bh  = blockIdx.z;
    const int b   = bh >> 3, h = bh & 7;

    #pragma unroll
    for (int j = 0; j < 4; j++) {
        int kvL = ty * 4 + j;
        int kv  = kv0 + kvL;
        __half v = __float2half(0.0f);
        if (kv < SEQ_KV)
            v = V[(size_t)(b * SEQ_KV + kv) * D_E + h * D_HEAD + d0 + tx];
        t[kvL][tx] = v;
    }
    __syncthreads();
    #pragma unroll
    for (int j = 0; j < 4; j++) {
        int dL = ty * 4 + j;
        Vt[((size_t)bh * D_HEAD + d0 + dL) * SKV_PAD + kv0 + tx] = t[tx][dL];
    }
}

// ============================================================
// fp16 tensor-core GEMM, up to 3 independent segments per launch.
// Segment s: C = A @ W^T + bias  (per-seg M, K, oscale, ohalf)
// block 128x128x64(half), 3-stage cp.async, 1 sync/iter,
// ldmatrix frags + B-fragment double buffering.
// smem: sA[3][16KB] then sB[3][16KB] = 96KB, 2 CTAs/SM
// ============================================================
struct Seg {
    const __half* A;
    const __half* W;
    const float*  bias;
    void*         C;
    int M, K, ohalf;
    float oscale;
};

#define GSTG 16384u
#define GEMM_SMEM (6 * 16384)

__global__ __launch_bounds__(256, 2) void gemm_f16(
    Seg s0, Seg s1, Seg s2, int nx, int N)
{
    extern __shared__ __half gsm[];

    const int tid  = threadIdx.x;
    const int lane = tid & 31;
    const int wid  = tid >> 5;
    const int wm   = wid >> 2;
    const int wn   = wid & 3;
    const int r4   = lane >> 2;
    const int c    = lane & 3;
    const int m0   = blockIdx.y * 128;

    int bx = blockIdx.x;
    Seg s = (bx < nx) ? s0 : ((bx < 2 * nx) ? s1 : s2);
    bx = (bx >= nx) ? (bx >= 2 * nx ? bx - 2 * nx : bx - nx) : bx;
    const int n0 = bx * 128;
    if (m0 >= s.M) return;                 // uniform per-CTA early exit

    const __half* A = s.A;
    const __half* W = s.W;
    const int M = s.M, K = s.K;

    const unsigned sa_s = (unsigned)__cvta_generic_to_shared(gsm);
    const unsigned sb_s = sa_s + 3 * GSTG;

    float acc[4][4][4];
    #pragma unroll
    for (int i = 0; i < 4; i++)
        #pragma unroll
        for (int j = 0; j < 4; j++)
            #pragma unroll
            for (int e = 0; e < 4; e++) acc[i][j][e] = 0.0f;

    auto issue = [&](int ch, int buf) {
        const int k0 = ch * 64;
        #pragma unroll
        for (int i = 0; i < 4; i++) {
            int u = tid + i * 256;
            int row = u >> 3, g = u & 7;
            int gr = m0 + row;
            int sz = (gr < M) ? 16 : 0;
            int grc = (gr < M) ? gr : (M - 1);
            cp_async16(sa_s + (unsigned)buf * GSTG + (unsigned)(row * 128 + ((g ^ (row & 7)) << 4)),
                       A + (size_t)grc * K + k0 + g * 8, sz);
        }
        #pragma unroll
        for (int i = 0; i < 4; i++) {
            int u = tid + i * 256;
            int row = u >> 3, g = u & 7;
            cp_async16(sb_s + (unsigned)buf * GSTG + (unsigned)(row * 128 + ((g ^ (row & 7)) << 4)),
                       W + (size_t)(n0 + row) * K + k0 + g * 8, 16);
        }
        cp_commit();
    };

    // ldmatrix lane roles
    const int arow = (lane & 7) + (lane & 8);
    const int ahib = (lane & 16) ? 1 : 0;
    const int brow = (lane & 7) + ((lane & 16) ? 8 : 0);
    const int bhib = (lane & 8) ? 1 : 0;
    const int l7   = lane & 7;

    const int nk = K >> 6;
    issue(0, 0);
    if (nk > 1) issue(1, 1);

    for (int i = 0; i < nk; i++) {
        const int buf = i % 3;
        if (i + 1 < nk) cp_wait<1>(); else cp_wait<0>();
        __syncthreads();

        const unsigned aT = sa_s + (unsigned)buf * GSTG;
        const unsigned bT = sb_s + (unsigned)buf * GSTG;
        const unsigned bRow0 = bT + (unsigned)((wn * 32 + brow) * 128);
        const unsigned bRow1 = bT + (unsigned)((wn * 32 + 16 + brow) * 128);

        // B-fragment double buffer: preload kt=0
        unsigned bf[2][4][2];
        {
            const unsigned gb = (unsigned)((bhib ^ l7) << 4);
            ldsm_x4(bf[0][0][0], bf[0][0][1], bf[0][1][0], bf[0][1][1], bRow0 + gb);
            ldsm_x4(bf[0][2][0], bf[0][2][1], bf[0][3][0], bf[0][3][1], bRow1 + gb);
        }

        #pragma unroll
        for (int kt = 0; kt < 4; kt++) {
            const int cur = kt & 1;
            if (kt < 3) {
                const unsigned gb = (unsigned)(((2 * (kt + 1) + bhib) ^ l7) << 4);
                ldsm_x4(bf[cur ^ 1][0][0], bf[cur ^ 1][0][1],
                        bf[cur ^ 1][1][0], bf[cur ^ 1][1][1], bRow0 + gb);
                ldsm_x4(bf[cur ^ 1][2][0], bf[cur ^ 1][2][1],
                        bf[cur ^ 1][3][0], bf[cur ^ 1][3][1], bRow1 + gb);
            }
            unsigned af[4][4];
            const unsigned ga = (unsigned)(((2 * kt + ahib) ^ l7) << 4);
            #pragma unroll
            for (int mi = 0; mi < 4; mi++)
                ldsm_x4(af[mi][0], af[mi][1], af[mi][2], af[mi][3],
                        aT + (unsigned)((wm * 64 + mi * 16 + arow) * 128) + ga);
            #pragma unroll
            for (int mi = 0; mi < 4; mi++)
                #pragma unroll
                for (int ni = 0; ni < 4; ni++)
                    mma_f16(acc[mi][ni], af[mi], bf[cur][ni]);
        }

        if (i + 2 < nk) issue(i + 2, (i + 2) % 3);
    }

    // ---- epilogue ----
    #pragma unroll
    for (int mi = 0; mi < 4; mi++) {
        int row1 = m0 + wm * 64 + mi * 16 + r4;
        int row2 = row1 + 8;
        #pragma unroll
        for (int ni = 0; ni < 4; ni++) {
            int colg = n0 + wn * 32 + ni * 8 + c * 2;
            float b0 = s.bias[colg], b1 = s.bias[colg + 1];
            float v00 = acc[mi][ni][0] + b0, v01 = acc[mi][ni][1] + b1;
            float v10 = acc[mi][ni][2] + b0, v11 = acc[mi][ni][3] + b1;
            if (s.ohalf) {
                __half* C = (__half*)s.C;
                if (row1 < M)
                    *reinterpret_cast<unsigned*>(C + (size_t)row1 * N + colg) =
                        packh2(s.oscale * v00, s.oscale * v01);
                if (row2 < M)
                    *reinterpret_cast<unsigned*>(C + (size_t)row2 * N + colg) =
                        packh2(s.oscale * v10, s.oscale * v11);
            } else {
                float* C = (float*)s.C;
                if (row1 < M)
                    *reinterpret_cast<float2*>(C + (size_t)row1 * N + colg) = make_float2(v00, v01);
                if (row2 < M)
                    *reinterpret_cast<float2*>(C + (size_t)row2 * N + colg) = make_float2(v10, v11);
            }
        }
    }
}

// ============================================================
// fa6: fp16 flash attention (unchanged from round 13)
// ============================================================
#define NCHUNK 17
#define KTB 16384u
#define VTB 16384u
#define FA6_SMEM_BYTES (4 * (16384 + 16384))

__global__ __launch_bounds__(256, 1) void fa6_f16(
    const __half* __restrict__ Q, const __half* __restrict__ K,
    const __half* __restrict__ Vt, __half* __restrict__ O)
{
    extern __shared__ unsigned sm4[];

    const int tid  = threadIdx.x;
    const int lane = tid & 31;
    const int wid  = tid >> 5;
    const int r4   = lane >> 2;
    const int c    = lane & 3;
    const int q0   = blockIdx.x * 128;
    const int h    = blockIdx.y;
    const int b    = blockIdx.z;

    const unsigned sbase = (unsigned)__cvta_generic_to_shared(sm4);
    const unsigned k_s = sbase;
    const unsigned v_s = sbase + 4 * KTB;

    const __half* kb  = K + ((size_t)(b * SEQ_KV)) * D_E + h * D_HEAD;
    const __half* vtb = Vt + ((size_t)(b * N_HEADS + h)) * D_HEAD * SKV_PAD;

    const int lrow = (lane & 7) + ((lane & 16) ? 8 : 0);
    const int kbit = (lane & 8) ? 1 : 0;
    const int lx   = lane & 7;

    unsigned qf[8][4];
    {
        const unsigned* qb = reinterpret_cast<const unsigned*>(
            Q + ((size_t)(b * SEQ_Q + q0 + wid * 16)) * D_E + h * D_HEAD);
        #pragma unroll
        for (int kt = 0; kt < 8; kt++) {
            qf[kt][0] = __ldg(qb + (size_t)r4 * 512 + kt * 8 + c);
            qf[kt][1] = __ldg(qb + (size_t)(r4 + 8) * 512 + kt * 8 + c);
            qf[kt][2] = __ldg(qb + (size_t)r4 * 512 + kt * 8 + c + 4);
            qf[kt][3] = __ldg(qb + (size_t)(r4 + 8) * 512 + kt * 8 + c + 4);
        }
    }

    float oacc[16][4];
    #pragma unroll
    for (int nt = 0; nt < 16; nt++)
        #pragma unroll
        for (int e = 0; e < 4; e++) oacc[nt][e] = 0.0f;

    float row_m0 = -1e30f, row_m1 = -1e30f;
    float row_l0 = 0.0f,   row_l1 = 0.0f;

    auto issue_chunk = [&](int t, int buf) {
        const int kv0 = t * 64;
        #pragma unroll
        for (int i = 0; i < 4; i++) {
            int u = tid + i * 256;
            int kv = u >> 4, g = u & 15;
            int kvg = kv0 + kv;
            int sz = (kvg < SEQ_KV) ? 16 : 0;
            int kvc = (kvg < SEQ_KV) ? kvg : (SEQ_KV - 1);
            cp_async16(k_s + (unsigned)buf * KTB + (unsigned)(kv * 256 + ((g ^ (kv & 7)) << 4)),
                       kb + (size_t)kvc * D_E + g * 8, sz);
        }
        #pragma unroll
        for (int i = 0; i < 4; i++) {
            int u = tid + i * 256;
            int d = u >> 3, g = u & 7;
            cp_async16(v_s + (unsigned)buf * VTB + (unsigned)(d * 128 + ((g ^ (d & 7)) << 4)),
                       vtb + (size_t)d * SKV_PAD + kv0 + g * 8, 16);
        }
        cp_commit();
    };

    issue_chunk(0, 0);
    issue_chunk(1, 1);
    issue_chunk(2, 2);

    for (int t = 0; t < NCHUNK; t++) {
        const int kv0 = t * 64;
        const int buf = t & 3;

        if (t + 3 <= NCHUNK) cp_wait<2>();
        else if (t + 2 == NCHUNK) cp_wait<1>();
        else cp_wait<0>();
        __syncthreads();

        const unsigned kT = k_s + (unsigned)buf * KTB + lrow * 256;
        const unsigned vT = v_s + (unsigned)buf * VTB + lrow * 128;

        float sacc[8][4];
        #pragma unroll
        for (int ni = 0; ni < 8; ni++)
            #pragma unroll
            for (int e = 0; e < 4; e++) sacc[ni][e] = 0.0f;

        unsigned kf[2][4][4];
        {
            const unsigned g0 = (unsigned)(((kbit) ^ lx) << 4);
            #pragma unroll
            for (int np = 0; np < 4; np++)
                ldsm_x4(kf[0][np][0], kf[0][np][1], kf[0][np][2], kf[0][np][3],
                        kT + np * 4096 + g0);
        }
        #pragma unroll
        for (int kt = 0; kt < 8; kt++) {
            const int cur = kt & 1;
            if (kt < 7) {
                const unsigned gn = (unsigned)(((2 * (kt + 1) + kbit) ^ lx) << 4);
                #pragma unroll
                for (int np = 0; np < 4; np++)
                    ldsm_x4(kf[cur ^ 1][np][0], kf[cur ^ 1][np][1],
                            kf[cur ^ 1][np][2], kf[cur ^ 1][np][3],
                            kT + np * 4096 + gn);
            }
            #pragma unroll
            for (int np = 0; np < 4; np++) {
                unsigned bfA[2] = {kf[cur][np][0], kf[cur][np][1]};
                unsigned bfB[2] = {kf[cur][np][2], kf[cur][np][3]};
                mma_f16(sacc[2 * np],     qf[kt], bfA);
                mma_f16(sacc[2 * np + 1], qf[kt], bfB);
            }
        }

        float mx0 = -1e30f, mx1 = -1e30f;
        if (t == NCHUNK - 1) {
            #pragma unroll
            for (int ni = 0; ni < 8; ni++) {
                int colg = kv0 + ni * 8 + c * 2;
                if (colg >= SEQ_KV) {
                    sacc[ni][0] = -1e30f; sacc[ni][1] = -1e30f;
                    sacc[ni][2] = -1e30f; sacc[ni][3] = -1e30f;
                }
                mx0 = fmaxf(mx0, fmaxf(sacc[ni][0], sacc[ni][1]));
                mx1 = fmaxf(mx1, fmaxf(sacc[ni][2], sacc[ni][3]));
            }
        } else {
            #pragma unroll
            for (int ni = 0; ni < 8; ni++) {
                mx0 = fmaxf(mx0, fmaxf(sacc[ni][0], sacc[ni][1]));
                mx1 = fmaxf(mx1, fmaxf(sacc[ni][2], sacc[ni][3]));
            }
        }
        mx0 = fmaxf(mx0, __shfl_xor_sync(0xffffffffu, mx0, 1));
        mx0 = fmaxf(mx0, __shfl_xor_sync(0xffffffffu, mx0, 2));
        mx1 = fmaxf(mx1, __shfl_xor_sync(0xffffffffu, mx1, 1));
        mx1 = fmaxf(mx1, __shfl_xor_sync(0xffffffffu, mx1, 2));

        float mnew0 = fmaxf(row_m0, mx0);
        float mnew1 = fmaxf(row_m1, mx1);
        float sc0 = fexp(row_m0 - mnew0);
        float sc1 = fexp(row_m1 - mnew1);
        row_m0 = mnew0; row_m1 = mnew1;

        float sum0 = 0.f, sum1 = 0.f;
        #pragma unroll
        for (int ni = 0; ni < 8; ni++) {
            sacc[ni][0] = fexp(sacc[ni][0] - mnew0);
            sacc[ni][1] = fexp(sacc[ni][1] - mnew0);
            sacc[ni][2] = fexp(sacc[ni][2] - mnew1);
            sacc[ni][3] = fexp(sacc[ni][3] - mnew1);
            sum0 += sacc[ni][0] + sacc[ni][1];
            sum1 += sacc[ni][2] + sacc[ni][3];
        }
        sum0 += __shfl_xor_sync(0xffffffffu, sum0, 1);
        sum0 += __shfl_xor_sync(0xffffffffu, sum0, 2);
        sum1 += __shfl_xor_sync(0xffffffffu, sum1, 1);
        sum1 += __shfl_xor_sync(0xffffffffu, sum1, 2);
        row_l0 = row_l0 * sc0 + sum0;
        row_l1 = row_l1 * sc1 + sum1;

        #pragma unroll
        for (int nt = 0; nt < 16; nt++) {
            oacc[nt][0] *= sc0; oacc[nt][1] *= sc0;
            oacc[nt][2] *= sc1; oacc[nt][3] *= sc1;
        }

        #pragma unroll
        for (int kt = 0; kt < 4; kt++) {
            unsigned pa[4];
            pa[0] = packh2(sacc[2 * kt][0],     sacc[2 * kt][1]);
            pa[1] = packh2(sacc[2 * kt][2],     sacc[2 * kt][3]);
            pa[2] = packh2(sacc[2 * kt + 1][0], sacc[2 * kt + 1][1]);
            pa[3] = packh2(sacc[2 * kt + 1][2], sacc[2 * kt + 1][3]);

            const unsigned goff = (unsigned)(((2 * kt + kbit) ^ lx) << 4);
            #pragma unroll
            for (int np = 0; np < 8; np++) {
                unsigned b0, b1, b2, b3;
                ldsm_x4(b0, b1, b2, b3, vT + np * 2048 + goff);
                unsigned bfA[2] = {b0, b1};
                unsigned bfB[2] = {b2, b3};
                mma_f16(oacc[2 * np],     pa, bfA);
                mma_f16(oacc[2 * np + 1], pa, bfB);
            }
        }

        if (t + 3 < NCHUNK) issue_chunk(t + 3, (t + 3) & 3);
    }

    float inv0 = 1.0f / row_l0;
    float inv1 = 1.0f / row_l1;
    __half* ob = O + ((size_t)(b * SEQ_Q + q0 + wid * 16 + r4)) * D_E + h * D_HEAD;
    #pragma unroll
    for (int nt = 0; nt < 16; nt++) {
        int colg = nt * 8 + c * 2;
        *reinterpret_cast<unsigned*>(ob + colg) =
            packh2(oacc[nt][0] * inv0, oacc[nt][1] * inv0);
        *reinterpret_cast<unsigned*>(ob + (size_t)8 * D_E + colg) =
            packh2(oacc[nt][2] * inv1, oacc[nt][3] * inv1);
    }
}

// ============================================================
// launch
// ============================================================
extern "C" void kernel_launch(void* const* d_in, const int* in_sizes, int n_in,
                              void* d_out, int out_size)
{
    const float* x  = (const float*)d_in[0];
    const float* y  = (const float*)d_in[1];
    const float* Wq = (const float*)d_in[2];
    const float* bq = (const float*)d_in[3];
    const float* Wk = (const float*)d_in[4];
    const float* bk = (const float*)d_in[5];
    const float* Wv = (const float*)d_in[6];
    const float* bv = (const float*)d_in[7];
    const float* Wo = (const float*)d_in[8];
    const float* bo = (const float*)d_in[9];
    float* out = (float*)d_out;

    __half *hx, *hy, *hWq, *hWk, *hWv, *hWo, *pQ, *pK, *pV, *pVt, *pO;
    cudaGetSymbolAddress((void**)&hx,  g_hx);
    cudaGetSymbolAddress((void**)&hy,  g_hy);
    cudaGetSymbolAddress((void**)&hWq, g_hWq);
    cudaGetSymbolAddress((void**)&hWk, g_hWk);
    cudaGetSymbolAddress((void**)&hWv, g_hWv);
    cudaGetSymbolAddress((void**)&hWo, g_hWo);
    cudaGetSymbolAddress((void**)&pQ,  g_Q);
    cudaGetSymbolAddress((void**)&pK,  g_K);
    cudaGetSymbolAddress((void**)&pV,  g_V);
    cudaGetSymbolAddress((void**)&pVt, g_Vt);
    cudaGetSymbolAddress((void**)&pO,  g_O);

    const float qscale = 0.08838834764831845f;  // 1/sqrt(128)

    // launch 0: all fp32->fp16 conversions
    cvt_all<<<(C_N4 + 255) / 256, 256>>>(x, y, Wq, Wk, Wv, Wo,
                                         hx, hy, hWq, hWk, hWv, hWo);

    cudaFuncSetAttribute(gemm_f16, cudaFuncAttributeMaxDynamicSharedMemorySize, GEMM_SMEM);

    // launch 1: Q + K + V projections in one launch (3 segments)
    Seg sq = { hx, hWq, bq, pQ, MQ,  D_E, 1, qscale };
    Seg sk = { hy, hWk, bk, pK, MKV, D_C, 1, 1.0f };
    Seg sv = { hy, hWv, bv, pV, MKV, D_C, 1, 1.0f };
    gemm_f16<<<dim3(24, (MQ + 127) / 128), 256, GEMM_SMEM>>>(sq, sk, sv, 8, D_E);

    // launch 2: V transpose
    transpose_v<<<dim3(SKV_PAD / 32, D_HEAD / 32, BATCH * N_HEADS), dim3(32, 8)>>>(pV, pVt);

    // launch 3: attention
    cudaFuncSetAttribute(fa6_f16, cudaFuncAttributeMaxDynamicSharedMemorySize, FA6_SMEM_BYTES);
    fa6_f16<<<dim3(SEQ_Q / 128, N_HEADS, BATCH), 256, FA6_SMEM_BYTES>>>(pQ, pK, pVt, pO);

    // launch 4: output projection -> d_out (fp32)
    Seg so = { pO, hWo, bo, out, MQ, D_E, 0, 1.0f };
    gemm_f16<<<dim3(8, (MQ + 127) / 128), 256, GEMM_SMEM>>>(so, so, so, 8, D_E);
}